// round 3
// baseline (speedup 1.0000x reference)
#include <cuda_runtime.h>
#include <math.h>

#define VV 32000
#define DD 256
#define HH 256
#define LLEN 4
#define TT 128
#define BB 8
#define G4 1024
#define NROWS 5040      // 5 steps * 126 starts * 8 batch
#define RPAD 5056       // 79*64
#define NCH 250         // 32000/128
#define LOGINF 1000000.0f
#define EOS_TOK 1

// ------------------------- device scratch (globals) -------------------------
__device__ float g_emb[TT*BB*DD];         // (t*B+b, d)
__device__ float g_WhhET[G4*HH];          // transposed W_hh_e: [gatecol][k]
__device__ float g_preE[TT*BB*G4];        // emb @ W_ih_e + b_e
__device__ float g_hA[BB*HH];             // encoder h double buffer
__device__ float g_hB[BB*HH];
__device__ float g_cE[BB*HH];
__device__ float g_enc[TT*BB*HH];         // 0.5*h
__device__ float g_seg[TT*BB*HH];         // tanh(enc @ W_start)
__device__ float g_startIh[TT*BB*G4];
__device__ float g_winIh[TT*BB*G4];
__device__ float g_decIh[5*1024*G4];      // per-step input projections (padded rows)
__device__ float g_hD[1024*HH];           // decoder h prev (1024 rows, pad zero)
__device__ float g_cD[1024*HH];
__device__ float g_gates[1024*G4];
__device__ float g_hdec[RPAD*HH];         // r = s*1008 + (j-1)*8 + b
__device__ float g_u[RPAD*HH];
__device__ float g_pM[NCH*RPAD];
__device__ float g_pS[NCH*RPAD];
__device__ float g_lse[RPAD];
__device__ float g_tlp[RPAD];
__device__ float g_elp[RPAD];
__device__ float g_logpy[(TT-1)*LLEN*BB]; // (j, k, b), j=1..126 used

__device__ __forceinline__ float sigf(float x) { return 1.0f / (1.0f + expf(-x)); }

// ------------------------- init: zero recurrent state ------------------------
__global__ void init_kernel() {
    int i = blockIdx.x * 256 + threadIdx.x;
    if (i < 1024*HH) { g_hD[i] = 0.f; g_cD[i] = 0.f; }
    if (i < BB*HH)   { g_hA[i] = 0.f; g_cE[i] = 0.f; }
}

// ------------------------- embedding gather ---------------------------------
__global__ void embed_kernel(const int* __restrict__ x, const float* __restrict__ E) {
    int tb = blockIdx.x;           // t*B+b
    int t = tb >> 3, b = tb & 7;
    int tok = x[b*TT + t];
    int d = threadIdx.x * 4;       // 64 threads
    *(float4*)&g_emb[(size_t)tb*DD + d] = *(const float4*)&E[(size_t)tok*DD + d];
}

// ------------------------- transpose W_hh_e (256x1024 -> 1024x256) ----------
__global__ void transpose_kernel(const float* __restrict__ W) {
    int idx = blockIdx.x * 256 + threadIdx.x;   // grid 1024
    int n = idx >> 8, k = idx & 255;
    g_WhhET[idx] = W[(size_t)k*G4 + n];
}

// ------------------------- generic fp32 GEMM 64x64 tile ----------------------
// C = act(A(MxK) @ B(KxN) + bias + addM) ; act: 0 none, 1 tanh
__global__ __launch_bounds__(256) void gemm_kernel(
    const float* __restrict__ A, const float* __restrict__ Bm,
    const float* __restrict__ bias, const float* __restrict__ addM,
    float* __restrict__ C, int M, int N, int K, int act)
{
    __shared__ float As[16][68];
    __shared__ float Bs[16][68];
    int n0 = blockIdx.x * 64, m0 = blockIdx.y * 64;
    int tid = threadIdx.x;
    int tx = tid & 15, ty = tid >> 4;
    float acc[4][4];
    #pragma unroll
    for (int i = 0; i < 4; i++)
        #pragma unroll
        for (int j = 0; j < 4; j++) acc[i][j] = 0.f;

    int arow = tid >> 2, akk = (tid & 3) << 2;
    int bkk  = tid >> 4, bnc = (tid & 15) << 2;

    for (int k0 = 0; k0 < K; k0 += 16) {
        float4 av = *(const float4*)&A[(size_t)(m0 + arow)*K + k0 + akk];
        As[akk+0][arow] = av.x; As[akk+1][arow] = av.y;
        As[akk+2][arow] = av.z; As[akk+3][arow] = av.w;
        *(float4*)&Bs[bkk][bnc] = *(const float4*)&Bm[(size_t)(k0 + bkk)*N + n0 + bnc];
        __syncthreads();
        #pragma unroll
        for (int kk = 0; kk < 16; kk++) {
            float a0 = As[kk][ty*4+0], a1 = As[kk][ty*4+1];
            float a2 = As[kk][ty*4+2], a3 = As[kk][ty*4+3];
            float4 bq = *(float4*)&Bs[kk][tx*4];
            acc[0][0] += a0*bq.x; acc[0][1] += a0*bq.y; acc[0][2] += a0*bq.z; acc[0][3] += a0*bq.w;
            acc[1][0] += a1*bq.x; acc[1][1] += a1*bq.y; acc[1][2] += a1*bq.z; acc[1][3] += a1*bq.w;
            acc[2][0] += a2*bq.x; acc[2][1] += a2*bq.y; acc[2][2] += a2*bq.z; acc[2][3] += a2*bq.w;
            acc[3][0] += a3*bq.x; acc[3][1] += a3*bq.y; acc[3][2] += a3*bq.z; acc[3][3] += a3*bq.w;
        }
        __syncthreads();
    }
    #pragma unroll
    for (int i = 0; i < 4; i++) {
        int m = m0 + ty*4 + i;
        #pragma unroll
        for (int j = 0; j < 4; j++) {
            int n = n0 + tx*4 + j;
            float v = acc[i][j];
            if (bias) v += bias[n];
            if (addM) v += addM[(size_t)m*N + n];
            if (act == 1) v = tanhf(v);
            C[(size_t)m*N + n] = v;
        }
    }
}

// ------------------------- fused encoder LSTM step ---------------------------
// grid 4 blocks x 256 threads. Each thread: h-col n, 2 batches, all 4 gates.
__global__ __launch_bounds__(256) void enc_step_kernel(int t) {
    __shared__ float hs[BB][HH];
    const float* hin  = (t & 1) ? g_hB : g_hA;
    float*       hout = (t & 1) ? g_hA : g_hB;
    int tid = threadIdx.x;
    for (int i = tid; i < BB*HH; i += 256) hs[i >> 8][i & 255] = hin[i];
    __syncthreads();

    int n   = blockIdx.x * 64 + (tid & 63);
    int grp = tid >> 6;
    int b0  = grp * 2;
    float acc[4][2];
    #pragma unroll
    for (int q = 0; q < 4; q++) { acc[q][0] = 0.f; acc[q][1] = 0.f; }

    for (int k4 = 0; k4 < 64; k4++) {
        float4 h0 = *(float4*)&hs[b0][k4*4];
        float4 h1 = *(float4*)&hs[b0+1][k4*4];
        #pragma unroll
        for (int q = 0; q < 4; q++) {
            float4 w = *(const float4*)&g_WhhET[(size_t)(q*256 + n)*256 + k4*4];
            acc[q][0] += w.x*h0.x + w.y*h0.y + w.z*h0.z + w.w*h0.w;
            acc[q][1] += w.x*h1.x + w.y*h1.y + w.z*h1.z + w.w*h1.w;
        }
    }
    #pragma unroll
    for (int bb = 0; bb < 2; bb++) {
        int b = b0 + bb;
        const float* pre = &g_preE[(size_t)(t*BB + b)*G4];
        float gi = acc[0][bb] + pre[n];
        float gf = acc[1][bb] + pre[256 + n];
        float gg = acc[2][bb] + pre[512 + n];
        float go = acc[3][bb] + pre[768 + n];
        float c = sigf(gf) * g_cE[b*HH + n] + sigf(gi) * tanhf(gg);
        float h = sigf(go) * tanhf(c);
        g_cE[b*HH + n] = c;
        hout[b*HH + n] = h;
        g_enc[(size_t)(t*BB + b)*HH + n] = 0.5f * h;
    }
}

// ------------------------- build decoder per-step input projections ----------
__global__ void decih_kernel(const float* __restrict__ b_d) {
    int blk = blockIdx.x;              // 5*1024
    int s = blk >> 10, rr = blk & 1023;
    float* dst = &g_decIh[((size_t)s*1024 + rr)*G4];
    int tid = threadIdx.x;             // 256, 4 each
    if (rr >= 1008) {
        for (int i = 0; i < 4; i++) dst[tid*4 + i] = 0.f;
        return;
    }
    int j = (rr >> 3) + 1, b = rr & 7;
    const float* src;
    if (s == 0) src = &g_startIh[(size_t)rr*G4];
    else {
        int t = j + s - 1;
        if (t < TT) src = &g_winIh[(size_t)(t*BB + b)*G4];
        else        src = 0;
    }
    if (src) *(float4*)&dst[tid*4] = *(const float4*)&src[tid*4];
    else     *(float4*)&dst[tid*4] = *(const float4*)&b_d[tid*4];
}

// ------------------------- decoder LSTM cell ---------------------------------
__global__ void dec_cell_kernel(int s) {
    int rr = blockIdx.x;               // 1008
    int n = threadIdx.x;               // 256
    const float* g = &g_gates[(size_t)rr*G4];
    float gi = g[n], gf = g[256+n], gg = g[512+n], go = g[768+n];
    float c = sigf(gf) * g_cD[rr*HH + n] + sigf(gi) * tanhf(gg);
    float h = sigf(go) * tanhf(c);
    g_cD[rr*HH + n] = c;
    g_hD[rr*HH + n] = h;
    g_hdec[((size_t)s*1008 + rr)*HH + n] = h;
}

// ------------------------- big vocab GEMM with online (max,sumexp) -----------
// grid (NCH, RPAD/64). Block: 64 rows x 128 vocab, K=256.
__global__ __launch_bounds__(256) void lse_gemm_kernel(const float* __restrict__ E) {
    __shared__ float As[16][68];
    __shared__ float Es[16][132];
    __shared__ float Cs[64][132];
    int v0 = blockIdx.x * 128;
    int m0 = blockIdx.y * 64;
    int tid = threadIdx.x;
    int tx = tid & 15, ty = tid >> 4;
    float acc[4][8];
    #pragma unroll
    for (int i = 0; i < 4; i++)
        #pragma unroll
        for (int j = 0; j < 8; j++) acc[i][j] = 0.f;

    int am = tid >> 2, akq = (tid & 3) << 2;
    for (int k0 = 0; k0 < 256; k0 += 16) {
        float4 av = *(const float4*)&g_u[(size_t)(m0 + am)*HH + k0 + akq];
        As[akq+0][am] = av.x; As[akq+1][am] = av.y;
        As[akq+2][am] = av.z; As[akq+3][am] = av.w;
        #pragma unroll
        for (int rep = 0; rep < 2; rep++) {
            int task = tid + rep*256;
            int v = task & 127, kq = (task >> 7) << 2;
            float4 ev = *(const float4*)&E[(size_t)(v0 + v)*DD + k0 + kq];
            Es[kq+0][v] = ev.x; Es[kq+1][v] = ev.y;
            Es[kq+2][v] = ev.z; Es[kq+3][v] = ev.w;
        }
        __syncthreads();
        #pragma unroll
        for (int kk = 0; kk < 16; kk++) {
            float a0 = As[kk][ty*4+0], a1 = As[kk][ty*4+1];
            float a2 = As[kk][ty*4+2], a3 = As[kk][ty*4+3];
            float4 bq0 = *(float4*)&Es[kk][tx*8];
            float4 bq1 = *(float4*)&Es[kk][tx*8+4];
            acc[0][0]+=a0*bq0.x; acc[0][1]+=a0*bq0.y; acc[0][2]+=a0*bq0.z; acc[0][3]+=a0*bq0.w;
            acc[0][4]+=a0*bq1.x; acc[0][5]+=a0*bq1.y; acc[0][6]+=a0*bq1.z; acc[0][7]+=a0*bq1.w;
            acc[1][0]+=a1*bq0.x; acc[1][1]+=a1*bq0.y; acc[1][2]+=a1*bq0.z; acc[1][3]+=a1*bq0.w;
            acc[1][4]+=a1*bq1.x; acc[1][5]+=a1*bq1.y; acc[1][6]+=a1*bq1.z; acc[1][7]+=a1*bq1.w;
            acc[2][0]+=a2*bq0.x; acc[2][1]+=a2*bq0.y; acc[2][2]+=a2*bq0.z; acc[2][3]+=a2*bq0.w;
            acc[2][4]+=a2*bq1.x; acc[2][5]+=a2*bq1.y; acc[2][6]+=a2*bq1.z; acc[2][7]+=a2*bq1.w;
            acc[3][0]+=a3*bq0.x; acc[3][1]+=a3*bq0.y; acc[3][2]+=a3*bq0.z; acc[3][3]+=a3*bq0.w;
            acc[3][4]+=a3*bq1.x; acc[3][5]+=a3*bq1.y; acc[3][6]+=a3*bq1.z; acc[3][7]+=a3*bq1.w;
        }
        __syncthreads();
    }
    #pragma unroll
    for (int i = 0; i < 4; i++) {
        *(float4*)&Cs[ty*4+i][tx*8]   = *(float4*)&acc[i][0];
        *(float4*)&Cs[ty*4+i][tx*8+4] = *(float4*)&acc[i][4];
    }
    __syncthreads();
    // reduce 128 cols -> (max, sumexp) per row. 8 warps * 8 rows.
    int w = tid >> 5, lane = tid & 31;
    for (int rloc = w*8; rloc < w*8+8; rloc++) {
        float v0v = Cs[rloc][lane];
        float v1v = Cs[rloc][lane+32];
        float v2v = Cs[rloc][lane+64];
        float v3v = Cs[rloc][lane+96];
        float mx = fmaxf(fmaxf(v0v, v1v), fmaxf(v2v, v3v));
        #pragma unroll
        for (int off = 16; off > 0; off >>= 1)
            mx = fmaxf(mx, __shfl_xor_sync(0xffffffff, mx, off));
        float s = expf(v0v-mx) + expf(v1v-mx) + expf(v2v-mx) + expf(v3v-mx);
        #pragma unroll
        for (int off = 16; off > 0; off >>= 1)
            s += __shfl_xor_sync(0xffffffff, s, off);
        if (lane == 0) {
            g_pM[(size_t)blockIdx.x*RPAD + m0 + rloc] = mx;
            g_pS[(size_t)blockIdx.x*RPAD + m0 + rloc] = s;
        }
    }
}

// ------------------------- merge chunk partials -> LSE -----------------------
__global__ void lse_merge_kernel() {
    int r = blockIdx.x * 4 + (threadIdx.x >> 5);   // grid 1260
    int lane = threadIdx.x & 31;
    if (r >= NROWS) return;
    float lm[8], ls[8];
    float mx = -LOGINF;
    #pragma unroll
    for (int i = 0; i < 8; i++) {
        int c = lane + i*32;
        if (c < NCH) { lm[i] = g_pM[(size_t)c*RPAD + r]; ls[i] = g_pS[(size_t)c*RPAD + r]; }
        else         { lm[i] = -LOGINF; ls[i] = 0.f; }
        mx = fmaxf(mx, lm[i]);
    }
    #pragma unroll
    for (int off = 16; off > 0; off >>= 1)
        mx = fmaxf(mx, __shfl_xor_sync(0xffffffff, mx, off));
    float s = 0.f;
    #pragma unroll
    for (int i = 0; i < 8; i++) s += ls[i] * expf(lm[i] - mx);
    #pragma unroll
    for (int off = 16; off > 0; off >>= 1)
        s += __shfl_xor_sync(0xffffffff, s, off);
    if (lane == 0) g_lse[r] = mx + logf(s);
}

// ------------------------- per-row tgt + EOS log-probs -----------------------
__global__ void tgt_eos_kernel(const int* __restrict__ x, const float* __restrict__ E) {
    __shared__ float red[4];
    int r = blockIdx.x;                 // 5040
    int s = r / 1008, rem = r % 1008;
    int j = (rem >> 3) + 1, b = rem & 7;
    int tt = j + s;
    int tok = (tt < TT) ? x[b*TT + tt] : 0;
    int tid = threadIdx.x;              // 64
    float4 uv = *(const float4*)&g_u[(size_t)r*HH + tid*4];
    float4 et = *(const float4*)&E[(size_t)tok*DD + tid*4];
    float4 ee = *(const float4*)&E[(size_t)EOS_TOK*DD + tid*4];
    float dt = uv.x*et.x + uv.y*et.y + uv.z*et.z + uv.w*et.w;
    float de = uv.x*ee.x + uv.y*ee.y + uv.z*ee.z + uv.w*ee.w;
    #pragma unroll
    for (int off = 16; off > 0; off >>= 1) {
        dt += __shfl_xor_sync(0xffffffff, dt, off);
        de += __shfl_xor_sync(0xffffffff, de, off);
    }
    if ((tid & 31) == 0) { red[(tid >> 5)*2] = dt; red[(tid >> 5)*2 + 1] = de; }
    __syncthreads();
    if (tid == 0) {
        float lse = g_lse[r];
        g_tlp[r] = red[0] + red[2] - lse;
        g_elp[r] = red[1] + red[3] - lse;
    }
}

// ------------------------- assemble logpy ------------------------------------
__device__ __forceinline__ float is_single_tok(const int* x, int t, int b) {
    if (t >= TT) return 0.f;
    int tok = x[b*TT + t];
    return (tok == 2 || tok == 3 || tok == 4) ? -LOGINF : 0.f;
}

__global__ void logpy_kernel(const int* __restrict__ x) {
    int tid = blockIdx.x * 256 + threadIdx.x;   // grid 4
    if (tid >= 1008) return;
    int j = (tid >> 3) + 1, b = tid & 7;
    float iss0 = is_single_tok(x, j, b);
    float csum = 0.f;
    #pragma unroll
    for (int k = 0; k < LLEN; k++) {
        int rbase = (j-1)*8 + b;
        float tl = g_tlp[k*1008 + rbase];
        float el = g_elp[(k+1)*1008 + rbase];
        float addk = (k == 0) ? 0.f : is_single_tok(x, j + k, b);
        csum += tl + addk;
        float v = csum + ((k >= 1) ? iss0 : 0.f) + el + 1.0f;
        if (k > TT - 2 - j) v = -LOGINF;
        g_logpy[((size_t)j*LLEN + k)*BB + b] = v;
    }
}

// ------------------------- segmental DP + final reduction --------------------
__global__ void dp_kernel(const int* __restrict__ lengths, float* __restrict__ out) {
    __shared__ float alpha[TT-1][BB];
    __shared__ float nll_s[BB];
    int b = threadIdx.x;                 // 32 threads, 8 active
    if (b < BB) {
        float buf[LLEN];
        buf[0] = -LOGINF; buf[1] = -LOGINF; buf[2] = -LOGINF; buf[3] = 0.f;
        alpha[0][b] = 0.f;
        for (int m = 1; m <= TT-2; m++) {
            float c[LLEN];
            #pragma unroll
            for (int k = 0; k < LLEN; k++) {
                int idx = m - k;
                float d = (idx >= 1) ? g_logpy[((size_t)idx*LLEN + k)*BB + b] : -LOGINF;
                c[k] = buf[LLEN-1-k] + d;
            }
            float mx = fmaxf(fmaxf(c[0], c[1]), fmaxf(c[2], c[3]));
            float a = mx + logf(expf(c[0]-mx) + expf(c[1]-mx) + expf(c[2]-mx) + expf(c[3]-mx));
            buf[0] = buf[1]; buf[1] = buf[2]; buf[2] = buf[3]; buf[3] = a;
            alpha[m][b] = a;
        }
        nll_s[b] = -alpha[lengths[b] - 2][b];
    }
    __syncthreads();
    if (b == 0) {
        float tot = 0.f; int tl = 0;
        for (int i = 0; i < BB; i++) { tot += nll_s[i]; tl += lengths[i]; }
        out[0] = tot / (float)(tl - 2*BB);
    }
}

// ------------------------- host launch ---------------------------------------
extern "C" void kernel_launch(void* const* d_in, const int* in_sizes, int n_in,
                              void* d_out, int out_size) {
    const int*   x        = (const int*)  d_in[0];
    const int*   lengths  = (const int*)  d_in[1];
    const float* E        = (const float*)d_in[2];
    const float* W_ih_e   = (const float*)d_in[3];
    const float* W_hh_e   = (const float*)d_in[4];
    const float* b_e      = (const float*)d_in[5];
    const float* W_start  = (const float*)d_in[6];
    const float* W_ih_d   = (const float*)d_in[7];
    const float* W_hh_d   = (const float*)d_in[8];
    const float* b_d      = (const float*)d_in[9];
    const float* W_proj   = (const float*)d_in[10];
    float* out = (float*)d_out;

    float *p_emb, *p_preE, *p_enc, *p_seg, *p_startIh, *p_winIh, *p_decIh;
    float *p_hD, *p_gates, *p_hdec, *p_u;
    cudaGetSymbolAddress((void**)&p_emb, g_emb);
    cudaGetSymbolAddress((void**)&p_preE, g_preE);
    cudaGetSymbolAddress((void**)&p_enc, g_enc);
    cudaGetSymbolAddress((void**)&p_seg, g_seg);
    cudaGetSymbolAddress((void**)&p_startIh, g_startIh);
    cudaGetSymbolAddress((void**)&p_winIh, g_winIh);
    cudaGetSymbolAddress((void**)&p_decIh, g_decIh);
    cudaGetSymbolAddress((void**)&p_hD, g_hD);
    cudaGetSymbolAddress((void**)&p_gates, g_gates);
    cudaGetSymbolAddress((void**)&p_hdec, g_hdec);
    cudaGetSymbolAddress((void**)&p_u, g_u);

    init_kernel<<<1024, 256>>>();
    embed_kernel<<<TT*BB, 64>>>(x, E);
    transpose_kernel<<<1024, 256>>>(W_hh_e);

    // preE = emb @ W_ih_e + b_e   (1024 x 1024, K=256)
    gemm_kernel<<<dim3(16, 16), 256>>>(p_emb, W_ih_e, b_e, 0, p_preE, 1024, 1024, 256, 0);

    for (int t = 0; t < TT; t++)
        enc_step_kernel<<<4, 256>>>(t);

    // seg = tanh(enc @ W_start)   (1024 x 256)
    gemm_kernel<<<dim3(4, 16), 256>>>(p_enc, W_start, 0, 0, p_seg, 1024, 256, 256, 1);
    // startIh = seg @ W_ih_d + b_d  (1024 x 1024)
    gemm_kernel<<<dim3(16, 16), 256>>>(p_seg, W_ih_d, b_d, 0, p_startIh, 1024, 1024, 256, 0);
    // winIh = emb @ W_ih_d + b_d   (1024 x 1024)
    gemm_kernel<<<dim3(16, 16), 256>>>(p_emb, W_ih_d, b_d, 0, p_winIh, 1024, 1024, 256, 0);

    decih_kernel<<<5*1024, 256>>>(b_d);

    for (int s = 0; s < 5; s++) {
        gemm_kernel<<<dim3(16, 16), 256>>>(p_hD, W_hh_d, 0, p_decIh + (size_t)s*1024*G4,
                                           p_gates, 1024, 1024, 256, 0);
        dec_cell_kernel<<<1008, 256>>>(s);
    }

    // u = hdec @ W_proj   (5056 x 256)
    gemm_kernel<<<dim3(4, 79), 256>>>(p_hdec, W_proj, 0, 0, p_u, RPAD, 256, 256, 0);

    lse_gemm_kernel<<<dim3(NCH, RPAD/64), 256>>>(E);
    lse_merge_kernel<<<(NROWS + 3)/4, 128>>>();
    tgt_eos_kernel<<<NROWS, 64>>>(x, E);
    logpy_kernel<<<4, 256>>>(x);
    dp_kernel<<<1, 32>>>(lengths, out);
}

// round 4
// speedup vs baseline: 2.4737x; 2.4737x over previous
#include <cuda_runtime.h>
#include <math.h>

#define VV 32000
#define DD 256
#define HH 256
#define LLEN 4
#define TT 128
#define BB 8
#define G4 1024
#define NROWS 5040      // 5 steps * 126 starts * 8 batch
#define RPAD 5120       // 40 * 128
#define NCH 250         // 32000/128
#define LOGINF 1000000.0f
#define EOS_TOK 1
#define ENCB 16

// ------------------------- device scratch (globals) -------------------------
__device__ float g_emb[TT*BB*DD];         // (t*B+b, d)
__device__ float g_WhhET[G4*HH];          // transposed W_hh_e: [gatecol][k]
__device__ float g_preE[TT*BB*G4];        // emb @ W_ih_e + b_e
__device__ float g_hA[BB*HH];             // encoder h ping-pong
__device__ float g_hB[BB*HH];
__device__ float g_enc[TT*BB*HH];         // 0.5*h
__device__ float g_seg[TT*BB*HH];         // tanh(enc @ W_start)
__device__ float g_startIh[TT*BB*G4];
__device__ float g_winIh[TT*BB*G4];
__device__ float g_decIh[5*1024*G4];      // per-step input projections (padded rows)
__device__ float g_hD[1024*HH];           // decoder h prev (1024 rows, pad zero)
__device__ float g_cD[1024*HH];
__device__ float g_gates[1024*G4];
__device__ float g_hdec[RPAD*HH];         // r = s*1008 + (j-1)*8 + b
__device__ float g_u[RPAD*HH];
__device__ float g_pM[NCH*RPAD];
__device__ float g_pS[NCH*RPAD];
__device__ float g_lse[RPAD];
__device__ float g_tlp[RPAD];
__device__ float g_elp[RPAD];
__device__ float g_logpy[(TT-1)*LLEN*BB]; // (j, k, b), j=1..126 used
__device__ int   g_bar[TT];               // encoder step barrier counters

__device__ __forceinline__ float sigf(float x) { return 1.0f / (1.0f + expf(-x)); }

// ------------------------- init: zero recurrent state + barriers -------------
__global__ void init_kernel() {
    int i = blockIdx.x * 256 + threadIdx.x;
    if (i < 1024*HH) { g_hD[i] = 0.f; g_cD[i] = 0.f; }
    if (i < BB*HH)   { g_hA[i] = 0.f; g_hB[i] = 0.f; }
    if (i < TT)      g_bar[i] = 0;
}

// ------------------------- embedding gather ---------------------------------
__global__ void embed_kernel(const int* __restrict__ x, const float* __restrict__ E) {
    int tb = blockIdx.x;           // t*B+b
    int t = tb >> 3, b = tb & 7;
    int tok = x[b*TT + t];
    int d = threadIdx.x * 4;       // 64 threads
    *(float4*)&g_emb[(size_t)tb*DD + d] = *(const float4*)&E[(size_t)tok*DD + d];
}

// ------------------------- transpose W_hh_e (256x1024 -> 1024x256) ----------
__global__ void transpose_kernel(const float* __restrict__ W) {
    int idx = blockIdx.x * 256 + threadIdx.x;   // grid 1024
    int n = idx >> 8, k = idx & 255;
    g_WhhET[idx] = W[(size_t)k*G4 + n];
}

// ------------------------- generic fp32 GEMM 64x64 tile ----------------------
// C = act(A(MxK) @ B(KxN) + bias + addM) ; act: 0 none, 1 tanh
__global__ __launch_bounds__(256) void gemm_kernel(
    const float* __restrict__ A, const float* __restrict__ Bm,
    const float* __restrict__ bias, const float* __restrict__ addM,
    float* __restrict__ C, int M, int N, int K, int act)
{
    __shared__ float As[16][68];
    __shared__ float Bs[16][68];
    int n0 = blockIdx.x * 64, m0 = blockIdx.y * 64;
    int tid = threadIdx.x;
    int tx = tid & 15, ty = tid >> 4;
    float acc[4][4];
    #pragma unroll
    for (int i = 0; i < 4; i++)
        #pragma unroll
        for (int j = 0; j < 4; j++) acc[i][j] = 0.f;

    int arow = tid >> 2, akk = (tid & 3) << 2;
    int bkk  = tid >> 4, bnc = (tid & 15) << 2;

    for (int k0 = 0; k0 < K; k0 += 16) {
        float4 av = *(const float4*)&A[(size_t)(m0 + arow)*K + k0 + akk];
        As[akk+0][arow] = av.x; As[akk+1][arow] = av.y;
        As[akk+2][arow] = av.z; As[akk+3][arow] = av.w;
        *(float4*)&Bs[bkk][bnc] = *(const float4*)&Bm[(size_t)(k0 + bkk)*N + n0 + bnc];
        __syncthreads();
        #pragma unroll
        for (int kk = 0; kk < 16; kk++) {
            float a0 = As[kk][ty*4+0], a1 = As[kk][ty*4+1];
            float a2 = As[kk][ty*4+2], a3 = As[kk][ty*4+3];
            float4 bq = *(float4*)&Bs[kk][tx*4];
            acc[0][0] += a0*bq.x; acc[0][1] += a0*bq.y; acc[0][2] += a0*bq.z; acc[0][3] += a0*bq.w;
            acc[1][0] += a1*bq.x; acc[1][1] += a1*bq.y; acc[1][2] += a1*bq.z; acc[1][3] += a1*bq.w;
            acc[2][0] += a2*bq.x; acc[2][1] += a2*bq.y; acc[2][2] += a2*bq.z; acc[2][3] += a2*bq.w;
            acc[3][0] += a3*bq.x; acc[3][1] += a3*bq.y; acc[3][2] += a3*bq.z; acc[3][3] += a3*bq.w;
        }
        __syncthreads();
    }
    #pragma unroll
    for (int i = 0; i < 4; i++) {
        int m = m0 + ty*4 + i;
        #pragma unroll
        for (int j = 0; j < 4; j++) {
            int n = n0 + tx*4 + j;
            float v = acc[i][j];
            if (bias) v += bias[n];
            if (addM) v += addM[(size_t)m*N + n];
            if (act == 1) v = tanhf(v);
            C[(size_t)m*N + n] = v;
        }
    }
}

// ------------------------- persistent encoder LSTM (all 128 steps) ----------
// 16 co-resident blocks; block bi owns h-columns [bi*16, bi*16+16).
// Cross-block step barrier: threadfence + L2 atomic counter; h via __ldcg.
__global__ __launch_bounds__(256) void enc_all_kernel() {
    __shared__ float hs[BB][HH];
    __shared__ float pre[4][16][BB];
    __shared__ float csm[BB][16];
    int tid = threadIdx.x;
    int gate = tid >> 6;            // 0..3
    int nl = (tid >> 2) & 15;       // 0..15
    int quarter = tid & 3;          // k-range quarter
    int n = blockIdx.x * 16 + nl;
    int gcol = gate * 256 + n;
    const float* Wcol = &g_WhhET[(size_t)gcol * 256 + quarter * 64];
    if (tid < 128) csm[tid >> 4][tid & 15] = 0.f;

    for (int t = 0; t < TT; t++) {
        const float* hin = (t & 1) ? g_hB : g_hA;
        float*       hout = (t & 1) ? g_hA : g_hB;
        __syncthreads();
        for (int i = tid; i < BB*HH/4; i += 256) {
            float4 v = __ldcg(((const float4*)hin) + i);
            ((float4*)&hs[0][0])[i] = v;
        }
        __syncthreads();

        float acc[BB];
        #pragma unroll
        for (int b = 0; b < BB; b++) acc[b] = 0.f;
        #pragma unroll
        for (int k4 = 0; k4 < 16; k4++) {
            float4 w = *(const float4*)&Wcol[k4*4];
            int k = quarter*64 + k4*4;
            #pragma unroll
            for (int b = 0; b < BB; b++) {
                float4 hv = *(const float4*)&hs[b][k];
                acc[b] += w.x*hv.x + w.y*hv.y + w.z*hv.z + w.w*hv.w;
            }
        }
        #pragma unroll
        for (int off = 1; off <= 2; off <<= 1)
            #pragma unroll
            for (int b = 0; b < BB; b++)
                acc[b] += __shfl_xor_sync(0xffffffff, acc[b], off);
        if (quarter == 0) {
            #pragma unroll
            for (int b = 0; b < BB; b++) pre[gate][nl][b] = acc[b];
        }
        __syncthreads();

        if (tid < 128) {
            int b = tid >> 4, nn = tid & 15;
            int nc = blockIdx.x*16 + nn;
            const float* pr = &g_preE[((size_t)t*BB + b) * G4];
            float gi = pre[0][nn][b] + pr[nc];
            float gf = pre[1][nn][b] + pr[256+nc];
            float gg = pre[2][nn][b] + pr[512+nc];
            float go = pre[3][nn][b] + pr[768+nc];
            float c = sigf(gf)*csm[b][nn] + sigf(gi)*tanhf(gg);
            float h = sigf(go)*tanhf(c);
            csm[b][nn] = c;
            hout[b*HH + nc] = h;
            g_enc[((size_t)t*BB + b)*HH + nc] = 0.5f*h;
        }
        __threadfence();       // release: all h/enc writes visible at gpu scope
        __syncthreads();
        if (tid == 0) {
            atomicAdd(&g_bar[t], 1);
            while (atomicAdd(&g_bar[t], 0) < ENCB) { }
        }
        __syncthreads();
    }
}

// ------------------------- build decoder per-step input projections ----------
__global__ void decih_kernel(const float* __restrict__ b_d) {
    int blk = blockIdx.x;              // 5*1024
    int s = blk >> 10, rr = blk & 1023;
    float* dst = &g_decIh[((size_t)s*1024 + rr)*G4];
    int tid = threadIdx.x;             // 256, 4 each
    if (rr >= 1008) {
        for (int i = 0; i < 4; i++) dst[tid*4 + i] = 0.f;
        return;
    }
    int j = (rr >> 3) + 1, b = rr & 7;
    const float* src;
    if (s == 0) src = &g_startIh[(size_t)rr*G4];
    else {
        int t = j + s - 1;
        if (t < TT) src = &g_winIh[(size_t)(t*BB + b)*G4];
        else        src = 0;
    }
    if (src) *(float4*)&dst[tid*4] = *(const float4*)&src[tid*4];
    else     *(float4*)&dst[tid*4] = *(const float4*)&b_d[tid*4];
}

// ------------------------- decoder LSTM cell ---------------------------------
__global__ void dec_cell_kernel(int s) {
    int rr = blockIdx.x;               // 1008
    int n = threadIdx.x;               // 256
    const float* g = &g_gates[(size_t)rr*G4];
    float gi = g[n], gf = g[256+n], gg = g[512+n], go = g[768+n];
    float c = sigf(gf) * g_cD[rr*HH + n] + sigf(gi) * tanhf(gg);
    float h = sigf(go) * tanhf(c);
    g_cD[rr*HH + n] = c;
    g_hD[rr*HH + n] = h;
    g_hdec[((size_t)s*1008 + rr)*HH + n] = h;
}

// ------------------------- big vocab GEMM with online (max,sumexp) -----------
// grid (NCH, RPAD/128). 128x128 tile, 8x8 per thread, K=256.
__global__ __launch_bounds__(256) void lse_gemm2(const float* __restrict__ E) {
    __shared__ float As[8][132];
    __shared__ float Bs[8][132];
    int v0 = blockIdx.x * 128;
    int m0 = blockIdx.y * 128;
    int tid = threadIdx.x;
    int tx = tid & 15, ty = tid >> 4;
    int lrow = tid >> 1, lkq = (tid & 1) * 4;
    const float* Ap = g_u + (size_t)(m0 + lrow) * HH + lkq;
    const float* Bp = E   + (size_t)(v0 + lrow) * DD + lkq;

    float acc[8][8];
    #pragma unroll
    for (int i = 0; i < 8; i++)
        #pragma unroll
        for (int j = 0; j < 8; j++) acc[i][j] = 0.f;

    float4 av = *(const float4*)Ap;
    float4 bv = *(const float4*)Bp;

    for (int k0 = 0; k0 < 256; k0 += 8) {
        As[lkq+0][lrow] = av.x; As[lkq+1][lrow] = av.y;
        As[lkq+2][lrow] = av.z; As[lkq+3][lrow] = av.w;
        Bs[lkq+0][lrow] = bv.x; Bs[lkq+1][lrow] = bv.y;
        Bs[lkq+2][lrow] = bv.z; Bs[lkq+3][lrow] = bv.w;
        __syncthreads();
        if (k0 + 8 < 256) {
            av = *(const float4*)(Ap + k0 + 8);
            bv = *(const float4*)(Bp + k0 + 8);
        }
        #pragma unroll
        for (int kk = 0; kk < 8; kk++) {
            float a[8], b[8];
            *(float4*)&a[0] = *(float4*)&As[kk][ty*4];
            *(float4*)&a[4] = *(float4*)&As[kk][64 + ty*4];
            *(float4*)&b[0] = *(float4*)&Bs[kk][tx*4];
            *(float4*)&b[4] = *(float4*)&Bs[kk][64 + tx*4];
            #pragma unroll
            for (int i = 0; i < 8; i++)
                #pragma unroll
                for (int j = 0; j < 8; j++)
                    acc[i][j] += a[i]*b[j];
        }
        __syncthreads();
    }

    // per-row (max, sumexp): local over 8 cols, then merge across 16 lanes
    #pragma unroll
    for (int i = 0; i < 8; i++) {
        float mx = acc[i][0];
        #pragma unroll
        for (int j = 1; j < 8; j++) mx = fmaxf(mx, acc[i][j]);
        float s = 0.f;
        #pragma unroll
        for (int j = 0; j < 8; j++) s += expf(acc[i][j] - mx);
        #pragma unroll
        for (int off = 1; off <= 8; off <<= 1) {
            float om = __shfl_xor_sync(0xffffffff, mx, off);
            float os = __shfl_xor_sync(0xffffffff, s,  off);
            float M = fmaxf(mx, om);
            s = s*expf(mx - M) + os*expf(om - M);
            mx = M;
        }
        if (tx == 0) {
            int m_local = (i < 4) ? (ty*4 + i) : (64 + ty*4 + (i-4));
            g_pM[(size_t)blockIdx.x*RPAD + m0 + m_local] = mx;
            g_pS[(size_t)blockIdx.x*RPAD + m0 + m_local] = s;
        }
    }
}

// ------------------------- merge chunk partials -> LSE -----------------------
__global__ void lse_merge_kernel() {
    int r = blockIdx.x * 4 + (threadIdx.x >> 5);   // grid 1260
    int lane = threadIdx.x & 31;
    if (r >= NROWS) return;
    float lm[8], ls[8];
    float mx = -LOGINF;
    #pragma unroll
    for (int i = 0; i < 8; i++) {
        int c = lane + i*32;
        if (c < NCH) { lm[i] = g_pM[(size_t)c*RPAD + r]; ls[i] = g_pS[(size_t)c*RPAD + r]; }
        else         { lm[i] = -LOGINF; ls[i] = 0.f; }
        mx = fmaxf(mx, lm[i]);
    }
    #pragma unroll
    for (int off = 16; off > 0; off >>= 1)
        mx = fmaxf(mx, __shfl_xor_sync(0xffffffff, mx, off));
    float s = 0.f;
    #pragma unroll
    for (int i = 0; i < 8; i++) s += ls[i] * expf(lm[i] - mx);
    #pragma unroll
    for (int off = 16; off > 0; off >>= 1)
        s += __shfl_xor_sync(0xffffffff, s, off);
    if (lane == 0) g_lse[r] = mx + logf(s);
}

// ------------------------- per-row tgt + EOS log-probs -----------------------
__global__ void tgt_eos_kernel(const int* __restrict__ x, const float* __restrict__ E) {
    __shared__ float red[4];
    int r = blockIdx.x;                 // 5040
    int s = r / 1008, rem = r % 1008;
    int j = (rem >> 3) + 1, b = rem & 7;
    int tt = j + s;
    int tok = (tt < TT) ? x[b*TT + tt] : 0;
    int tid = threadIdx.x;              // 64
    float4 uv = *(const float4*)&g_u[(size_t)r*HH + tid*4];
    float4 et = *(const float4*)&E[(size_t)tok*DD + tid*4];
    float4 ee = *(const float4*)&E[(size_t)EOS_TOK*DD + tid*4];
    float dt = uv.x*et.x + uv.y*et.y + uv.z*et.z + uv.w*et.w;
    float de = uv.x*ee.x + uv.y*ee.y + uv.z*ee.z + uv.w*ee.w;
    #pragma unroll
    for (int off = 16; off > 0; off >>= 1) {
        dt += __shfl_xor_sync(0xffffffff, dt, off);
        de += __shfl_xor_sync(0xffffffff, de, off);
    }
    if ((tid & 31) == 0) { red[(tid >> 5)*2] = dt; red[(tid >> 5)*2 + 1] = de; }
    __syncthreads();
    if (tid == 0) {
        float lse = g_lse[r];
        g_tlp[r] = red[0] + red[2] - lse;
        g_elp[r] = red[1] + red[3] - lse;
    }
}

// ------------------------- assemble logpy ------------------------------------
__device__ __forceinline__ float is_single_tok(const int* x, int t, int b) {
    if (t >= TT) return 0.f;
    int tok = x[b*TT + t];
    return (tok == 2 || tok == 3 || tok == 4) ? -LOGINF : 0.f;
}

__global__ void logpy_kernel(const int* __restrict__ x) {
    int tid = blockIdx.x * 256 + threadIdx.x;   // grid 4
    if (tid >= 1008) return;
    int j = (tid >> 3) + 1, b = tid & 7;
    float iss0 = is_single_tok(x, j, b);
    float csum = 0.f;
    #pragma unroll
    for (int k = 0; k < LLEN; k++) {
        int rbase = (j-1)*8 + b;
        float tl = g_tlp[k*1008 + rbase];
        float el = g_elp[(k+1)*1008 + rbase];
        float addk = (k == 0) ? 0.f : is_single_tok(x, j + k, b);
        csum += tl + addk;
        float v = csum + ((k >= 1) ? iss0 : 0.f) + el + 1.0f;
        if (k > TT - 2 - j) v = -LOGINF;
        g_logpy[((size_t)j*LLEN + k)*BB + b] = v;
    }
}

// ------------------------- segmental DP + final reduction --------------------
__global__ void dp_kernel(const int* __restrict__ lengths, float* __restrict__ out) {
    __shared__ float alpha[TT-1][BB];
    __shared__ float nll_s[BB];
    int b = threadIdx.x;                 // 32 threads, 8 active
    if (b < BB) {
        float buf[LLEN];
        buf[0] = -LOGINF; buf[1] = -LOGINF; buf[2] = -LOGINF; buf[3] = 0.f;
        alpha[0][b] = 0.f;
        for (int m = 1; m <= TT-2; m++) {
            float c[LLEN];
            #pragma unroll
            for (int k = 0; k < LLEN; k++) {
                int idx = m - k;
                float d = (idx >= 1) ? g_logpy[((size_t)idx*LLEN + k)*BB + b] : -LOGINF;
                c[k] = buf[LLEN-1-k] + d;
            }
            float mx = fmaxf(fmaxf(c[0], c[1]), fmaxf(c[2], c[3]));
            float a = mx + logf(expf(c[0]-mx) + expf(c[1]-mx) + expf(c[2]-mx) + expf(c[3]-mx));
            buf[0] = buf[1]; buf[1] = buf[2]; buf[2] = buf[3]; buf[3] = a;
            alpha[m][b] = a;
        }
        nll_s[b] = -alpha[lengths[b] - 2][b];
    }
    __syncthreads();
    if (b == 0) {
        float tot = 0.f; int tl = 0;
        for (int i = 0; i < BB; i++) { tot += nll_s[i]; tl += lengths[i]; }
        out[0] = tot / (float)(tl - 2*BB);
    }
}

// ------------------------- host launch ---------------------------------------
extern "C" void kernel_launch(void* const* d_in, const int* in_sizes, int n_in,
                              void* d_out, int out_size) {
    const int*   x        = (const int*)  d_in[0];
    const int*   lengths  = (const int*)  d_in[1];
    const float* E        = (const float*)d_in[2];
    const float* W_ih_e   = (const float*)d_in[3];
    const float* W_hh_e   = (const float*)d_in[4];
    const float* b_e      = (const float*)d_in[5];
    const float* W_start  = (const float*)d_in[6];
    const float* W_ih_d   = (const float*)d_in[7];
    const float* W_hh_d   = (const float*)d_in[8];
    const float* b_d      = (const float*)d_in[9];
    const float* W_proj   = (const float*)d_in[10];
    float* out = (float*)d_out;

    float *p_emb, *p_preE, *p_enc, *p_seg, *p_startIh, *p_winIh, *p_decIh;
    float *p_hD, *p_gates, *p_hdec, *p_u;
    cudaGetSymbolAddress((void**)&p_emb, g_emb);
    cudaGetSymbolAddress((void**)&p_preE, g_preE);
    cudaGetSymbolAddress((void**)&p_enc, g_enc);
    cudaGetSymbolAddress((void**)&p_seg, g_seg);
    cudaGetSymbolAddress((void**)&p_startIh, g_startIh);
    cudaGetSymbolAddress((void**)&p_winIh, g_winIh);
    cudaGetSymbolAddress((void**)&p_decIh, g_decIh);
    cudaGetSymbolAddress((void**)&p_hD, g_hD);
    cudaGetSymbolAddress((void**)&p_gates, g_gates);
    cudaGetSymbolAddress((void**)&p_hdec, g_hdec);
    cudaGetSymbolAddress((void**)&p_u, g_u);

    init_kernel<<<1024, 256>>>();
    embed_kernel<<<TT*BB, 64>>>(x, E);
    transpose_kernel<<<1024, 256>>>(W_hh_e);

    // preE = emb @ W_ih_e + b_e   (1024 x 1024, K=256)
    gemm_kernel<<<dim3(16, 16), 256>>>(p_emb, W_ih_e, b_e, 0, p_preE, 1024, 1024, 256, 0);

    // full encoder recurrence in ONE persistent kernel
    enc_all_kernel<<<ENCB, 256>>>();

    // seg = tanh(enc @ W_start)   (1024 x 256)
    gemm_kernel<<<dim3(4, 16), 256>>>(p_enc, W_start, 0, 0, p_seg, 1024, 256, 256, 1);
    // startIh = seg @ W_ih_d + b_d  (1024 x 1024)
    gemm_kernel<<<dim3(16, 16), 256>>>(p_seg, W_ih_d, b_d, 0, p_startIh, 1024, 1024, 256, 0);
    // winIh = emb @ W_ih_d + b_d   (1024 x 1024)
    gemm_kernel<<<dim3(16, 16), 256>>>(p_emb, W_ih_d, b_d, 0, p_winIh, 1024, 1024, 256, 0);

    decih_kernel<<<5*1024, 256>>>(b_d);

    for (int s = 0; s < 5; s++) {
        gemm_kernel<<<dim3(16, 16), 256>>>(p_hD, W_hh_d, 0, p_decIh + (size_t)s*1024*G4,
                                           p_gates, 1024, 1024, 256, 0);
        dec_cell_kernel<<<1008, 256>>>(s);
    }

    // u = hdec @ W_proj   (5120 x 256)
    gemm_kernel<<<dim3(4, 80), 256>>>(p_hdec, W_proj, 0, 0, p_u, RPAD, 256, 256, 0);

    lse_gemm2<<<dim3(NCH, RPAD/128), 256>>>(E);
    lse_merge_kernel<<<(NROWS + 3)/4, 128>>>();
    tgt_eos_kernel<<<NROWS, 64>>>(x, E);
    logpy_kernel<<<4, 256>>>(x);
    dp_kernel<<<1, 32>>>(lengths, out);
}

// round 6
// speedup vs baseline: 3.2655x; 1.3201x over previous
#include <cuda_runtime.h>
#include <cuda_bf16.h>
#include <math.h>
#include <stdint.h>

#define VV 32000
#define DD 256
#define HH 256
#define LLEN 4
#define TT 128
#define BB 8
#define G4 1024
#define NROWS 5040      // 5 steps * 126 starts * 8 batch
#define RPAD 5120       // 40 * 128
#define NCHB 250        // 32000/128 vocab chunks
#define LOGINF 1000000.0f
#define EOS_TOK 1
#define ENCB 16
#define KSPLIT 768      // bf16 split K
#define CHUNKS 12       // 768/64

// ------------------------- device scratch (globals) -------------------------
__device__ float g_emb[TT*BB*DD];
__device__ float g_WhhET[G4*HH];
__device__ float g_preE[TT*BB*G4];
__device__ float g_hA[BB*HH];
__device__ float g_hB[BB*HH];
__device__ float g_enc[TT*BB*HH];
__device__ float g_seg[TT*BB*HH];
__device__ float g_startIh[TT*BB*G4];
__device__ float g_winIh[TT*BB*G4];
__device__ float g_decIh[5*1024*G4];
__device__ float g_hD[1024*HH];
__device__ float g_cD[1024*HH];
__device__ float g_gates[1024*G4];
__device__ float g_hdec[RPAD*HH];
__device__ float g_u[RPAD*HH];
__device__ __align__(16) __nv_bfloat16 g_uSplit[(size_t)RPAD*KSPLIT];   // [hi|lo|hi]
__device__ __align__(16) __nv_bfloat16 g_eSplit[(size_t)VV*KSPLIT];     // [hi|hi|lo]
__device__ float g_pM[(size_t)NCHB*RPAD];
__device__ float g_pS[(size_t)NCHB*RPAD];
__device__ float g_lse[RPAD];
__device__ float g_tlp[RPAD];
__device__ float g_elp[RPAD];
__device__ float g_logpy[(TT-1)*LLEN*BB];
__device__ int   g_bar[TT];

__device__ __forceinline__ float sigf(float x) { return 1.0f / (1.0f + expf(-x)); }

// FMA-pipe exp (no MUFU): magic-number rint + 2^f poly + exponent splice.
__device__ __forceinline__ float fexp(float x) {
    float t = fmaf(x, 1.442695041f, 12582912.0f);
    int   k = __float_as_int(t) - 0x4B400000;
    float kf = t - 12582912.0f;
    float f = fmaf(x, 1.442695041f, -kf);
    float p = 1.54035304e-4f;
    p = fmaf(p, f, 1.33335581e-3f);
    p = fmaf(p, f, 9.61812911e-3f);
    p = fmaf(p, f, 5.55041087e-2f);
    p = fmaf(p, f, 2.40226507e-1f);
    p = fmaf(p, f, 6.93147180e-1f);
    p = fmaf(p, f, 1.0f);
    float r = __int_as_float(__float_as_int(p) + (k << 23));
    return (x < -87.0f) ? 0.0f : r;
}

__device__ __forceinline__ uint32_t smem_u32(const void* p) {
    uint32_t a;
    asm("{ .reg .u64 t; cvta.to.shared.u64 t, %1; cvt.u32.u64 %0, t; }" : "=r"(a) : "l"(p));
    return a;
}

#define LDMX4(r0,r1,r2,r3,addr)                                               \
    asm volatile("ldmatrix.sync.aligned.m8n8.x4.shared.b16 {%0,%1,%2,%3}, [%4];" \
        : "=r"(r0), "=r"(r1), "=r"(r2), "=r"(r3) : "r"(addr))

#define MMA16816(c, a, b)                                                     \
    asm volatile("mma.sync.aligned.m16n8k16.row.col.f32.bf16.bf16.f32 "       \
        "{%0,%1,%2,%3}, {%4,%5,%6,%7}, {%8,%9}, {%0,%1,%2,%3};"               \
        : "+f"((c)[0]), "+f"((c)[1]), "+f"((c)[2]), "+f"((c)[3])              \
        : "r"((a)[0]), "r"((a)[1]), "r"((a)[2]), "r"((a)[3]),                 \
          "r"((b)[0]), "r"((b)[1]))

#define CPA16(dst, src)  asm volatile("cp.async.cg.shared.global [%0], [%1], 16;" :: "r"(dst), "l"(src))
#define CPA_COMMIT()     asm volatile("cp.async.commit_group;")
#define CPA_WAIT1()      asm volatile("cp.async.wait_group 1;")
#define CPA_WAIT0()      asm volatile("cp.async.wait_group 0;")

// ------------------------- init --------------------------------------------
__global__ void init_kernel() {
    int i = blockIdx.x * 256 + threadIdx.x;
    if (i < 1024*HH) { g_hD[i] = 0.f; g_cD[i] = 0.f; }
    if (i < BB*HH)   { g_hA[i] = 0.f; g_hB[i] = 0.f; }
    if (i < TT)      g_bar[i] = 0;
}

// ------------------------- embedding gather ---------------------------------
__global__ void embed_kernel(const int* __restrict__ x, const float* __restrict__ E) {
    int tb = blockIdx.x;
    int t = tb >> 3, b = tb & 7;
    int tok = x[b*TT + t];
    int d = threadIdx.x * 4;
    *(float4*)&g_emb[(size_t)tb*DD + d] = *(const float4*)&E[(size_t)tok*DD + d];
}

// ------------------------- transpose W_hh_e ---------------------------------
__global__ void transpose_kernel(const float* __restrict__ W) {
    int idx = blockIdx.x * 256 + threadIdx.x;
    int n = idx >> 8, k = idx & 255;
    g_WhhET[idx] = W[(size_t)k*G4 + n];
}

// ------------------------- generic fp32 GEMM 64x64 tile ----------------------
__global__ __launch_bounds__(256) void gemm_kernel(
    const float* __restrict__ A, const float* __restrict__ Bm,
    const float* __restrict__ bias, const float* __restrict__ addM,
    float* __restrict__ C, int M, int N, int K, int act)
{
    __shared__ float As[16][68];
    __shared__ float Bs[16][68];
    int n0 = blockIdx.x * 64, m0 = blockIdx.y * 64;
    int tid = threadIdx.x;
    int tx = tid & 15, ty = tid >> 4;
    float acc[4][4];
    #pragma unroll
    for (int i = 0; i < 4; i++)
        #pragma unroll
        for (int j = 0; j < 4; j++) acc[i][j] = 0.f;

    int arow = tid >> 2, akk = (tid & 3) << 2;
    int bkk  = tid >> 4, bnc = (tid & 15) << 2;

    for (int k0 = 0; k0 < K; k0 += 16) {
        float4 av = *(const float4*)&A[(size_t)(m0 + arow)*K + k0 + akk];
        As[akk+0][arow] = av.x; As[akk+1][arow] = av.y;
        As[akk+2][arow] = av.z; As[akk+3][arow] = av.w;
        *(float4*)&Bs[bkk][bnc] = *(const float4*)&Bm[(size_t)(k0 + bkk)*N + n0 + bnc];
        __syncthreads();
        #pragma unroll
        for (int kk = 0; kk < 16; kk++) {
            float a0 = As[kk][ty*4+0], a1 = As[kk][ty*4+1];
            float a2 = As[kk][ty*4+2], a3 = As[kk][ty*4+3];
            float4 bq = *(float4*)&Bs[kk][tx*4];
            acc[0][0] += a0*bq.x; acc[0][1] += a0*bq.y; acc[0][2] += a0*bq.z; acc[0][3] += a0*bq.w;
            acc[1][0] += a1*bq.x; acc[1][1] += a1*bq.y; acc[1][2] += a1*bq.z; acc[1][3] += a1*bq.w;
            acc[2][0] += a2*bq.x; acc[2][1] += a2*bq.y; acc[2][2] += a2*bq.z; acc[2][3] += a2*bq.w;
            acc[3][0] += a3*bq.x; acc[3][1] += a3*bq.y; acc[3][2] += a3*bq.z; acc[3][3] += a3*bq.w;
        }
        __syncthreads();
    }
    #pragma unroll
    for (int i = 0; i < 4; i++) {
        int m = m0 + ty*4 + i;
        #pragma unroll
        for (int j = 0; j < 4; j++) {
            int n = n0 + tx*4 + j;
            float v = acc[i][j];
            if (bias) v += bias[n];
            if (addM) v += addM[(size_t)m*N + n];
            if (act == 1) v = tanhf(v);
            C[(size_t)m*N + n] = v;
        }
    }
}

// ------------------------- persistent encoder LSTM ---------------------------
__global__ __launch_bounds__(256) void enc_all_kernel() {
    __shared__ float hs[BB][HH];
    __shared__ float pre[4][16][BB];
    __shared__ float csm[BB][16];
    int tid = threadIdx.x;
    int gate = tid >> 6;
    int nl = (tid >> 2) & 15;
    int quarter = tid & 3;
    int n = blockIdx.x * 16 + nl;
    int gcol = gate * 256 + n;
    const float* Wcol = &g_WhhET[(size_t)gcol * 256 + quarter * 64];
    if (tid < 128) csm[tid >> 4][tid & 15] = 0.f;

    for (int t = 0; t < TT; t++) {
        const float* hin  = (t & 1) ? g_hB : g_hA;
        float*       hout = (t & 1) ? g_hA : g_hB;
        __syncthreads();
        for (int i = tid; i < BB*HH/4; i += 256) {
            float4 v = __ldcg(((const float4*)hin) + i);
            ((float4*)&hs[0][0])[i] = v;
        }
        __syncthreads();

        float acc[BB];
        #pragma unroll
        for (int b = 0; b < BB; b++) acc[b] = 0.f;
        #pragma unroll
        for (int k4 = 0; k4 < 16; k4++) {
            float4 w = *(const float4*)&Wcol[k4*4];
            int k = quarter*64 + k4*4;
            #pragma unroll
            for (int b = 0; b < BB; b++) {
                float4 hv = *(const float4*)&hs[b][k];
                acc[b] += w.x*hv.x + w.y*hv.y + w.z*hv.z + w.w*hv.w;
            }
        }
        #pragma unroll
        for (int off = 1; off <= 2; off <<= 1)
            #pragma unroll
            for (int b = 0; b < BB; b++)
                acc[b] += __shfl_xor_sync(0xffffffff, acc[b], off);
        if (quarter == 0) {
            #pragma unroll
            for (int b = 0; b < BB; b++) pre[gate][nl][b] = acc[b];
        }
        __syncthreads();

        if (tid < 128) {
            int b = tid >> 4, nn = tid & 15;
            int nc = blockIdx.x*16 + nn;
            const float* pr = &g_preE[((size_t)t*BB + b) * G4];
            float gi = pre[0][nn][b] + pr[nc];
            float gf = pre[1][nn][b] + pr[256+nc];
            float gg = pre[2][nn][b] + pr[512+nc];
            float go = pre[3][nn][b] + pr[768+nc];
            float c = sigf(gf)*csm[b][nn] + sigf(gi)*tanhf(gg);
            float h = sigf(go)*tanhf(c);
            csm[b][nn] = c;
            hout[b*HH + nc] = h;
            g_enc[((size_t)t*BB + b)*HH + nc] = 0.5f*h;
        }
        __threadfence();
        __syncthreads();
        if (tid == 0) {
            atomicAdd(&g_bar[t], 1);
            while (atomicAdd(&g_bar[t], 0) < ENCB) { }
        }
        __syncthreads();
    }
}

// ------------------------- decoder input staging -----------------------------
__global__ void decih_kernel(const float* __restrict__ b_d) {
    int blk = blockIdx.x;
    int s = blk >> 10, rr = blk & 1023;
    float* dst = &g_decIh[((size_t)s*1024 + rr)*G4];
    int tid = threadIdx.x;
    if (rr >= 1008) {
        for (int i = 0; i < 4; i++) dst[tid*4 + i] = 0.f;
        return;
    }
    int j = (rr >> 3) + 1, b = rr & 7;
    const float* src;
    if (s == 0) src = &g_startIh[(size_t)rr*G4];
    else {
        int t = j + s - 1;
        if (t < TT) src = &g_winIh[(size_t)(t*BB + b)*G4];
        else        src = 0;
    }
    if (src) *(float4*)&dst[tid*4] = *(const float4*)&src[tid*4];
    else     *(float4*)&dst[tid*4] = *(const float4*)&b_d[tid*4];
}

// ------------------------- decoder LSTM cell ---------------------------------
__global__ void dec_cell_kernel(int s) {
    int rr = blockIdx.x;
    int n = threadIdx.x;
    const float* g = &g_gates[(size_t)rr*G4];
    float gi = g[n], gf = g[256+n], gg = g[512+n], go = g[768+n];
    float c = sigf(gf) * g_cD[rr*HH + n] + sigf(gi) * tanhf(gg);
    float h = sigf(go) * tanhf(c);
    g_cD[rr*HH + n] = c;
    g_hD[rr*HH + n] = h;
    g_hdec[((size_t)s*1008 + rr)*HH + n] = h;
}

// ------------------------- bf16 hi/lo splits ---------------------------------
__global__ void split_u_kernel() {
    int m = blockIdx.x, d = threadIdx.x;
    float u = g_u[(size_t)m*HH + d];
    __nv_bfloat16 hi = __float2bfloat16(u);
    __nv_bfloat16 lo = __float2bfloat16(u - __bfloat162float(hi));
    size_t base = (size_t)m*KSPLIT;
    g_uSplit[base + d]       = hi;
    g_uSplit[base + 256 + d] = lo;
    g_uSplit[base + 512 + d] = hi;
}
__global__ void split_e_kernel(const float* __restrict__ E) {
    int v = blockIdx.x, d = threadIdx.x;
    float e = E[(size_t)v*DD + d];
    __nv_bfloat16 hi = __float2bfloat16(e);
    __nv_bfloat16 lo = __float2bfloat16(e - __bfloat162float(hi));
    size_t base = (size_t)v*KSPLIT;
    g_eSplit[base + d]       = hi;
    g_eSplit[base + 256 + d] = hi;
    g_eSplit[base + 512 + d] = lo;
}

// ------------------------- bf16 HMMA vocab GEMM + online LSE -----------------
// grid (250, 40) x 256 thr. CTA tile: 128 u-rows x 128 vocab, K=768.
// 8 warps = 4(m) x 2(n); warp tile 32x64 via m16n8k16 mma.
// Dyn smem 64KB: [A0 16K][B0 16K][A1 16K][B1 16K], SW128-style swizzle.
__global__ __launch_bounds__(256) void lse_mma_kernel() {
    extern __shared__ char dsm[];
    __shared__ float partM[2][128];
    __shared__ float partS[2][128];
    uint32_t sbase = smem_u32(dsm);
    int tid = threadIdx.x, lane = tid & 31, wid = tid >> 5;
    int wm = wid >> 1, wn = wid & 1;
    int v0 = blockIdx.x * 128, m0 = blockIdx.y * 128;

    const __nv_bfloat16* Abase = g_uSplit + (size_t)m0 * KSPLIT;
    const __nv_bfloat16* Bbase = g_eSplit + (size_t)v0 * KSPLIT;

    // staging: 1024 x 16B per tile; 4 per thread
    int sr[4], sc[4]; uint32_t sso[4];
    #pragma unroll
    for (int it = 0; it < 4; it++) {
        int idx = tid + it*256;
        int r = idx >> 3, c = idx & 7;
        sr[it] = r; sc[it] = c;
        uint32_t off = (uint32_t)(r>>3)*1024u + (uint32_t)(r&7)*128u;
        sso[it] = off + (((uint32_t)c*16u) ^ ((uint32_t)(r&7)*16u));
    }

    // ldmatrix address components
    int rowA = wm*32 + (lane & 15);
    uint32_t aBase = ((uint32_t)(rowA >> 3) << 10) + ((uint32_t)(rowA & 7) << 7);
    uint32_t aH = ((uint32_t)(lane >> 4)) << 4;
    uint32_t aM = ((uint32_t)(rowA & 7)) << 4;
    int rowB = wn*64 + (lane & 7) + ((lane & 16) >> 1);
    uint32_t bBase = ((uint32_t)(rowB >> 3) << 10) + ((uint32_t)(rowB & 7) << 7);
    uint32_t bH = ((uint32_t)((lane >> 3) & 1)) << 4;
    uint32_t bM = ((uint32_t)(lane & 7)) << 4;

    float acc[2][8][4];
    #pragma unroll
    for (int i = 0; i < 2; i++)
        #pragma unroll
        for (int j = 0; j < 8; j++)
            #pragma unroll
            for (int q = 0; q < 4; q++) acc[i][j][q] = 0.f;

    // issue chunk 0
    {
        #pragma unroll
        for (int it = 0; it < 4; it++) {
            const char* ga = (const char*)(Abase + (size_t)sr[it]*KSPLIT + sc[it]*8);
            const char* gb = (const char*)(Bbase + (size_t)sr[it]*KSPLIT + sc[it]*8);
            CPA16(sbase + sso[it], ga);
            CPA16(sbase + 16384u + sso[it], gb);
        }
        CPA_COMMIT();
    }

    for (int s = 0; s < CHUNKS; s++) {
        int buf = s & 1;
        if (s + 1 < CHUNKS) {
            int k0 = (s + 1) * 64;
            uint32_t dst = sbase + (uint32_t)((s+1)&1)*32768u;
            #pragma unroll
            for (int it = 0; it < 4; it++) {
                const char* ga = (const char*)(Abase + (size_t)sr[it]*KSPLIT + k0 + sc[it]*8);
                const char* gb = (const char*)(Bbase + (size_t)sr[it]*KSPLIT + k0 + sc[it]*8);
                CPA16(dst + sso[it], ga);
                CPA16(dst + 16384u + sso[it], gb);
            }
            CPA_COMMIT();
            CPA_WAIT1();
        } else {
            CPA_WAIT0();
        }
        __syncthreads();

        uint32_t sA = sbase + (uint32_t)buf*32768u;
        uint32_t sB = sA + 16384u;
        #pragma unroll
        for (int ks = 0; ks < 4; ks++) {
            uint32_t a[2][4];
            #pragma unroll
            for (int mi = 0; mi < 2; mi++) {
                uint32_t addr = sA + aBase + (uint32_t)mi*2048u + (((uint32_t)ks*32u + aH) ^ aM);
                LDMX4(a[mi][0], a[mi][1], a[mi][2], a[mi][3], addr);
            }
            uint32_t b[8][2];
            #pragma unroll
            for (int p = 0; p < 4; p++) {
                uint32_t addr = sB + bBase + (uint32_t)p*2048u + (((uint32_t)ks*32u + bH) ^ bM);
                LDMX4(b[2*p][0], b[2*p][1], b[2*p+1][0], b[2*p+1][1], addr);
            }
            #pragma unroll
            for (int mi = 0; mi < 2; mi++)
                #pragma unroll
                for (int nt = 0; nt < 8; nt++)
                    MMA16816(acc[mi][nt], a[mi], b[nt]);
        }
        __syncthreads();
    }

    // epilogue: per-row (max, sumexp) over this CTA's 128 vocab cols
    int r4 = lane >> 2;
    #pragma unroll
    for (int mi = 0; mi < 2; mi++) {
        #pragma unroll
        for (int h = 0; h < 2; h++) {
            float mx = -LOGINF;
            #pragma unroll
            for (int nt = 0; nt < 8; nt++) {
                mx = fmaxf(mx, acc[mi][nt][h*2]);
                mx = fmaxf(mx, acc[mi][nt][h*2+1]);
            }
            float sum = 0.f;
            #pragma unroll
            for (int nt = 0; nt < 8; nt++) {
                sum += fexp(acc[mi][nt][h*2]   - mx);
                sum += fexp(acc[mi][nt][h*2+1] - mx);
            }
            #pragma unroll
            for (int off = 1; off <= 2; off <<= 1) {
                float om = __shfl_xor_sync(0xffffffff, mx, off);
                float os = __shfl_xor_sync(0xffffffff, sum, off);
                float M = fmaxf(mx, om);
                sum = sum * fexp(mx - M) + os * fexp(om - M);
                mx = M;
            }
            if ((lane & 3) == 0) {
                int mloc = wm*32 + mi*16 + h*8 + r4;
                partM[wn][mloc] = mx;
                partS[wn][mloc] = sum;
            }
        }
    }
    __syncthreads();
    if (tid < 128) {
        float ma = partM[0][tid], mb = partM[1][tid];
        float M = fmaxf(ma, mb);
        float S = partS[0][tid] * fexp(ma - M) + partS[1][tid] * fexp(mb - M);
        g_pM[(size_t)blockIdx.x*RPAD + m0 + tid] = M;
        g_pS[(size_t)blockIdx.x*RPAD + m0 + tid] = S;
    }
}

// ------------------------- merge chunk partials -> LSE -----------------------
__global__ void lse_merge_kernel() {
    int r = blockIdx.x * 4 + (threadIdx.x >> 5);
    int lane = threadIdx.x & 31;
    if (r >= NROWS) return;
    float lm[8], ls[8];
    float mx = -LOGINF;
    #pragma unroll
    for (int i = 0; i < 8; i++) {
        int c = lane + i*32;
        if (c < NCHB) { lm[i] = g_pM[(size_t)c*RPAD + r]; ls[i] = g_pS[(size_t)c*RPAD + r]; }
        else          { lm[i] = -LOGINF; ls[i] = 0.f; }
        mx = fmaxf(mx, lm[i]);
    }
    #pragma unroll
    for (int off = 16; off > 0; off >>= 1)
        mx = fmaxf(mx, __shfl_xor_sync(0xffffffff, mx, off));
    float s = 0.f;
    #pragma unroll
    for (int i = 0; i < 8; i++) s += ls[i] * expf(lm[i] - mx);
    #pragma unroll
    for (int off = 16; off > 0; off >>= 1)
        s += __shfl_xor_sync(0xffffffff, s, off);
    if (lane == 0) g_lse[r] = mx + logf(s);
}

// ------------------------- per-row tgt + EOS log-probs -----------------------
__global__ void tgt_eos_kernel(const int* __restrict__ x, const float* __restrict__ E) {
    __shared__ float red[4];
    int r = blockIdx.x;
    int s = r / 1008, rem = r % 1008;
    int j = (rem >> 3) + 1, b = rem & 7;
    int tt = j + s;
    int tok = (tt < TT) ? x[b*TT + tt] : 0;
    int tid = threadIdx.x;
    float4 uv = *(const float4*)&g_u[(size_t)r*HH + tid*4];
    float4 et = *(const float4*)&E[(size_t)tok*DD + tid*4];
    float4 ee = *(const float4*)&E[(size_t)EOS_TOK*DD + tid*4];
    float dt = uv.x*et.x + uv.y*et.y + uv.z*et.z + uv.w*et.w;
    float de = uv.x*ee.x + uv.y*ee.y + uv.z*ee.z + uv.w*ee.w;
    #pragma unroll
    for (int off = 16; off > 0; off >>= 1) {
        dt += __shfl_xor_sync(0xffffffff, dt, off);
        de += __shfl_xor_sync(0xffffffff, de, off);
    }
    if ((tid & 31) == 0) { red[(tid >> 5)*2] = dt; red[(tid >> 5)*2 + 1] = de; }
    __syncthreads();
    if (tid == 0) {
        float lse = g_lse[r];
        g_tlp[r] = red[0] + red[2] - lse;
        g_elp[r] = red[1] + red[3] - lse;
    }
}

// ------------------------- assemble logpy ------------------------------------
__device__ __forceinline__ float is_single_tok(const int* x, int t, int b) {
    if (t >= TT) return 0.f;
    int tok = x[b*TT + t];
    return (tok == 2 || tok == 3 || tok == 4) ? -LOGINF : 0.f;
}

__global__ void logpy_kernel(const int* __restrict__ x) {
    int tid = blockIdx.x * 256 + threadIdx.x;
    if (tid >= 1008) return;
    int j = (tid >> 3) + 1, b = tid & 7;
    float iss0 = is_single_tok(x, j, b);
    float csum = 0.f;
    #pragma unroll
    for (int k = 0; k < LLEN; k++) {
        int rbase = (j-1)*8 + b;
        float tl = g_tlp[k*1008 + rbase];
        float el = g_elp[(k+1)*1008 + rbase];
        float addk = (k == 0) ? 0.f : is_single_tok(x, j + k, b);
        csum += tl + addk;
        float v = csum + ((k >= 1) ? iss0 : 0.f) + el + 1.0f;
        if (k > TT - 2 - j) v = -LOGINF;
        g_logpy[((size_t)j*LLEN + k)*BB + b] = v;
    }
}

// ------------------------- segmental DP + final reduction --------------------
__global__ void dp_kernel(const int* __restrict__ lengths, float* __restrict__ out) {
    __shared__ float alpha[TT-1][BB];
    __shared__ float nll_s[BB];
    int b = threadIdx.x;
    if (b < BB) {
        float buf[LLEN];
        buf[0] = -LOGINF; buf[1] = -LOGINF; buf[2] = -LOGINF; buf[3] = 0.f;
        alpha[0][b] = 0.f;
        for (int m = 1; m <= TT-2; m++) {
            float c[LLEN];
            #pragma unroll
            for (int k = 0; k < LLEN; k++) {
                int idx = m - k;
                float d = (idx >= 1) ? g_logpy[((size_t)idx*LLEN + k)*BB + b] : -LOGINF;
                c[k] = buf[LLEN-1-k] + d;
            }
            float mx = fmaxf(fmaxf(c[0], c[1]), fmaxf(c[2], c[3]));
            float a = mx + logf(expf(c[0]-mx) + expf(c[1]-mx) + expf(c[2]-mx) + expf(c[3]-mx));
            buf[0] = buf[1]; buf[1] = buf[2]; buf[2] = buf[3]; buf[3] = a;
            alpha[m][b] = a;
        }
        nll_s[b] = -alpha[lengths[b] - 2][b];
    }
    __syncthreads();
    if (b == 0) {
        float tot = 0.f; int tl = 0;
        for (int i = 0; i < BB; i++) { tot += nll_s[i]; tl += lengths[i]; }
        out[0] = tot / (float)(tl - 2*BB);
    }
}

// ------------------------- host launch ---------------------------------------
extern "C" void kernel_launch(void* const* d_in, const int* in_sizes, int n_in,
                              void* d_out, int out_size) {
    const int*   x        = (const int*)  d_in[0];
    const int*   lengths  = (const int*)  d_in[1];
    const float* E        = (const float*)d_in[2];
    const float* W_ih_e   = (const float*)d_in[3];
    const float* W_hh_e   = (const float*)d_in[4];
    const float* b_e      = (const float*)d_in[5];
    const float* W_start  = (const float*)d_in[6];
    const float* W_ih_d   = (const float*)d_in[7];
    const float* W_hh_d   = (const float*)d_in[8];
    const float* b_d      = (const float*)d_in[9];
    const float* W_proj   = (const float*)d_in[10];
    float* out = (float*)d_out;

    float *p_emb, *p_preE, *p_enc, *p_seg, *p_startIh, *p_winIh, *p_decIh;
    float *p_hD, *p_gates, *p_hdec, *p_u;
    cudaGetSymbolAddress((void**)&p_emb, g_emb);
    cudaGetSymbolAddress((void**)&p_preE, g_preE);
    cudaGetSymbolAddress((void**)&p_enc, g_enc);
    cudaGetSymbolAddress((void**)&p_seg, g_seg);
    cudaGetSymbolAddress((void**)&p_startIh, g_startIh);
    cudaGetSymbolAddress((void**)&p_winIh, g_winIh);
    cudaGetSymbolAddress((void**)&p_decIh, g_decIh);
    cudaGetSymbolAddress((void**)&p_hD, g_hD);
    cudaGetSymbolAddress((void**)&p_gates, g_gates);
    cudaGetSymbolAddress((void**)&p_hdec, g_hdec);
    cudaGetSymbolAddress((void**)&p_u, g_u);

    cudaFuncSetAttribute(lse_mma_kernel, cudaFuncAttributeMaxDynamicSharedMemorySize, 65536);

    init_kernel<<<1024, 256>>>();
    embed_kernel<<<TT*BB, 64>>>(x, E);
    transpose_kernel<<<1024, 256>>>(W_hh_e);
    split_e_kernel<<<VV, 256>>>(E);

    gemm_kernel<<<dim3(16, 16), 256>>>(p_emb, W_ih_e, b_e, 0, p_preE, 1024, 1024, 256, 0);

    enc_all_kernel<<<ENCB, 256>>>();

    gemm_kernel<<<dim3(4, 16), 256>>>(p_enc, W_start, 0, 0, p_seg, 1024, 256, 256, 1);
    gemm_kernel<<<dim3(16, 16), 256>>>(p_seg, W_ih_d, b_d, 0, p_startIh, 1024, 1024, 256, 0);
    gemm_kernel<<<dim3(16, 16), 256>>>(p_emb, W_ih_d, b_d, 0, p_winIh, 1024, 1024, 256, 0);

    decih_kernel<<<5*1024, 256>>>(b_d);

    for (int s = 0; s < 5; s++) {
        gemm_kernel<<<dim3(16, 16), 256>>>(p_hD, W_hh_d, 0, p_decIh + (size_t)s*1024*G4,
                                           p_gates, 1024, 1024, 256, 0);
        dec_cell_kernel<<<1008, 256>>>(s);
    }

    gemm_kernel<<<dim3(4, 80), 256>>>(p_hdec, W_proj, 0, 0, p_u, RPAD, 256, 256, 0);
    split_u_kernel<<<RPAD, 256>>>();

    lse_mma_kernel<<<dim3(NCHB, RPAD/128), 256, 65536>>>();
    lse_merge_kernel<<<(NROWS + 3)/4, 128>>>();
    tgt_eos_kernel<<<NROWS, 64>>>(x, E);
    logpy_kernel<<<4, 256>>>(x);
    dp_kernel<<<1, 32>>>(lengths, out);
}

// round 7
// speedup vs baseline: 3.2863x; 1.0064x over previous
#include <cuda_runtime.h>
#include <cuda_bf16.h>
#include <math.h>
#include <stdint.h>

#define VV 32000
#define DD 256
#define HH 256
#define LLEN 4
#define TT 128
#define BB 8
#define G4 1024
#define NROWS 5040      // 5 steps * 126 starts * 8 batch
#define RPAD 5120       // 40 * 128
#define NCHV 125        // 32000/256 vocab chunks
#define LOGINF 1000000.0f
#define EOS_TOK 1
#define ENCB 16
#define KSPLIT 768      // bf16 split K
#define CHUNKS 12       // 768/64

// ------------------------- device scratch (globals) -------------------------
__device__ float g_emb[TT*BB*DD];
__device__ float g_WhhET[G4*HH];
__device__ float g_preE[TT*BB*G4];
__device__ float g_hA[BB*HH];
__device__ float g_hB[BB*HH];
__device__ float g_enc[TT*BB*HH];
__device__ float g_seg[TT*BB*HH];
__device__ float g_startIh[TT*BB*G4];
__device__ float g_winIh[TT*BB*G4];
__device__ float g_decIh[5*1024*G4];
__device__ float g_hD[1024*HH];
__device__ float g_cD[1024*HH];
__device__ float g_gates[1024*G4];
__device__ float g_hdec[RPAD*HH];
__device__ float g_u[RPAD*HH];
__device__ __align__(16) __nv_bfloat16 g_uSplit[(size_t)RPAD*KSPLIT];   // [hi|lo|hi]
__device__ __align__(16) __nv_bfloat16 g_eSplit[(size_t)VV*KSPLIT];     // [hi|hi|lo]
__device__ float g_pM[(size_t)NCHV*RPAD];
__device__ float g_pS[(size_t)NCHV*RPAD];
__device__ float g_lse[RPAD];
__device__ float g_tlp[RPAD];
__device__ float g_elp[RPAD];
__device__ float g_logpy[(TT-1)*LLEN*BB];
__device__ int   g_bar[TT];

__device__ __forceinline__ float sigf(float x) { return 1.0f / (1.0f + expf(-x)); }

// FMA-pipe exp (no MUFU): magic-number rint + 2^f poly + exponent splice.
__device__ __forceinline__ float fexp(float x) {
    float t = fmaf(x, 1.442695041f, 12582912.0f);
    int   k = __float_as_int(t) - 0x4B400000;
    float kf = t - 12582912.0f;
    float f = fmaf(x, 1.442695041f, -kf);
    float p = 1.54035304e-4f;
    p = fmaf(p, f, 1.33335581e-3f);
    p = fmaf(p, f, 9.61812911e-3f);
    p = fmaf(p, f, 5.55041087e-2f);
    p = fmaf(p, f, 2.40226507e-1f);
    p = fmaf(p, f, 6.93147180e-1f);
    p = fmaf(p, f, 1.0f);
    float r = __int_as_float(__float_as_int(p) + (k << 23));
    return (x < -87.0f) ? 0.0f : r;
}

__device__ __forceinline__ uint32_t smem_u32(const void* p) {
    uint32_t a;
    asm("{ .reg .u64 t; cvta.to.shared.u64 t, %1; cvt.u32.u64 %0, t; }" : "=r"(a) : "l"(p));
    return a;
}

#define LDMX4(r0,r1,r2,r3,addr)                                               \
    asm volatile("ldmatrix.sync.aligned.m8n8.x4.shared.b16 {%0,%1,%2,%3}, [%4];" \
        : "=r"(r0), "=r"(r1), "=r"(r2), "=r"(r3) : "r"(addr))

#define MMA16816(c, a, b)                                                     \
    asm volatile("mma.sync.aligned.m16n8k16.row.col.f32.bf16.bf16.f32 "       \
        "{%0,%1,%2,%3}, {%4,%5,%6,%7}, {%8,%9}, {%0,%1,%2,%3};"               \
        : "+f"((c)[0]), "+f"((c)[1]), "+f"((c)[2]), "+f"((c)[3])              \
        : "r"((a)[0]), "r"((a)[1]), "r"((a)[2]), "r"((a)[3]),                 \
          "r"((b)[0]), "r"((b)[1]))

#define CPA16(dst, src)  asm volatile("cp.async.cg.shared.global [%0], [%1], 16;" :: "r"(dst), "l"(src))
#define CPA_COMMIT()     asm volatile("cp.async.commit_group;")
#define CPA_WAIT1()      asm volatile("cp.async.wait_group 1;")
#define CPA_WAIT0()      asm volatile("cp.async.wait_group 0;")

// swizzled offset within a K64 tile: row r (128B rows), 16B-chunk c
__device__ __forceinline__ uint32_t sw_off(int r, int c) {
    uint32_t off = (uint32_t)(r >> 3)*1024u + (uint32_t)(r & 7)*128u;
    return off + (((uint32_t)c*16u) ^ ((uint32_t)(r & 7)*16u));
}

// ------------------------- init --------------------------------------------
__global__ void init_kernel() {
    int i = blockIdx.x * 256 + threadIdx.x;
    if (i < 1024*HH) { g_hD[i] = 0.f; g_cD[i] = 0.f; }
    if (i < BB*HH)   { g_hA[i] = 0.f; g_hB[i] = 0.f; }
    if (i < TT)      g_bar[i] = 0;
}

// ------------------------- embedding gather ---------------------------------
__global__ void embed_kernel(const int* __restrict__ x, const float* __restrict__ E) {
    int tb = blockIdx.x;
    int t = tb >> 3, b = tb & 7;
    int tok = x[b*TT + t];
    int d = threadIdx.x * 4;
    *(float4*)&g_emb[(size_t)tb*DD + d] = *(const float4*)&E[(size_t)tok*DD + d];
}

// ------------------------- transpose W_hh_e ---------------------------------
__global__ void transpose_kernel(const float* __restrict__ W) {
    int idx = blockIdx.x * 256 + threadIdx.x;
    int n = idx >> 8, k = idx & 255;
    g_WhhET[idx] = W[(size_t)k*G4 + n];
}

// ------------------------- generic fp32 GEMM 64x64 tile ----------------------
// act: 0 none, 1 tanh, 2 = write u-splits as epilogue (requires N==256)
__global__ __launch_bounds__(256) void gemm_kernel(
    const float* __restrict__ A, const float* __restrict__ Bm,
    const float* __restrict__ bias, const float* __restrict__ addM,
    float* __restrict__ C, int M, int N, int K, int act)
{
    __shared__ float As[16][68];
    __shared__ float Bs[16][68];
    int n0 = blockIdx.x * 64, m0 = blockIdx.y * 64;
    int tid = threadIdx.x;
    int tx = tid & 15, ty = tid >> 4;
    float acc[4][4];
    #pragma unroll
    for (int i = 0; i < 4; i++)
        #pragma unroll
        for (int j = 0; j < 4; j++) acc[i][j] = 0.f;

    int arow = tid >> 2, akk = (tid & 3) << 2;
    int bkk  = tid >> 4, bnc = (tid & 15) << 2;

    for (int k0 = 0; k0 < K; k0 += 16) {
        float4 av = *(const float4*)&A[(size_t)(m0 + arow)*K + k0 + akk];
        As[akk+0][arow] = av.x; As[akk+1][arow] = av.y;
        As[akk+2][arow] = av.z; As[akk+3][arow] = av.w;
        *(float4*)&Bs[bkk][bnc] = *(const float4*)&Bm[(size_t)(k0 + bkk)*N + n0 + bnc];
        __syncthreads();
        #pragma unroll
        for (int kk = 0; kk < 16; kk++) {
            float a0 = As[kk][ty*4+0], a1 = As[kk][ty*4+1];
            float a2 = As[kk][ty*4+2], a3 = As[kk][ty*4+3];
            float4 bq = *(float4*)&Bs[kk][tx*4];
            acc[0][0] += a0*bq.x; acc[0][1] += a0*bq.y; acc[0][2] += a0*bq.z; acc[0][3] += a0*bq.w;
            acc[1][0] += a1*bq.x; acc[1][1] += a1*bq.y; acc[1][2] += a1*bq.z; acc[1][3] += a1*bq.w;
            acc[2][0] += a2*bq.x; acc[2][1] += a2*bq.y; acc[2][2] += a2*bq.z; acc[2][3] += a2*bq.w;
            acc[3][0] += a3*bq.x; acc[3][1] += a3*bq.y; acc[3][2] += a3*bq.z; acc[3][3] += a3*bq.w;
        }
        __syncthreads();
    }
    #pragma unroll
    for (int i = 0; i < 4; i++) {
        int m = m0 + ty*4 + i;
        #pragma unroll
        for (int j = 0; j < 4; j++) {
            int n = n0 + tx*4 + j;
            float v = acc[i][j];
            if (bias) v += bias[n];
            if (addM) v += addM[(size_t)m*N + n];
            if (act == 1) v = tanhf(v);
            C[(size_t)m*N + n] = v;
            if (act == 2) {
                __nv_bfloat16 hi = __float2bfloat16(v);
                __nv_bfloat16 lo = __float2bfloat16(v - __bfloat162float(hi));
                size_t sb = (size_t)m*KSPLIT + n;
                g_uSplit[sb]       = hi;
                g_uSplit[sb + 256] = lo;
                g_uSplit[sb + 512] = hi;
            }
        }
    }
}

// ------------------------- persistent encoder LSTM ---------------------------
__global__ __launch_bounds__(256) void enc_all_kernel() {
    __shared__ float hs[BB][HH];
    __shared__ float pre[4][16][BB];
    __shared__ float csm[BB][16];
    int tid = threadIdx.x;
    int gate = tid >> 6;
    int nl = (tid >> 2) & 15;
    int quarter = tid & 3;
    int n = blockIdx.x * 16 + nl;
    int gcol = gate * 256 + n;
    const float* Wcol = &g_WhhET[(size_t)gcol * 256 + quarter * 64];
    if (tid < 128) csm[tid >> 4][tid & 15] = 0.f;

    for (int t = 0; t < TT; t++) {
        const float* hin  = (t & 1) ? g_hB : g_hA;
        float*       hout = (t & 1) ? g_hA : g_hB;
        __syncthreads();
        for (int i = tid; i < BB*HH/4; i += 256) {
            float4 v = __ldcg(((const float4*)hin) + i);
            ((float4*)&hs[0][0])[i] = v;
        }
        __syncthreads();

        float acc[BB];
        #pragma unroll
        for (int b = 0; b < BB; b++) acc[b] = 0.f;
        #pragma unroll
        for (int k4 = 0; k4 < 16; k4++) {
            float4 w = *(const float4*)&Wcol[k4*4];
            int k = quarter*64 + k4*4;
            #pragma unroll
            for (int b = 0; b < BB; b++) {
                float4 hv = *(const float4*)&hs[b][k];
                acc[b] += w.x*hv.x + w.y*hv.y + w.z*hv.z + w.w*hv.w;
            }
        }
        #pragma unroll
        for (int off = 1; off <= 2; off <<= 1)
            #pragma unroll
            for (int b = 0; b < BB; b++)
                acc[b] += __shfl_xor_sync(0xffffffff, acc[b], off);
        if (quarter == 0) {
            #pragma unroll
            for (int b = 0; b < BB; b++) pre[gate][nl][b] = acc[b];
        }
        __syncthreads();

        if (tid < 128) {
            int b = tid >> 4, nn = tid & 15;
            int nc = blockIdx.x*16 + nn;
            const float* pr = &g_preE[((size_t)t*BB + b) * G4];
            float gi = pre[0][nn][b] + pr[nc];
            float gf = pre[1][nn][b] + pr[256+nc];
            float gg = pre[2][nn][b] + pr[512+nc];
            float go = pre[3][nn][b] + pr[768+nc];
            float c = sigf(gf)*csm[b][nn] + sigf(gi)*tanhf(gg);
            float h = sigf(go)*tanhf(c);
            csm[b][nn] = c;
            hout[b*HH + nc] = h;
            g_enc[((size_t)t*BB + b)*HH + nc] = 0.5f*h;
        }
        __threadfence();
        __syncthreads();
        if (tid == 0) {
            atomicAdd(&g_bar[t], 1);
            while (atomicAdd(&g_bar[t], 0) < ENCB) { }
        }
        __syncthreads();
    }
}

// ------------------------- decoder input staging -----------------------------
__global__ void decih_kernel(const float* __restrict__ b_d) {
    int blk = blockIdx.x;
    int s = blk >> 10, rr = blk & 1023;
    float* dst = &g_decIh[((size_t)s*1024 + rr)*G4];
    int tid = threadIdx.x;
    if (rr >= 1008) {
        for (int i = 0; i < 4; i++) dst[tid*4 + i] = 0.f;
        return;
    }
    int j = (rr >> 3) + 1, b = rr & 7;
    const float* src;
    if (s == 0) src = &g_startIh[(size_t)rr*G4];
    else {
        int t = j + s - 1;
        if (t < TT) src = &g_winIh[(size_t)(t*BB + b)*G4];
        else        src = 0;
    }
    if (src) *(float4*)&dst[tid*4] = *(const float4*)&src[tid*4];
    else     *(float4*)&dst[tid*4] = *(const float4*)&b_d[tid*4];
}

// ------------------------- decoder LSTM cell ---------------------------------
__global__ void dec_cell_kernel(int s) {
    int rr = blockIdx.x;
    int n = threadIdx.x;
    const float* g = &g_gates[(size_t)rr*G4];
    float gi = g[n], gf = g[256+n], gg = g[512+n], go = g[768+n];
    float c = sigf(gf) * g_cD[rr*HH + n] + sigf(gi) * tanhf(gg);
    float h = sigf(go) * tanhf(c);
    g_cD[rr*HH + n] = c;
    g_hD[rr*HH + n] = h;
    g_hdec[((size_t)s*1008 + rr)*HH + n] = h;
}

// ------------------------- bf16 hi/lo split of E -----------------------------
__global__ void split_e_kernel(const float* __restrict__ E) {
    int v = blockIdx.x, d = threadIdx.x;
    float e = E[(size_t)v*DD + d];
    __nv_bfloat16 hi = __float2bfloat16(e);
    __nv_bfloat16 lo = __float2bfloat16(e - __bfloat162float(hi));
    size_t base = (size_t)v*KSPLIT;
    g_eSplit[base + d]       = hi;
    g_eSplit[base + 256 + d] = hi;
    g_eSplit[base + 512 + d] = lo;
}

// ------------------------- bf16 HMMA vocab GEMM + online LSE -----------------
// grid (125, 40) x 256 thr. CTA tile: 128 u-rows x 256 vocab, K=768.
// 8 warps = 2(m) x 4(n); warp tile 64x64 via m16n8k16 mma.
// Dyn smem 96KB: buf0 [A 16K | B 32K] @0, buf1 @48K. SW128-style swizzle.
__global__ __launch_bounds__(256) void lse_mma_kernel() {
    extern __shared__ char dsm[];
    __shared__ float partM[4][128];
    __shared__ float partS[4][128];
    uint32_t sbase = smem_u32(dsm);
    int tid = threadIdx.x, lane = tid & 31, wid = tid >> 5;
    int wm = wid >> 2, wn = wid & 3;          // 2 x 4 warp grid
    int v0 = blockIdx.x * 256, m0 = blockIdx.y * 128;

    const __nv_bfloat16* Abase = g_uSplit + (size_t)m0 * KSPLIT;
    const __nv_bfloat16* Bbase = g_eSplit + (size_t)v0 * KSPLIT;

    // ldmatrix address components (A: 64 rows/warp; B: 64 rows/warp of 256)
    int rowA = wm*64 + (lane & 15);
    uint32_t aBase = ((uint32_t)(rowA >> 3) << 10) + ((uint32_t)(rowA & 7) << 7);
    uint32_t aH = ((uint32_t)(lane >> 4)) << 4;
    uint32_t aM = ((uint32_t)(rowA & 7)) << 4;
    int rowB = wn*64 + (lane & 7) + ((lane & 16) >> 1);
    uint32_t bBase = ((uint32_t)(rowB >> 3) << 10) + ((uint32_t)(rowB & 7) << 7);
    uint32_t bH = ((uint32_t)((lane >> 3) & 1)) << 4;
    uint32_t bM = ((uint32_t)(lane & 7)) << 4;

    float acc[4][8][4];
    #pragma unroll
    for (int i = 0; i < 4; i++)
        #pragma unroll
        for (int j = 0; j < 8; j++)
            #pragma unroll
            for (int q = 0; q < 4; q++) acc[i][j][q] = 0.f;

    // issue chunk 0: A 1024 x16B (4/thr), B 2048 x16B (8/thr)
    {
        #pragma unroll
        for (int it = 0; it < 4; it++) {
            int idx = tid + it*256;
            int r = idx >> 3, c = idx & 7;
            CPA16(sbase + sw_off(r, c), (const char*)(Abase + (size_t)r*KSPLIT + c*8));
        }
        #pragma unroll
        for (int it = 0; it < 8; it++) {
            int idx = tid + it*256;
            int r = idx >> 3, c = idx & 7;
            CPA16(sbase + 16384u + sw_off(r, c), (const char*)(Bbase + (size_t)r*KSPLIT + c*8));
        }
        CPA_COMMIT();
    }

    for (int s = 0; s < CHUNKS; s++) {
        int buf = s & 1;
        if (s + 1 < CHUNKS) {
            int k0 = (s + 1) * 64;
            uint32_t dst = sbase + (uint32_t)((s+1)&1)*49152u;
            #pragma unroll
            for (int it = 0; it < 4; it++) {
                int idx = tid + it*256;
                int r = idx >> 3, c = idx & 7;
                CPA16(dst + sw_off(r, c), (const char*)(Abase + (size_t)r*KSPLIT + k0 + c*8));
            }
            #pragma unroll
            for (int it = 0; it < 8; it++) {
                int idx = tid + it*256;
                int r = idx >> 3, c = idx & 7;
                CPA16(dst + 16384u + sw_off(r, c), (const char*)(Bbase + (size_t)r*KSPLIT + k0 + c*8));
            }
            CPA_COMMIT();
            CPA_WAIT1();
        } else {
            CPA_WAIT0();
        }
        __syncthreads();

        uint32_t sA = sbase + (uint32_t)buf*49152u;
        uint32_t sB = sA + 16384u;
        #pragma unroll
        for (int ks = 0; ks < 4; ks++) {
            uint32_t a[4][4];
            #pragma unroll
            for (int mi = 0; mi < 4; mi++) {
                uint32_t addr = sA + aBase + (uint32_t)mi*2048u + (((uint32_t)ks*32u + aH) ^ aM);
                LDMX4(a[mi][0], a[mi][1], a[mi][2], a[mi][3], addr);
            }
            uint32_t b[8][2];
            #pragma unroll
            for (int p = 0; p < 4; p++) {
                uint32_t addr = sB + bBase + (uint32_t)p*2048u + (((uint32_t)ks*32u + bH) ^ bM);
                LDMX4(b[2*p][0], b[2*p][1], b[2*p+1][0], b[2*p+1][1], addr);
            }
            #pragma unroll
            for (int mi = 0; mi < 4; mi++)
                #pragma unroll
                for (int nt = 0; nt < 8; nt++)
                    MMA16816(acc[mi][nt], a[mi], b[nt]);
        }
        __syncthreads();
    }

    // epilogue: per-row (max, sumexp) over this CTA's 256 vocab cols
    int r4 = lane >> 2;
    #pragma unroll
    for (int mi = 0; mi < 4; mi++) {
        #pragma unroll
        for (int h = 0; h < 2; h++) {
            float mx = -LOGINF;
            #pragma unroll
            for (int nt = 0; nt < 8; nt++) {
                mx = fmaxf(mx, acc[mi][nt][h*2]);
                mx = fmaxf(mx, acc[mi][nt][h*2+1]);
            }
            float sum = 0.f;
            #pragma unroll
            for (int nt = 0; nt < 8; nt++) {
                sum += fexp(acc[mi][nt][h*2]   - mx);
                sum += fexp(acc[mi][nt][h*2+1] - mx);
            }
            #pragma unroll
            for (int off = 1; off <= 2; off <<= 1) {
                float om = __shfl_xor_sync(0xffffffff, mx, off);
                float os = __shfl_xor_sync(0xffffffff, sum, off);
                float M = fmaxf(mx, om);
                sum = sum * fexp(mx - M) + os * fexp(om - M);
                mx = M;
            }
            if ((lane & 3) == 0) {
                int mloc = wm*64 + mi*16 + h*8 + r4;
                partM[wn][mloc] = mx;
                partS[wn][mloc] = sum;
            }
        }
    }
    __syncthreads();
    if (tid < 128) {
        float M = partM[0][tid], S = partS[0][tid];
        #pragma unroll
        for (int p = 1; p < 4; p++) {
            float m2 = partM[p][tid], s2 = partS[p][tid];
            float Mn = fmaxf(M, m2);
            S = S * fexp(M - Mn) + s2 * fexp(m2 - Mn);
            M = Mn;
        }
        g_pM[(size_t)blockIdx.x*RPAD + m0 + tid] = M;
        g_pS[(size_t)blockIdx.x*RPAD + m0 + tid] = S;
    }
}

// ------------------------- merge chunk partials -> LSE -----------------------
__global__ void lse_merge_kernel() {
    int r = blockIdx.x * 4 + (threadIdx.x >> 5);
    int lane = threadIdx.x & 31;
    if (r >= NROWS) return;
    float lm[4], ls[4];
    float mx = -LOGINF;
    #pragma unroll
    for (int i = 0; i < 4; i++) {
        int c = lane + i*32;
        if (c < NCHV) { lm[i] = g_pM[(size_t)c*RPAD + r]; ls[i] = g_pS[(size_t)c*RPAD + r]; }
        else          { lm[i] = -LOGINF; ls[i] = 0.f; }
        mx = fmaxf(mx, lm[i]);
    }
    #pragma unroll
    for (int off = 16; off > 0; off >>= 1)
        mx = fmaxf(mx, __shfl_xor_sync(0xffffffff, mx, off));
    float s = 0.f;
    #pragma unroll
    for (int i = 0; i < 4; i++) s += ls[i] * expf(lm[i] - mx);
    #pragma unroll
    for (int off = 16; off > 0; off >>= 1)
        s += __shfl_xor_sync(0xffffffff, s, off);
    if (lane == 0) g_lse[r] = mx + logf(s);
}

// ------------------------- per-row tgt + EOS log-probs -----------------------
__global__ void tgt_eos_kernel(const int* __restrict__ x, const float* __restrict__ E) {
    __shared__ float red[4];
    int r = blockIdx.x;
    int s = r / 1008, rem = r % 1008;
    int j = (rem >> 3) + 1, b = rem & 7;
    int tt = j + s;
    int tok = (tt < TT) ? x[b*TT + tt] : 0;
    int tid = threadIdx.x;
    float4 uv = *(const float4*)&g_u[(size_t)r*HH + tid*4];
    float4 et = *(const float4*)&E[(size_t)tok*DD + tid*4];
    float4 ee = *(const float4*)&E[(size_t)EOS_TOK*DD + tid*4];
    float dt = uv.x*et.x + uv.y*et.y + uv.z*et.z + uv.w*et.w;
    float de = uv.x*ee.x + uv.y*ee.y + uv.z*ee.z + uv.w*ee.w;
    #pragma unroll
    for (int off = 16; off > 0; off >>= 1) {
        dt += __shfl_xor_sync(0xffffffff, dt, off);
        de += __shfl_xor_sync(0xffffffff, de, off);
    }
    if ((tid & 31) == 0) { red[(tid >> 5)*2] = dt; red[(tid >> 5)*2 + 1] = de; }
    __syncthreads();
    if (tid == 0) {
        float lse = g_lse[r];
        g_tlp[r] = red[0] + red[2] - lse;
        g_elp[r] = red[1] + red[3] - lse;
    }
}

// ------------------------- assemble logpy ------------------------------------
__device__ __forceinline__ float is_single_tok(const int* x, int t, int b) {
    if (t >= TT) return 0.f;
    int tok = x[b*TT + t];
    return (tok == 2 || tok == 3 || tok == 4) ? -LOGINF : 0.f;
}

__global__ void logpy_kernel(const int* __restrict__ x) {
    int tid = blockIdx.x * 256 + threadIdx.x;
    if (tid >= 1008) return;
    int j = (tid >> 3) + 1, b = tid & 7;
    float iss0 = is_single_tok(x, j, b);
    float csum = 0.f;
    #pragma unroll
    for (int k = 0; k < LLEN; k++) {
        int rbase = (j-1)*8 + b;
        float tl = g_tlp[k*1008 + rbase];
        float el = g_elp[(k+1)*1008 + rbase];
        float addk = (k == 0) ? 0.f : is_single_tok(x, j + k, b);
        csum += tl + addk;
        float v = csum + ((k >= 1) ? iss0 : 0.f) + el + 1.0f;
        if (k > TT - 2 - j) v = -LOGINF;
        g_logpy[((size_t)j*LLEN + k)*BB + b] = v;
    }
}

// ------------------------- segmental DP + final reduction --------------------
__global__ void dp_kernel(const int* __restrict__ lengths, float* __restrict__ out) {
    __shared__ float alpha[TT-1][BB];
    __shared__ float nll_s[BB];
    int b = threadIdx.x;
    if (b < BB) {
        float buf[LLEN];
        buf[0] = -LOGINF; buf[1] = -LOGINF; buf[2] = -LOGINF; buf[3] = 0.f;
        alpha[0][b] = 0.f;
        for (int m = 1; m <= TT-2; m++) {
            float c[LLEN];
            #pragma unroll
            for (int k = 0; k < LLEN; k++) {
                int idx = m - k;
                float d = (idx >= 1) ? g_logpy[((size_t)idx*LLEN + k)*BB + b] : -LOGINF;
                c[k] = buf[LLEN-1-k] + d;
            }
            float mx = fmaxf(fmaxf(c[0], c[1]), fmaxf(c[2], c[3]));
            float a = mx + logf(expf(c[0]-mx) + expf(c[1]-mx) + expf(c[2]-mx) + expf(c[3]-mx));
            buf[0] = buf[1]; buf[1] = buf[2]; buf[2] = buf[3]; buf[3] = a;
            alpha[m][b] = a;
        }
        nll_s[b] = -alpha[lengths[b] - 2][b];
    }
    __syncthreads();
    if (b == 0) {
        float tot = 0.f; int tl = 0;
        for (int i = 0; i < BB; i++) { tot += nll_s[i]; tl += lengths[i]; }
        out[0] = tot / (float)(tl - 2*BB);
    }
}

// ------------------------- host launch ---------------------------------------
extern "C" void kernel_launch(void* const* d_in, const int* in_sizes, int n_in,
                              void* d_out, int out_size) {
    const int*   x        = (const int*)  d_in[0];
    const int*   lengths  = (const int*)  d_in[1];
    const float* E        = (const float*)d_in[2];
    const float* W_ih_e   = (const float*)d_in[3];
    const float* W_hh_e   = (const float*)d_in[4];
    const float* b_e      = (const float*)d_in[5];
    const float* W_start  = (const float*)d_in[6];
    const float* W_ih_d   = (const float*)d_in[7];
    const float* W_hh_d   = (const float*)d_in[8];
    const float* b_d      = (const float*)d_in[9];
    const float* W_proj   = (const float*)d_in[10];
    float* out = (float*)d_out;

    float *p_emb, *p_preE, *p_enc, *p_seg, *p_startIh, *p_winIh, *p_decIh;
    float *p_hD, *p_gates, *p_hdec, *p_u;
    cudaGetSymbolAddress((void**)&p_emb, g_emb);
    cudaGetSymbolAddress((void**)&p_preE, g_preE);
    cudaGetSymbolAddress((void**)&p_enc, g_enc);
    cudaGetSymbolAddress((void**)&p_seg, g_seg);
    cudaGetSymbolAddress((void**)&p_startIh, g_startIh);
    cudaGetSymbolAddress((void**)&p_winIh, g_winIh);
    cudaGetSymbolAddress((void**)&p_decIh, g_decIh);
    cudaGetSymbolAddress((void**)&p_hD, g_hD);
    cudaGetSymbolAddress((void**)&p_gates, g_gates);
    cudaGetSymbolAddress((void**)&p_hdec, g_hdec);
    cudaGetSymbolAddress((void**)&p_u, g_u);

    cudaFuncSetAttribute(lse_mma_kernel, cudaFuncAttributeMaxDynamicSharedMemorySize, 98304);

    init_kernel<<<1024, 256>>>();
    embed_kernel<<<TT*BB, 64>>>(x, E);
    transpose_kernel<<<1024, 256>>>(W_hh_e);
    split_e_kernel<<<VV, 256>>>(E);

    gemm_kernel<<<dim3(16, 16), 256>>>(p_emb, W_ih_e, b_e, 0, p_preE, 1024, 1024, 256, 0);

    enc_all_kernel<<<ENCB, 256>>>();

    gemm_kernel<<<dim3(4, 16), 256>>>(p_enc, W_start, 0, 0, p_seg, 1024, 256, 256, 1);
    gemm_kernel<<<dim3(16, 16), 256>>>(p_seg, W_ih_d, b_d, 0, p_startIh, 1024, 1024, 256, 0);
    gemm_kernel<<<dim3(16, 16), 256>>>(p_emb, W_ih_d, b_d, 0, p_winIh, 1024, 1024, 256, 0);

    decih_kernel<<<5*1024, 256>>>(b_d);

    for (int s = 0; s < 5; s++) {
        gemm_kernel<<<dim3(16, 16), 256>>>(p_hD, W_hh_d, 0, p_decIh + (size_t)s*1024*G4,
                                           p_gates, 1024, 1024, 256, 0);
        dec_cell_kernel<<<1008, 256>>>(s);
    }

    // u = hdec @ W_proj, fused u-split epilogue (act=2, N=256)
    gemm_kernel<<<dim3(4, 80), 256>>>(p_hdec, W_proj, 0, 0, p_u, RPAD, 256, 256, 2);

    lse_mma_kernel<<<dim3(NCHV, RPAD/128), 256, 98304>>>();
    lse_merge_kernel<<<(NROWS + 3)/4, 128>>>();
    tgt_eos_kernel<<<NROWS, 64>>>(x, E);
    logpy_kernel<<<4, 256>>>(x);
    dp_kernel<<<1, 32>>>(lengths, out);
}

// round 8
// speedup vs baseline: 3.5386x; 1.0768x over previous
#include <cuda_runtime.h>
#include <cuda_fp16.h>
#include <math.h>
#include <stdint.h>

#define VV 32000
#define DD 256
#define HH 256
#define LLEN 4
#define TT 128
#define BB 8
#define G4 1024
#define NROWS 5040      // 5 steps * 126 starts * 8 batch
#define RPAD 5120       // 40 * 128
#define NCHV 125        // 32000/256 vocab chunks
#define LOGINF 1000000.0f
#define EOS_TOK 1
#define ENCB 16
#define KSPLIT 512      // fp16 2-term split K
#define CHUNKS 8        // 512/64

// ------------------------- device scratch (globals) -------------------------
__device__ float g_emb[TT*BB*DD];
__device__ float g_WhhET[G4*HH];
__device__ float g_preE[TT*BB*G4];
__device__ float g_hA[BB*HH];
__device__ float g_hB[BB*HH];
__device__ float g_enc[TT*BB*HH];
__device__ float g_seg[TT*BB*HH];
__device__ float g_startIh[TT*BB*G4];
__device__ float g_winIh[TT*BB*G4];
__device__ float g_decIh[5*1024*G4];
__device__ float g_hD[1024*HH];
__device__ float g_cD[1024*HH];
__device__ float g_gates[1024*G4];
__device__ float g_hdec[RPAD*HH];
__device__ float g_u[RPAD*HH];
__device__ __align__(16) __half g_uSplit[(size_t)RPAD*KSPLIT];   // [hi|lo]
__device__ __align__(16) __half g_eSplit[(size_t)VV*KSPLIT];     // [hi|hi]
__device__ float g_pM[(size_t)NCHV*RPAD];
__device__ float g_pS[(size_t)NCHV*RPAD];
__device__ float g_lse[RPAD];
__device__ float g_tlp[RPAD];
__device__ float g_elp[RPAD];
__device__ float g_logpy[(TT-1)*LLEN*BB];
__device__ int   g_bar[TT];

__device__ __forceinline__ float sigf(float x) { return 1.0f / (1.0f + expf(-x)); }

// FMA-pipe exp (no MUFU): magic-number rint + 2^f poly + exponent splice.
__device__ __forceinline__ float fexp(float x) {
    float t = fmaf(x, 1.442695041f, 12582912.0f);
    int   k = __float_as_int(t) - 0x4B400000;
    float kf = t - 12582912.0f;
    float f = fmaf(x, 1.442695041f, -kf);
    float p = 1.54035304e-4f;
    p = fmaf(p, f, 1.33335581e-3f);
    p = fmaf(p, f, 9.61812911e-3f);
    p = fmaf(p, f, 5.55041087e-2f);
    p = fmaf(p, f, 2.40226507e-1f);
    p = fmaf(p, f, 6.93147180e-1f);
    p = fmaf(p, f, 1.0f);
    float r = __int_as_float(__float_as_int(p) + (k << 23));
    return (x < -87.0f) ? 0.0f : r;
}

__device__ __forceinline__ uint32_t smem_u32(const void* p) {
    uint32_t a;
    asm("{ .reg .u64 t; cvta.to.shared.u64 t, %1; cvt.u32.u64 %0, t; }" : "=r"(a) : "l"(p));
    return a;
}

#define LDMX4(r0,r1,r2,r3,addr)                                               \
    asm volatile("ldmatrix.sync.aligned.m8n8.x4.shared.b16 {%0,%1,%2,%3}, [%4];" \
        : "=r"(r0), "=r"(r1), "=r"(r2), "=r"(r3) : "r"(addr))

#define MMA16816(c, a, b)                                                     \
    asm volatile("mma.sync.aligned.m16n8k16.row.col.f32.f16.f16.f32 "         \
        "{%0,%1,%2,%3}, {%4,%5,%6,%7}, {%8,%9}, {%0,%1,%2,%3};"               \
        : "+f"((c)[0]), "+f"((c)[1]), "+f"((c)[2]), "+f"((c)[3])              \
        : "r"((a)[0]), "r"((a)[1]), "r"((a)[2]), "r"((a)[3]),                 \
          "r"((b)[0]), "r"((b)[1]))

#define CPA16(dst, src)  asm volatile("cp.async.cg.shared.global [%0], [%1], 16;" :: "r"(dst), "l"(src))
#define CPA_COMMIT()     asm volatile("cp.async.commit_group;")
#define CPA_WAIT1()      asm volatile("cp.async.wait_group 1;")
#define CPA_WAIT0()      asm volatile("cp.async.wait_group 0;")

// swizzled offset within a K64 tile: row r (128B rows), 16B-chunk c
__device__ __forceinline__ uint32_t sw_off(int r, int c) {
    uint32_t off = (uint32_t)(r >> 3)*1024u + (uint32_t)(r & 7)*128u;
    return off + (((uint32_t)c*16u) ^ ((uint32_t)(r & 7)*16u));
}

// ------------------------- init --------------------------------------------
__global__ void init_kernel() {
    int i = blockIdx.x * 256 + threadIdx.x;
    if (i < 1024*HH) { g_hD[i] = 0.f; g_cD[i] = 0.f; }
    if (i < BB*HH)   { g_hA[i] = 0.f; g_hB[i] = 0.f; }
    if (i < TT)      g_bar[i] = 0;
}

// ------------------------- embedding gather ---------------------------------
__global__ void embed_kernel(const int* __restrict__ x, const float* __restrict__ E) {
    int tb = blockIdx.x;
    int t = tb >> 3, b = tb & 7;
    int tok = x[b*TT + t];
    int d = threadIdx.x * 4;
    *(float4*)&g_emb[(size_t)tb*DD + d] = *(const float4*)&E[(size_t)tok*DD + d];
}

// ------------------------- transpose W_hh_e ---------------------------------
__global__ void transpose_kernel(const float* __restrict__ W) {
    int idx = blockIdx.x * 256 + threadIdx.x;
    int n = idx >> 8, k = idx & 255;
    g_WhhET[idx] = W[(size_t)k*G4 + n];
}

// ------------------------- generic fp32 GEMM 64x64 tile ----------------------
// act: 0 none, 1 tanh, 2 = write u fp16 hi/lo splits as epilogue (N==256)
__global__ __launch_bounds__(256) void gemm_kernel(
    const float* __restrict__ A, const float* __restrict__ Bm,
    const float* __restrict__ bias, const float* __restrict__ addM,
    float* __restrict__ C, int M, int N, int K, int act)
{
    __shared__ float As[16][68];
    __shared__ float Bs[16][68];
    int n0 = blockIdx.x * 64, m0 = blockIdx.y * 64;
    int tid = threadIdx.x;
    int tx = tid & 15, ty = tid >> 4;
    float acc[4][4];
    #pragma unroll
    for (int i = 0; i < 4; i++)
        #pragma unroll
        for (int j = 0; j < 4; j++) acc[i][j] = 0.f;

    int arow = tid >> 2, akk = (tid & 3) << 2;
    int bkk  = tid >> 4, bnc = (tid & 15) << 2;

    for (int k0 = 0; k0 < K; k0 += 16) {
        float4 av = *(const float4*)&A[(size_t)(m0 + arow)*K + k0 + akk];
        As[akk+0][arow] = av.x; As[akk+1][arow] = av.y;
        As[akk+2][arow] = av.z; As[akk+3][arow] = av.w;
        *(float4*)&Bs[bkk][bnc] = *(const float4*)&Bm[(size_t)(k0 + bkk)*N + n0 + bnc];
        __syncthreads();
        #pragma unroll
        for (int kk = 0; kk < 16; kk++) {
            float a0 = As[kk][ty*4+0], a1 = As[kk][ty*4+1];
            float a2 = As[kk][ty*4+2], a3 = As[kk][ty*4+3];
            float4 bq = *(float4*)&Bs[kk][tx*4];
            acc[0][0] += a0*bq.x; acc[0][1] += a0*bq.y; acc[0][2] += a0*bq.z; acc[0][3] += a0*bq.w;
            acc[1][0] += a1*bq.x; acc[1][1] += a1*bq.y; acc[1][2] += a1*bq.z; acc[1][3] += a1*bq.w;
            acc[2][0] += a2*bq.x; acc[2][1] += a2*bq.y; acc[2][2] += a2*bq.z; acc[2][3] += a2*bq.w;
            acc[3][0] += a3*bq.x; acc[3][1] += a3*bq.y; acc[3][2] += a3*bq.z; acc[3][3] += a3*bq.w;
        }
        __syncthreads();
    }
    #pragma unroll
    for (int i = 0; i < 4; i++) {
        int m = m0 + ty*4 + i;
        #pragma unroll
        for (int j = 0; j < 4; j++) {
            int n = n0 + tx*4 + j;
            float v = acc[i][j];
            if (bias) v += bias[n];
            if (addM) v += addM[(size_t)m*N + n];
            if (act == 1) v = tanhf(v);
            C[(size_t)m*N + n] = v;
            if (act == 2) {
                __half hi = __float2half_rn(v);
                __half lo = __float2half_rn(v - __half2float(hi));
                size_t sb = (size_t)m*KSPLIT + n;
                g_uSplit[sb]       = hi;
                g_uSplit[sb + 256] = lo;
            }
        }
    }
}

// ------------------------- persistent encoder LSTM ---------------------------
__global__ __launch_bounds__(256) void enc_all_kernel() {
    __shared__ float hs[BB][HH];
    __shared__ float pre[4][16][BB];
    __shared__ float csm[BB][16];
    int tid = threadIdx.x;
    int gate = tid >> 6;
    int nl = (tid >> 2) & 15;
    int quarter = tid & 3;
    int n = blockIdx.x * 16 + nl;
    int gcol = gate * 256 + n;
    const float* Wcol = &g_WhhET[(size_t)gcol * 256 + quarter * 64];
    if (tid < 128) csm[tid >> 4][tid & 15] = 0.f;
    __syncthreads();

    for (int t = 0; t < TT; t++) {
        const float* hin  = (t & 1) ? g_hB : g_hA;
        float*       hout = (t & 1) ? g_hA : g_hB;
        for (int i = tid; i < BB*HH/4; i += 256) {
            float4 v = __ldcg(((const float4*)hin) + i);
            ((float4*)&hs[0][0])[i] = v;
        }
        __syncthreads();

        float acc[BB];
        #pragma unroll
        for (int b = 0; b < BB; b++) acc[b] = 0.f;
        #pragma unroll
        for (int k4 = 0; k4 < 16; k4++) {
            float4 w = *(const float4*)&Wcol[k4*4];
            int k = quarter*64 + k4*4;
            #pragma unroll
            for (int b = 0; b < BB; b++) {
                float4 hv = *(const float4*)&hs[b][k];
                acc[b] += w.x*hv.x + w.y*hv.y + w.z*hv.z + w.w*hv.w;
            }
        }
        #pragma unroll
        for (int off = 1; off <= 2; off <<= 1)
            #pragma unroll
            for (int b = 0; b < BB; b++)
                acc[b] += __shfl_xor_sync(0xffffffff, acc[b], off);
        if (quarter == 0) {
            #pragma unroll
            for (int b = 0; b < BB; b++) pre[gate][nl][b] = acc[b];
        }
        __syncthreads();

        if (tid < 128) {
            int b = tid >> 4, nn = tid & 15;
            int nc = blockIdx.x*16 + nn;
            const float* pr = &g_preE[((size_t)t*BB + b) * G4];
            float gi = pre[0][nn][b] + pr[nc];
            float gf = pre[1][nn][b] + pr[256+nc];
            float gg = pre[2][nn][b] + pr[512+nc];
            float go = pre[3][nn][b] + pr[768+nc];
            float c = sigf(gf)*csm[b][nn] + sigf(gi)*tanhf(gg);
            float h = sigf(go)*tanhf(c);
            csm[b][nn] = c;
            hout[b*HH + nc] = h;
            g_enc[((size_t)t*BB + b)*HH + nc] = 0.5f*h;
        }
        __syncthreads();                 // all writes done within CTA
        if (tid == 0) {
            int* bar = &g_bar[t];
            asm volatile("red.release.gpu.global.add.s32 [%0], 1;" :: "l"(bar) : "memory");
            int v;
            do {
                asm volatile("ld.acquire.gpu.global.s32 %0, [%1];" : "=r"(v) : "l"(bar) : "memory");
            } while (v < ENCB);
        }
        __syncthreads();
    }
}

// ------------------------- decoder input staging -----------------------------
__global__ void decih_kernel(const float* __restrict__ b_d) {
    int blk = blockIdx.x;
    int s = blk >> 10, rr = blk & 1023;
    float* dst = &g_decIh[((size_t)s*1024 + rr)*G4];
    int tid = threadIdx.x;
    if (rr >= 1008) {
        for (int i = 0; i < 4; i++) dst[tid*4 + i] = 0.f;
        return;
    }
    int j = (rr >> 3) + 1, b = rr & 7;
    const float* src;
    if (s == 0) src = &g_startIh[(size_t)rr*G4];
    else {
        int t = j + s - 1;
        if (t < TT) src = &g_winIh[(size_t)(t*BB + b)*G4];
        else        src = 0;
    }
    if (src) *(float4*)&dst[tid*4] = *(const float4*)&src[tid*4];
    else     *(float4*)&dst[tid*4] = *(const float4*)&b_d[tid*4];
}

// ------------------------- decoder LSTM cell ---------------------------------
__global__ void dec_cell_kernel(int s) {
    int rr = blockIdx.x;
    int n = threadIdx.x;
    const float* g = &g_gates[(size_t)rr*G4];
    float gi = g[n], gf = g[256+n], gg = g[512+n], go = g[768+n];
    float c = sigf(gf) * g_cD[rr*HH + n] + sigf(gi) * tanhf(gg);
    float h = sigf(go) * tanhf(c);
    g_cD[rr*HH + n] = c;
    g_hD[rr*HH + n] = h;
    g_hdec[((size_t)s*1008 + rr)*HH + n] = h;
}

// ------------------------- fp16 hi split of E (duplicated) -------------------
__global__ void split_e_kernel(const float* __restrict__ E) {
    int v = blockIdx.x, d = threadIdx.x;
    float e = E[(size_t)v*DD + d];
    __half hi = __float2half_rn(e);
    size_t base = (size_t)v*KSPLIT;
    g_eSplit[base + d]       = hi;
    g_eSplit[base + 256 + d] = hi;
}

// ------------------------- fp16 HMMA vocab GEMM + online LSE -----------------
// grid (125, 40) x 256 thr. CTA tile: 128 u-rows x 256 vocab, K=512.
// 8 warps = 2(m) x 4(n); warp tile 64x64 via m16n8k16 mma.
// Dyn smem 96KB: buf0 [A 16K | B 32K] @0, buf1 @48K. SW128-style swizzle.
__global__ __launch_bounds__(256) void lse_mma_kernel() {
    extern __shared__ char dsm[];
    __shared__ float partM[4][128];
    __shared__ float partS[4][128];
    uint32_t sbase = smem_u32(dsm);
    int tid = threadIdx.x, lane = tid & 31, wid = tid >> 5;
    int wm = wid >> 2, wn = wid & 3;          // 2 x 4 warp grid
    int v0 = blockIdx.x * 256, m0 = blockIdx.y * 128;

    const __half* Abase = g_uSplit + (size_t)m0 * KSPLIT;
    const __half* Bbase = g_eSplit + (size_t)v0 * KSPLIT;

    // ldmatrix address components (A: 64 rows/warp; B: 64 rows/warp of 256)
    int rowA = wm*64 + (lane & 15);
    uint32_t aBase = ((uint32_t)(rowA >> 3) << 10) + ((uint32_t)(rowA & 7) << 7);
    uint32_t aH = ((uint32_t)(lane >> 4)) << 4;
    uint32_t aM = ((uint32_t)(rowA & 7)) << 4;
    int rowB = wn*64 + (lane & 7) + ((lane & 16) >> 1);
    uint32_t bBase = ((uint32_t)(rowB >> 3) << 10) + ((uint32_t)(rowB & 7) << 7);
    uint32_t bH = ((uint32_t)((lane >> 3) & 1)) << 4;
    uint32_t bM = ((uint32_t)(lane & 7)) << 4;

    float acc[4][8][4];
    #pragma unroll
    for (int i = 0; i < 4; i++)
        #pragma unroll
        for (int j = 0; j < 8; j++)
            #pragma unroll
            for (int q = 0; q < 4; q++) acc[i][j][q] = 0.f;

    // issue chunk 0: A 1024 x16B (4/thr), B 2048 x16B (8/thr)
    {
        #pragma unroll
        for (int it = 0; it < 4; it++) {
            int idx = tid + it*256;
            int r = idx >> 3, c = idx & 7;
            CPA16(sbase + sw_off(r, c), (const char*)(Abase + (size_t)r*KSPLIT + c*8));
        }
        #pragma unroll
        for (int it = 0; it < 8; it++) {
            int idx = tid + it*256;
            int r = idx >> 3, c = idx & 7;
            CPA16(sbase + 16384u + sw_off(r, c), (const char*)(Bbase + (size_t)r*KSPLIT + c*8));
        }
        CPA_COMMIT();
    }

    for (int s = 0; s < CHUNKS; s++) {
        int buf = s & 1;
        if (s + 1 < CHUNKS) {
            int k0 = (s + 1) * 64;
            uint32_t dst = sbase + (uint32_t)((s+1)&1)*49152u;
            #pragma unroll
            for (int it = 0; it < 4; it++) {
                int idx = tid + it*256;
                int r = idx >> 3, c = idx & 7;
                CPA16(dst + sw_off(r, c), (const char*)(Abase + (size_t)r*KSPLIT + k0 + c*8));
            }
            #pragma unroll
            for (int it = 0; it < 8; it++) {
                int idx = tid + it*256;
                int r = idx >> 3, c = idx & 7;
                CPA16(dst + 16384u + sw_off(r, c), (const char*)(Bbase + (size_t)r*KSPLIT + k0 + c*8));
            }
            CPA_COMMIT();
            CPA_WAIT1();
        } else {
            CPA_WAIT0();
        }
        __syncthreads();

        uint32_t sA = sbase + (uint32_t)buf*49152u;
        uint32_t sB = sA + 16384u;
        #pragma unroll
        for (int ks = 0; ks < 4; ks++) {
            uint32_t a[4][4];
            #pragma unroll
            for (int mi = 0; mi < 4; mi++) {
                uint32_t addr = sA + aBase + (uint32_t)mi*2048u + (((uint32_t)ks*32u + aH) ^ aM);
                LDMX4(a[mi][0], a[mi][1], a[mi][2], a[mi][3], addr);
            }
            uint32_t b[8][2];
            #pragma unroll
            for (int p = 0; p < 4; p++) {
                uint32_t addr = sB + bBase + (uint32_t)p*2048u + (((uint32_t)ks*32u + bH) ^ bM);
                LDMX4(b[2*p][0], b[2*p][1], b[2*p+1][0], b[2*p+1][1], addr);
            }
            #pragma unroll
            for (int mi = 0; mi < 4; mi++)
                #pragma unroll
                for (int nt = 0; nt < 8; nt++)
                    MMA16816(acc[mi][nt], a[mi], b[nt]);
        }
        __syncthreads();
    }

    // epilogue: per-row (max, sumexp) over this CTA's 256 vocab cols
    int r4 = lane >> 2;
    #pragma unroll
    for (int mi = 0; mi < 4; mi++) {
        #pragma unroll
        for (int h = 0; h < 2; h++) {
            float mx = -LOGINF;
            #pragma unroll
            for (int nt = 0; nt < 8; nt++) {
                mx = fmaxf(mx, acc[mi][nt][h*2]);
                mx = fmaxf(mx, acc[mi][nt][h*2+1]);
            }
            float sum = 0.f;
            #pragma unroll
            for (int nt = 0; nt < 8; nt++) {
                sum += fexp(acc[mi][nt][h*2]   - mx);
                sum += fexp(acc[mi][nt][h*2+1] - mx);
            }
            #pragma unroll
            for (int off = 1; off <= 2; off <<= 1) {
                float om = __shfl_xor_sync(0xffffffff, mx, off);
                float os = __shfl_xor_sync(0xffffffff, sum, off);
                float M = fmaxf(mx, om);
                sum = sum * fexp(mx - M) + os * fexp(om - M);
                mx = M;
            }
            if ((lane & 3) == 0) {
                int mloc = wm*64 + mi*16 + h*8 + r4;
                partM[wn][mloc] = mx;
                partS[wn][mloc] = sum;
            }
        }
    }
    __syncthreads();
    if (tid < 128) {
        float M = partM[0][tid], S = partS[0][tid];
        #pragma unroll
        for (int p = 1; p < 4; p++) {
            float m2 = partM[p][tid], s2 = partS[p][tid];
            float Mn = fmaxf(M, m2);
            S = S * fexp(M - Mn) + s2 * fexp(m2 - Mn);
            M = Mn;
        }
        g_pM[(size_t)blockIdx.x*RPAD + m0 + tid] = M;
        g_pS[(size_t)blockIdx.x*RPAD + m0 + tid] = S;
    }
}

// ------------------------- merge chunk partials -> LSE -----------------------
__global__ void lse_merge_kernel() {
    int r = blockIdx.x * 4 + (threadIdx.x >> 5);
    int lane = threadIdx.x & 31;
    if (r >= NROWS) return;
    float lm[4], ls[4];
    float mx = -LOGINF;
    #pragma unroll
    for (int i = 0; i < 4; i++) {
        int c = lane + i*32;
        if (c < NCHV) { lm[i] = g_pM[(size_t)c*RPAD + r]; ls[i] = g_pS[(size_t)c*RPAD + r]; }
        else          { lm[i] = -LOGINF; ls[i] = 0.f; }
        mx = fmaxf(mx, lm[i]);
    }
    #pragma unroll
    for (int off = 16; off > 0; off >>= 1)
        mx = fmaxf(mx, __shfl_xor_sync(0xffffffff, mx, off));
    float s = 0.f;
    #pragma unroll
    for (int i = 0; i < 4; i++) s += ls[i] * expf(lm[i] - mx);
    #pragma unroll
    for (int off = 16; off > 0; off >>= 1)
        s += __shfl_xor_sync(0xffffffff, s, off);
    if (lane == 0) g_lse[r] = mx + logf(s);
}

// ------------------------- per-row tgt + EOS log-probs -----------------------
__global__ void tgt_eos_kernel(const int* __restrict__ x, const float* __restrict__ E) {
    __shared__ float red[4];
    int r = blockIdx.x;
    int s = r / 1008, rem = r % 1008;
    int j = (rem >> 3) + 1, b = rem & 7;
    int tt = j + s;
    int tok = (tt < TT) ? x[b*TT + tt] : 0;
    int tid = threadIdx.x;
    float4 uv = *(const float4*)&g_u[(size_t)r*HH + tid*4];
    float4 et = *(const float4*)&E[(size_t)tok*DD + tid*4];
    float4 ee = *(const float4*)&E[(size_t)EOS_TOK*DD + tid*4];
    float dt = uv.x*et.x + uv.y*et.y + uv.z*et.z + uv.w*et.w;
    float de = uv.x*ee.x + uv.y*ee.y + uv.z*ee.z + uv.w*ee.w;
    #pragma unroll
    for (int off = 16; off > 0; off >>= 1) {
        dt += __shfl_xor_sync(0xffffffff, dt, off);
        de += __shfl_xor_sync(0xffffffff, de, off);
    }
    if ((tid & 31) == 0) { red[(tid >> 5)*2] = dt; red[(tid >> 5)*2 + 1] = de; }
    __syncthreads();
    if (tid == 0) {
        float lse = g_lse[r];
        g_tlp[r] = red[0] + red[2] - lse;
        g_elp[r] = red[1] + red[3] - lse;
    }
}

// ------------------------- assemble logpy ------------------------------------
__device__ __forceinline__ float is_single_tok(const int* x, int t, int b) {
    if (t >= TT) return 0.f;
    int tok = x[b*TT + t];
    return (tok == 2 || tok == 3 || tok == 4) ? -LOGINF : 0.f;
}

__global__ void logpy_kernel(const int* __restrict__ x) {
    int tid = blockIdx.x * 256 + threadIdx.x;
    if (tid >= 1008) return;
    int j = (tid >> 3) + 1, b = tid & 7;
    float iss0 = is_single_tok(x, j, b);
    float csum = 0.f;
    #pragma unroll
    for (int k = 0; k < LLEN; k++) {
        int rbase = (j-1)*8 + b;
        float tl = g_tlp[k*1008 + rbase];
        float el = g_elp[(k+1)*1008 + rbase];
        float addk = (k == 0) ? 0.f : is_single_tok(x, j + k, b);
        csum += tl + addk;
        float v = csum + ((k >= 1) ? iss0 : 0.f) + el + 1.0f;
        if (k > TT - 2 - j) v = -LOGINF;
        g_logpy[((size_t)j*LLEN + k)*BB + b] = v;
    }
}

// ------------------------- segmental DP + final reduction --------------------
__global__ void dp_kernel(const int* __restrict__ lengths, float* __restrict__ out) {
    __shared__ float alpha[TT-1][BB];
    __shared__ float nll_s[BB];
    int b = threadIdx.x;
    if (b < BB) {
        float buf[LLEN];
        buf[0] = -LOGINF; buf[1] = -LOGINF; buf[2] = -LOGINF; buf[3] = 0.f;
        alpha[0][b] = 0.f;
        for (int m = 1; m <= TT-2; m++) {
            float c[LLEN];
            #pragma unroll
            for (int k = 0; k < LLEN; k++) {
                int idx = m - k;
                float d = (idx >= 1) ? g_logpy[((size_t)idx*LLEN + k)*BB + b] : -LOGINF;
                c[k] = buf[LLEN-1-k] + d;
            }
            float mx = fmaxf(fmaxf(c[0], c[1]), fmaxf(c[2], c[3]));
            float a = mx + logf(expf(c[0]-mx) + expf(c[1]-mx) + expf(c[2]-mx) + expf(c[3]-mx));
            buf[0] = buf[1]; buf[1] = buf[2]; buf[2] = buf[3]; buf[3] = a;
            alpha[m][b] = a;
        }
        nll_s[b] = -alpha[lengths[b] - 2][b];
    }
    __syncthreads();
    if (b == 0) {
        float tot = 0.f; int tl = 0;
        for (int i = 0; i < BB; i++) { tot += nll_s[i]; tl += lengths[i]; }
        out[0] = tot / (float)(tl - 2*BB);
    }
}

// ------------------------- host launch ---------------------------------------
extern "C" void kernel_launch(void* const* d_in, const int* in_sizes, int n_in,
                              void* d_out, int out_size) {
    const int*   x        = (const int*)  d_in[0];
    const int*   lengths  = (const int*)  d_in[1];
    const float* E        = (const float*)d_in[2];
    const float* W_ih_e   = (const float*)d_in[3];
    const float* W_hh_e   = (const float*)d_in[4];
    const float* b_e      = (const float*)d_in[5];
    const float* W_start  = (const float*)d_in[6];
    const float* W_ih_d   = (const float*)d_in[7];
    const float* W_hh_d   = (const float*)d_in[8];
    const float* b_d      = (const float*)d_in[9];
    const float* W_proj   = (const float*)d_in[10];
    float* out = (float*)d_out;

    float *p_emb, *p_preE, *p_enc, *p_seg, *p_startIh, *p_winIh, *p_decIh;
    float *p_hD, *p_gates, *p_hdec, *p_u;
    cudaGetSymbolAddress((void**)&p_emb, g_emb);
    cudaGetSymbolAddress((void**)&p_preE, g_preE);
    cudaGetSymbolAddress((void**)&p_enc, g_enc);
    cudaGetSymbolAddress((void**)&p_seg, g_seg);
    cudaGetSymbolAddress((void**)&p_startIh, g_startIh);
    cudaGetSymbolAddress((void**)&p_winIh, g_winIh);
    cudaGetSymbolAddress((void**)&p_decIh, g_decIh);
    cudaGetSymbolAddress((void**)&p_hD, g_hD);
    cudaGetSymbolAddress((void**)&p_gates, g_gates);
    cudaGetSymbolAddress((void**)&p_hdec, g_hdec);
    cudaGetSymbolAddress((void**)&p_u, g_u);

    cudaFuncSetAttribute(lse_mma_kernel, cudaFuncAttributeMaxDynamicSharedMemorySize, 98304);

    init_kernel<<<1024, 256>>>();
    embed_kernel<<<TT*BB, 64>>>(x, E);
    transpose_kernel<<<1024, 256>>>(W_hh_e);
    split_e_kernel<<<VV, 256>>>(E);

    gemm_kernel<<<dim3(16, 16), 256>>>(p_emb, W_ih_e, b_e, 0, p_preE, 1024, 1024, 256, 0);

    enc_all_kernel<<<ENCB, 256>>>();

    gemm_kernel<<<dim3(4, 16), 256>>>(p_enc, W_start, 0, 0, p_seg, 1024, 256, 256, 1);
    gemm_kernel<<<dim3(16, 16), 256>>>(p_seg, W_ih_d, b_d, 0, p_startIh, 1024, 1024, 256, 0);
    gemm_kernel<<<dim3(16, 16), 256>>>(p_emb, W_ih_d, b_d, 0, p_winIh, 1024, 1024, 256, 0);

    decih_kernel<<<5*1024, 256>>>(b_d);

    for (int s = 0; s < 5; s++) {
        gemm_kernel<<<dim3(16, 16), 256>>>(p_hD, W_hh_d, 0, p_decIh + (size_t)s*1024*G4,
                                           p_gates, 1024, 1024, 256, 0);
        dec_cell_kernel<<<1008, 256>>>(s);
    }

    // u = hdec @ W_proj, fused fp16 u-split epilogue (act=2, N=256)
    gemm_kernel<<<dim3(4, 80), 256>>>(p_hdec, W_proj, 0, 0, p_u, RPAD, 256, 256, 2);

    lse_mma_kernel<<<dim3(NCHV, RPAD/128), 256, 98304>>>();
    lse_merge_kernel<<<(NROWS + 3)/4, 128>>>();
    tgt_eos_kernel<<<NROWS, 64>>>(x, E);
    logpy_kernel<<<4, 256>>>(x);
    dp_kernel<<<1, 32>>>(lengths, out);
}

// round 9
// speedup vs baseline: 3.8556x; 1.0896x over previous
#include <cuda_runtime.h>
#include <cuda_fp16.h>
#include <math.h>
#include <stdint.h>

#define VV 32000
#define DD 256
#define HH 256
#define LLEN 4
#define TT 128
#define BB 8
#define G4 1024
#define NROWS 5040      // 5 steps * 126 starts * 8 batch
#define RPAD 5120       // 40 * 128
#define NCHV 125        // 32000/256 vocab chunks
#define LOGINF 1000000.0f
#define EOS_TOK 1
#define ENCB 16
#define KSPLIT 256      // single-term fp16 K
#define CHUNKS 4        // 256/64

// ------------------------- device scratch (globals) -------------------------
__device__ float g_emb[TT*BB*DD];
__device__ float g_WhhET[G4*HH];
__device__ float g_preE[TT*BB*G4];
__device__ float g_hA[BB*HH];
__device__ float g_hB[BB*HH];
__device__ float g_enc[TT*BB*HH];
__device__ float g_seg[TT*BB*HH];
__device__ float g_startIh[TT*BB*G4];
__device__ float g_winIh[TT*BB*G4];
__device__ float g_decIh[5*1024*G4];
__device__ float g_hD[1024*HH];
__device__ float g_cD[1024*HH];
__device__ float g_gates[1024*G4];
__device__ float g_hdec[RPAD*HH];
__device__ float g_u[RPAD*HH];
__device__ __align__(16) __half g_uH[(size_t)RPAD*KSPLIT];
__device__ __align__(16) __half g_eH[(size_t)VV*KSPLIT];
__device__ float g_pM[(size_t)NCHV*RPAD];
__device__ float g_pS[(size_t)NCHV*RPAD];
__device__ float g_lse[RPAD];
__device__ float g_tlp[RPAD];
__device__ float g_elp[RPAD];
__device__ float g_logpy[(TT-1)*LLEN*BB];
__device__ int   g_bar[TT];

__device__ __forceinline__ float sigf(float x) { return 1.0f / (1.0f + expf(-x)); }

// FMA-pipe exp (no MUFU): magic-number rint + 2^f poly + exponent splice.
__device__ __forceinline__ float fexp(float x) {
    float t = fmaf(x, 1.442695041f, 12582912.0f);
    int   k = __float_as_int(t) - 0x4B400000;
    float kf = t - 12582912.0f;
    float f = fmaf(x, 1.442695041f, -kf);
    float p = 1.54035304e-4f;
    p = fmaf(p, f, 1.33335581e-3f);
    p = fmaf(p, f, 9.61812911e-3f);
    p = fmaf(p, f, 5.55041087e-2f);
    p = fmaf(p, f, 2.40226507e-1f);
    p = fmaf(p, f, 6.93147180e-1f);
    p = fmaf(p, f, 1.0f);
    float r = __int_as_float(__float_as_int(p) + (k << 23));
    return (x < -87.0f) ? 0.0f : r;
}

__device__ __forceinline__ uint32_t smem_u32(const void* p) {
    uint32_t a;
    asm("{ .reg .u64 t; cvta.to.shared.u64 t, %1; cvt.u32.u64 %0, t; }" : "=r"(a) : "l"(p));
    return a;
}

#define LDMX4(r0,r1,r2,r3,addr)                                               \
    asm volatile("ldmatrix.sync.aligned.m8n8.x4.shared.b16 {%0,%1,%2,%3}, [%4];" \
        : "=r"(r0), "=r"(r1), "=r"(r2), "=r"(r3) : "r"(addr))

#define MMA16816(c, a, b)                                                     \
    asm volatile("mma.sync.aligned.m16n8k16.row.col.f32.f16.f16.f32 "         \
        "{%0,%1,%2,%3}, {%4,%5,%6,%7}, {%8,%9}, {%0,%1,%2,%3};"               \
        : "+f"((c)[0]), "+f"((c)[1]), "+f"((c)[2]), "+f"((c)[3])              \
        : "r"((a)[0]), "r"((a)[1]), "r"((a)[2]), "r"((a)[3]),                 \
          "r"((b)[0]), "r"((b)[1]))

#define CPA16(dst, src)  asm volatile("cp.async.cg.shared.global [%0], [%1], 16;" :: "r"(dst), "l"(src))
#define CPA_COMMIT()     asm volatile("cp.async.commit_group;")
#define CPA_WAIT1()      asm volatile("cp.async.wait_group 1;")
#define CPA_WAIT0()      asm volatile("cp.async.wait_group 0;")

// swizzled offset within a K64 tile: row r (128B rows), 16B-chunk c
__device__ __forceinline__ uint32_t sw_off(int r, int c) {
    uint32_t off = (uint32_t)(r >> 3)*1024u + (uint32_t)(r & 7)*128u;
    return off + (((uint32_t)c*16u) ^ ((uint32_t)(r & 7)*16u));
}

// ------------------------- init + W_hh_e transpose ---------------------------
__global__ void init_kernel(const float* __restrict__ W) {
    int i = blockIdx.x * 256 + threadIdx.x;       // grid 1024 -> 262144
    if (i < 1024*HH) { g_hD[i] = 0.f; g_cD[i] = 0.f; }
    if (i < BB*HH)   { g_hA[i] = 0.f; g_hB[i] = 0.f; }
    if (i < TT)      g_bar[i] = 0;
    int n = i >> 8, k = i & 255;
    g_WhhET[i] = W[(size_t)k*G4 + n];
}

// ------------------------- embedding gather ---------------------------------
__global__ void embed_kernel(const int* __restrict__ x, const float* __restrict__ E) {
    int tb = blockIdx.x;
    int t = tb >> 3, b = tb & 7;
    int tok = x[b*TT + t];
    int d = threadIdx.x * 4;
    *(float4*)&g_emb[(size_t)tb*DD + d] = *(const float4*)&E[(size_t)tok*DD + d];
}

// ------------------------- generic fp32 GEMM 64x64 tile ----------------------
// act: 0 none, 1 tanh, 2 = also write fp16 u (N==256)
__global__ __launch_bounds__(256) void gemm_kernel(
    const float* __restrict__ A, const float* __restrict__ Bm,
    const float* __restrict__ bias, const float* __restrict__ addM,
    float* __restrict__ C, int M, int N, int K, int act)
{
    __shared__ float As[16][68];
    __shared__ float Bs[16][68];
    int n0 = blockIdx.x * 64, m0 = blockIdx.y * 64;
    int tid = threadIdx.x;
    int tx = tid & 15, ty = tid >> 4;
    float acc[4][4];
    #pragma unroll
    for (int i = 0; i < 4; i++)
        #pragma unroll
        for (int j = 0; j < 4; j++) acc[i][j] = 0.f;

    int arow = tid >> 2, akk = (tid & 3) << 2;
    int bkk  = tid >> 4, bnc = (tid & 15) << 2;

    for (int k0 = 0; k0 < K; k0 += 16) {
        float4 av = *(const float4*)&A[(size_t)(m0 + arow)*K + k0 + akk];
        As[akk+0][arow] = av.x; As[akk+1][arow] = av.y;
        As[akk+2][arow] = av.z; As[akk+3][arow] = av.w;
        *(float4*)&Bs[bkk][bnc] = *(const float4*)&Bm[(size_t)(k0 + bkk)*N + n0 + bnc];
        __syncthreads();
        #pragma unroll
        for (int kk = 0; kk < 16; kk++) {
            float a0 = As[kk][ty*4+0], a1 = As[kk][ty*4+1];
            float a2 = As[kk][ty*4+2], a3 = As[kk][ty*4+3];
            float4 bq = *(float4*)&Bs[kk][tx*4];
            acc[0][0] += a0*bq.x; acc[0][1] += a0*bq.y; acc[0][2] += a0*bq.z; acc[0][3] += a0*bq.w;
            acc[1][0] += a1*bq.x; acc[1][1] += a1*bq.y; acc[1][2] += a1*bq.z; acc[1][3] += a1*bq.w;
            acc[2][0] += a2*bq.x; acc[2][1] += a2*bq.y; acc[2][2] += a2*bq.z; acc[2][3] += a2*bq.w;
            acc[3][0] += a3*bq.x; acc[3][1] += a3*bq.y; acc[3][2] += a3*bq.z; acc[3][3] += a3*bq.w;
        }
        __syncthreads();
    }
    #pragma unroll
    for (int i = 0; i < 4; i++) {
        int m = m0 + ty*4 + i;
        #pragma unroll
        for (int j = 0; j < 4; j++) {
            int n = n0 + tx*4 + j;
            float v = acc[i][j];
            if (bias) v += bias[n];
            if (addM) v += addM[(size_t)m*N + n];
            if (act == 1) v = tanhf(v);
            C[(size_t)m*N + n] = v;
            if (act == 2) g_uH[(size_t)m*KSPLIT + n] = __float2half_rn(v);
        }
    }
}

// ------------------------- persistent encoder LSTM ---------------------------
__global__ __launch_bounds__(256) void enc_all_kernel() {
    __shared__ float hs[BB][HH];
    __shared__ float pre[4][16][BB];
    __shared__ float csm[BB][16];
    int tid = threadIdx.x;
    int gate = tid >> 6;
    int nl = (tid >> 2) & 15;
    int quarter = tid & 3;
    int n = blockIdx.x * 16 + nl;
    int gcol = gate * 256 + n;
    const float* Wcol = &g_WhhET[(size_t)gcol * 256 + quarter * 64];
    if (tid < 128) csm[tid >> 4][tid & 15] = 0.f;
    __syncthreads();

    for (int t = 0; t < TT; t++) {
        const float* hin  = (t & 1) ? g_hB : g_hA;
        float*       hout = (t & 1) ? g_hA : g_hB;
        for (int i = tid; i < BB*HH/4; i += 256) {
            float4 v = __ldcg(((const float4*)hin) + i);
            ((float4*)&hs[0][0])[i] = v;
        }
        __syncthreads();

        float acc[BB];
        #pragma unroll
        for (int b = 0; b < BB; b++) acc[b] = 0.f;
        #pragma unroll
        for (int k4 = 0; k4 < 16; k4++) {
            float4 w = *(const float4*)&Wcol[k4*4];
            int k = quarter*64 + k4*4;
            #pragma unroll
            for (int b = 0; b < BB; b++) {
                float4 hv = *(const float4*)&hs[b][k];
                acc[b] += w.x*hv.x + w.y*hv.y + w.z*hv.z + w.w*hv.w;
            }
        }
        #pragma unroll
        for (int off = 1; off <= 2; off <<= 1)
            #pragma unroll
            for (int b = 0; b < BB; b++)
                acc[b] += __shfl_xor_sync(0xffffffff, acc[b], off);
        if (quarter == 0) {
            #pragma unroll
            for (int b = 0; b < BB; b++) pre[gate][nl][b] = acc[b];
        }
        __syncthreads();

        if (tid < 128) {
            int b = tid >> 4, nn = tid & 15;
            int nc = blockIdx.x*16 + nn;
            const float* pr = &g_preE[((size_t)t*BB + b) * G4];
            float gi = pre[0][nn][b] + pr[nc];
            float gf = pre[1][nn][b] + pr[256+nc];
            float gg = pre[2][nn][b] + pr[512+nc];
            float go = pre[3][nn][b] + pr[768+nc];
            float c = sigf(gf)*csm[b][nn] + sigf(gi)*tanhf(gg);
            float h = sigf(go)*tanhf(c);
            csm[b][nn] = c;
            hout[b*HH + nc] = h;
            g_enc[((size_t)t*BB + b)*HH + nc] = 0.5f*h;
        }
        __syncthreads();
        if (tid == 0) {
            int* bar = &g_bar[t];
            asm volatile("red.release.gpu.global.add.s32 [%0], 1;" :: "l"(bar) : "memory");
            int v;
            do {
                asm volatile("ld.acquire.gpu.global.s32 %0, [%1];" : "=r"(v) : "l"(bar) : "memory");
            } while (v < ENCB);
        }
        __syncthreads();
    }
}

// ------------------------- decoder input staging -----------------------------
__global__ void decih_kernel(const float* __restrict__ b_d) {
    int blk = blockIdx.x;
    int s = blk >> 10, rr = blk & 1023;
    float* dst = &g_decIh[((size_t)s*1024 + rr)*G4];
    int tid = threadIdx.x;
    if (rr >= 1008) {
        for (int i = 0; i < 4; i++) dst[tid*4 + i] = 0.f;
        return;
    }
    int j = (rr >> 3) + 1, b = rr & 7;
    const float* src;
    if (s == 0) src = &g_startIh[(size_t)rr*G4];
    else {
        int t = j + s - 1;
        if (t < TT) src = &g_winIh[(size_t)(t*BB + b)*G4];
        else        src = 0;
    }
    if (src) *(float4*)&dst[tid*4] = *(const float4*)&src[tid*4];
    else     *(float4*)&dst[tid*4] = *(const float4*)&b_d[tid*4];
}

// ------------------------- decoder LSTM cell ---------------------------------
__global__ void dec_cell_kernel(int s) {
    int rr = blockIdx.x;
    int n = threadIdx.x;
    const float* g = &g_gates[(size_t)rr*G4];
    float gi = g[n], gf = g[256+n], gg = g[512+n], go = g[768+n];
    float c = sigf(gf) * g_cD[rr*HH + n] + sigf(gi) * tanhf(gg);
    float h = sigf(go) * tanhf(c);
    g_cD[rr*HH + n] = c;
    g_hD[rr*HH + n] = h;
    g_hdec[((size_t)s*1008 + rr)*HH + n] = h;
}

// ------------------------- fp16 cast of E (vectorized) -----------------------
__global__ void cast_e_kernel(const float* __restrict__ E) {
    int i = blockIdx.x * 256 + threadIdx.x;       // grid 8000 -> 2.048M float2
    float2 e2 = *(const float2*)&E[(size_t)i*4];
    float2 e2b = *(const float2*)&E[(size_t)i*4 + 2];
    __half2 h0 = __floats2half2_rn(e2.x, e2.y);
    __half2 h1 = __floats2half2_rn(e2b.x, e2b.y);
    *(__half2*)&g_eH[(size_t)i*4]     = h0;
    *(__half2*)&g_eH[(size_t)i*4 + 2] = h1;
}

// ------------------------- fp16 HMMA vocab GEMM + online LSE -----------------
// grid (125, 40) x 256 thr. CTA tile: 128 u-rows x 256 vocab, K=256.
// 8 warps = 2(m) x 4(n); warp tile 64x64 via m16n8k16 mma.
// Dyn smem 96KB: buf0 [A 16K | B 32K] @0, buf1 @48K. SW128-style swizzle.
__global__ __launch_bounds__(256) void lse_mma_kernel() {
    extern __shared__ char dsm[];
    __shared__ float partM[4][128];
    __shared__ float partS[4][128];
    uint32_t sbase = smem_u32(dsm);
    int tid = threadIdx.x, lane = tid & 31, wid = tid >> 5;
    int wm = wid >> 2, wn = wid & 3;          // 2 x 4 warp grid
    int v0 = blockIdx.x * 256, m0 = blockIdx.y * 128;

    const __half* Abase = g_uH + (size_t)m0 * KSPLIT;
    const __half* Bbase = g_eH + (size_t)v0 * KSPLIT;

    // ldmatrix address components (A: 64 rows/warp; B: 64 rows/warp of 256)
    int rowA = wm*64 + (lane & 15);
    uint32_t aBase = ((uint32_t)(rowA >> 3) << 10) + ((uint32_t)(rowA & 7) << 7);
    uint32_t aH = ((uint32_t)(lane >> 4)) << 4;
    uint32_t aM = ((uint32_t)(rowA & 7)) << 4;
    int rowB = wn*64 + (lane & 7) + ((lane & 16) >> 1);
    uint32_t bBase = ((uint32_t)(rowB >> 3) << 10) + ((uint32_t)(rowB & 7) << 7);
    uint32_t bH = ((uint32_t)((lane >> 3) & 1)) << 4;
    uint32_t bM = ((uint32_t)(lane & 7)) << 4;

    float acc[4][8][4];
    #pragma unroll
    for (int i = 0; i < 4; i++)
        #pragma unroll
        for (int j = 0; j < 8; j++)
            #pragma unroll
            for (int q = 0; q < 4; q++) acc[i][j][q] = 0.f;

    // issue chunk 0: A 1024 x16B (4/thr), B 2048 x16B (8/thr)
    {
        #pragma unroll
        for (int it = 0; it < 4; it++) {
            int idx = tid + it*256;
            int r = idx >> 3, c = idx & 7;
            CPA16(sbase + sw_off(r, c), (const char*)(Abase + (size_t)r*KSPLIT + c*8));
        }
        #pragma unroll
        for (int it = 0; it < 8; it++) {
            int idx = tid + it*256;
            int r = idx >> 3, c = idx & 7;
            CPA16(sbase + 16384u + sw_off(r, c), (const char*)(Bbase + (size_t)r*KSPLIT + c*8));
        }
        CPA_COMMIT();
    }

    for (int s = 0; s < CHUNKS; s++) {
        int buf = s & 1;
        if (s + 1 < CHUNKS) {
            int k0 = (s + 1) * 64;
            uint32_t dst = sbase + (uint32_t)((s+1)&1)*49152u;
            #pragma unroll
            for (int it = 0; it < 4; it++) {
                int idx = tid + it*256;
                int r = idx >> 3, c = idx & 7;
                CPA16(dst + sw_off(r, c), (const char*)(Abase + (size_t)r*KSPLIT + k0 + c*8));
            }
            #pragma unroll
            for (int it = 0; it < 8; it++) {
                int idx = tid + it*256;
                int r = idx >> 3, c = idx & 7;
                CPA16(dst + 16384u + sw_off(r, c), (const char*)(Bbase + (size_t)r*KSPLIT + k0 + c*8));
            }
            CPA_COMMIT();
            CPA_WAIT1();
        } else {
            CPA_WAIT0();
        }
        __syncthreads();

        uint32_t sA = sbase + (uint32_t)buf*49152u;
        uint32_t sB = sA + 16384u;
        #pragma unroll
        for (int ks = 0; ks < 4; ks++) {
            uint32_t a[4][4];
            #pragma unroll
            for (int mi = 0; mi < 4; mi++) {
                uint32_t addr = sA + aBase + (uint32_t)mi*2048u + (((uint32_t)ks*32u + aH) ^ aM);
                LDMX4(a[mi][0], a[mi][1], a[mi][2], a[mi][3], addr);
            }
            uint32_t b[8][2];
            #pragma unroll
            for (int p = 0; p < 4; p++) {
                uint32_t addr = sB + bBase + (uint32_t)p*2048u + (((uint32_t)ks*32u + bH) ^ bM);
                LDMX4(b[2*p][0], b[2*p][1], b[2*p+1][0], b[2*p+1][1], addr);
            }
            #pragma unroll
            for (int mi = 0; mi < 4; mi++)
                #pragma unroll
                for (int nt = 0; nt < 8; nt++)
                    MMA16816(acc[mi][nt], a[mi], b[nt]);
        }
        __syncthreads();
    }

    // epilogue: per-row (max, sumexp) over this CTA's 256 vocab cols
    int r4 = lane >> 2;
    #pragma unroll
    for (int mi = 0; mi < 4; mi++) {
        #pragma unroll
        for (int h = 0; h < 2; h++) {
            float mx = -LOGINF;
            #pragma unroll
            for (int nt = 0; nt < 8; nt++) {
                mx = fmaxf(mx, acc[mi][nt][h*2]);
                mx = fmaxf(mx, acc[mi][nt][h*2+1]);
            }
            float sum = 0.f;
            #pragma unroll
            for (int nt = 0; nt < 8; nt++) {
                sum += fexp(acc[mi][nt][h*2]   - mx);
                sum += fexp(acc[mi][nt][h*2+1] - mx);
            }
            #pragma unroll
            for (int off = 1; off <= 2; off <<= 1) {
                float om = __shfl_xor_sync(0xffffffff, mx, off);
                float os = __shfl_xor_sync(0xffffffff, sum, off);
                float M = fmaxf(mx, om);
                sum = sum * fexp(mx - M) + os * fexp(om - M);
                mx = M;
            }
            if ((lane & 3) == 0) {
                int mloc = wm*64 + mi*16 + h*8 + r4;
                partM[wn][mloc] = mx;
                partS[wn][mloc] = sum;
            }
        }
    }
    __syncthreads();
    if (tid < 128) {
        float M = partM[0][tid], S = partS[0][tid];
        #pragma unroll
        for (int p = 1; p < 4; p++) {
            float m2 = partM[p][tid], s2 = partS[p][tid];
            float Mn = fmaxf(M, m2);
            S = S * fexp(M - Mn) + s2 * fexp(m2 - Mn);
            M = Mn;
        }
        g_pM[(size_t)blockIdx.x*RPAD + m0 + tid] = M;
        g_pS[(size_t)blockIdx.x*RPAD + m0 + tid] = S;
    }
}

// ------------------------- merge chunk partials -> LSE -----------------------
__global__ void lse_merge_kernel() {
    int r = blockIdx.x * 4 + (threadIdx.x >> 5);
    int lane = threadIdx.x & 31;
    if (r >= NROWS) return;
    float lm[4], ls[4];
    float mx = -LOGINF;
    #pragma unroll
    for (int i = 0; i < 4; i++) {
        int c = lane + i*32;
        if (c < NCHV) { lm[i] = g_pM[(size_t)c*RPAD + r]; ls[i] = g_pS[(size_t)c*RPAD + r]; }
        else          { lm[i] = -LOGINF; ls[i] = 0.f; }
        mx = fmaxf(mx, lm[i]);
    }
    #pragma unroll
    for (int off = 16; off > 0; off >>= 1)
        mx = fmaxf(mx, __shfl_xor_sync(0xffffffff, mx, off));
    float s = 0.f;
    #pragma unroll
    for (int i = 0; i < 4; i++) s += ls[i] * expf(lm[i] - mx);
    #pragma unroll
    for (int off = 16; off > 0; off >>= 1)
        s += __shfl_xor_sync(0xffffffff, s, off);
    if (lane == 0) g_lse[r] = mx + logf(s);
}

// ------------------------- per-row tgt + EOS log-probs -----------------------
__global__ void tgt_eos_kernel(const int* __restrict__ x, const float* __restrict__ E) {
    __shared__ float red[4];
    int r = blockIdx.x;
    int s = r / 1008, rem = r % 1008;
    int j = (rem >> 3) + 1, b = rem & 7;
    int tt = j + s;
    int tok = (tt < TT) ? x[b*TT + tt] : 0;
    int tid = threadIdx.x;
    float4 uv = *(const float4*)&g_u[(size_t)r*HH + tid*4];
    float4 et = *(const float4*)&E[(size_t)tok*DD + tid*4];
    float4 ee = *(const float4*)&E[(size_t)EOS_TOK*DD + tid*4];
    float dt = uv.x*et.x + uv.y*et.y + uv.z*et.z + uv.w*et.w;
    float de = uv.x*ee.x + uv.y*ee.y + uv.z*ee.z + uv.w*ee.w;
    #pragma unroll
    for (int off = 16; off > 0; off >>= 1) {
        dt += __shfl_xor_sync(0xffffffff, dt, off);
        de += __shfl_xor_sync(0xffffffff, de, off);
    }
    if ((tid & 31) == 0) { red[(tid >> 5)*2] = dt; red[(tid >> 5)*2 + 1] = de; }
    __syncthreads();
    if (tid == 0) {
        float lse = g_lse[r];
        g_tlp[r] = red[0] + red[2] - lse;
        g_elp[r] = red[1] + red[3] - lse;
    }
}

// ------------------------- assemble logpy ------------------------------------
__device__ __forceinline__ float is_single_tok(const int* x, int t, int b) {
    if (t >= TT) return 0.f;
    int tok = x[b*TT + t];
    return (tok == 2 || tok == 3 || tok == 4) ? -LOGINF : 0.f;
}

__global__ void logpy_kernel(const int* __restrict__ x) {
    int tid = blockIdx.x * 256 + threadIdx.x;
    if (tid >= 1008) return;
    int j = (tid >> 3) + 1, b = tid & 7;
    float iss0 = is_single_tok(x, j, b);
    float csum = 0.f;
    #pragma unroll
    for (int k = 0; k < LLEN; k++) {
        int rbase = (j-1)*8 + b;
        float tl = g_tlp[k*1008 + rbase];
        float el = g_elp[(k+1)*1008 + rbase];
        float addk = (k == 0) ? 0.f : is_single_tok(x, j + k, b);
        csum += tl + addk;
        float v = csum + ((k >= 1) ? iss0 : 0.f) + el + 1.0f;
        if (k > TT - 2 - j) v = -LOGINF;
        g_logpy[((size_t)j*LLEN + k)*BB + b] = v;
    }
}

// ------------------------- segmental DP + final reduction --------------------
__global__ void dp_kernel(const int* __restrict__ lengths, float* __restrict__ out) {
    __shared__ float alpha[TT-1][BB];
    __shared__ float nll_s[BB];
    int b = threadIdx.x;
    if (b < BB) {
        float buf[LLEN];
        buf[0] = -LOGINF; buf[1] = -LOGINF; buf[2] = -LOGINF; buf[3] = 0.f;
        alpha[0][b] = 0.f;
        for (int m = 1; m <= TT-2; m++) {
            float c[LLEN];
            #pragma unroll
            for (int k = 0; k < LLEN; k++) {
                int idx = m - k;
                float d = (idx >= 1) ? g_logpy[((size_t)idx*LLEN + k)*BB + b] : -LOGINF;
                c[k] = buf[LLEN-1-k] + d;
            }
            float mx = fmaxf(fmaxf(c[0], c[1]), fmaxf(c[2], c[3]));
            float a = mx + logf(expf(c[0]-mx) + expf(c[1]-mx) + expf(c[2]-mx) + expf(c[3]-mx));
            buf[0] = buf[1]; buf[1] = buf[2]; buf[2] = buf[3]; buf[3] = a;
            alpha[m][b] = a;
        }
        nll_s[b] = -alpha[lengths[b] - 2][b];
    }
    __syncthreads();
    if (b == 0) {
        float tot = 0.f; int tl = 0;
        for (int i = 0; i < BB; i++) { tot += nll_s[i]; tl += lengths[i]; }
        out[0] = tot / (float)(tl - 2*BB);
    }
}

// ------------------------- host launch ---------------------------------------
extern "C" void kernel_launch(void* const* d_in, const int* in_sizes, int n_in,
                              void* d_out, int out_size) {
    const int*   x        = (const int*)  d_in[0];
    const int*   lengths  = (const int*)  d_in[1];
    const float* E        = (const float*)d_in[2];
    const float* W_ih_e   = (const float*)d_in[3];
    const float* W_hh_e   = (const float*)d_in[4];
    const float* b_e      = (const float*)d_in[5];
    const float* W_start  = (const float*)d_in[6];
    const float* W_ih_d   = (const float*)d_in[7];
    const float* W_hh_d   = (const float*)d_in[8];
    const float* b_d      = (const float*)d_in[9];
    const float* W_proj   = (const float*)d_in[10];
    float* out = (float*)d_out;

    float *p_emb, *p_preE, *p_enc, *p_seg, *p_startIh, *p_winIh, *p_decIh;
    float *p_hD, *p_gates, *p_hdec, *p_u;
    cudaGetSymbolAddress((void**)&p_emb, g_emb);
    cudaGetSymbolAddress((void**)&p_preE, g_preE);
    cudaGetSymbolAddress((void**)&p_enc, g_enc);
    cudaGetSymbolAddress((void**)&p_seg, g_seg);
    cudaGetSymbolAddress((void**)&p_startIh, g_startIh);
    cudaGetSymbolAddress((void**)&p_winIh, g_winIh);
    cudaGetSymbolAddress((void**)&p_decIh, g_decIh);
    cudaGetSymbolAddress((void**)&p_hD, g_hD);
    cudaGetSymbolAddress((void**)&p_gates, g_gates);
    cudaGetSymbolAddress((void**)&p_hdec, g_hdec);
    cudaGetSymbolAddress((void**)&p_u, g_u);

    cudaFuncSetAttribute(lse_mma_kernel, cudaFuncAttributeMaxDynamicSharedMemorySize, 98304);

    // launch order chosen so the 4th launch (ncu sample slot) is enc_all
    init_kernel<<<1024, 256>>>(W_hh_e);                                   // 1
    embed_kernel<<<TT*BB, 64>>>(x, E);                                    // 2
    gemm_kernel<<<dim3(16, 16), 256>>>(p_emb, W_ih_e, b_e, 0, p_preE,
                                       1024, 1024, 256, 0);               // 3
    enc_all_kernel<<<ENCB, 256>>>();                                      // 4  <- ncu

    cast_e_kernel<<<8000, 256>>>(E);
    gemm_kernel<<<dim3(4, 16), 256>>>(p_enc, W_start, 0, 0, p_seg, 1024, 256, 256, 1);
    gemm_kernel<<<dim3(16, 16), 256>>>(p_seg, W_ih_d, b_d, 0, p_startIh, 1024, 1024, 256, 0);
    gemm_kernel<<<dim3(16, 16), 256>>>(p_emb, W_ih_d, b_d, 0, p_winIh, 1024, 1024, 256, 0);

    decih_kernel<<<5*1024, 256>>>(b_d);

    for (int s = 0; s < 5; s++) {
        gemm_kernel<<<dim3(16, 16), 256>>>(p_hD, W_hh_d, 0, p_decIh + (size_t)s*1024*G4,
                                           p_gates, 1024, 1024, 256, 0);
        dec_cell_kernel<<<1008, 256>>>(s);
    }

    // u = hdec @ W_proj, fused fp16 u cast (act=2, N=256)
    gemm_kernel<<<dim3(4, 80), 256>>>(p_hdec, W_proj, 0, 0, p_u, RPAD, 256, 256, 2);

    lse_mma_kernel<<<dim3(NCHV, RPAD/128), 256, 98304>>>();
    lse_merge_kernel<<<(NROWS + 3)/4, 128>>>();
    tgt_eos_kernel<<<NROWS, 64>>>(x, E);
    logpy_kernel<<<4, 256>>>(x);
    dp_kernel<<<1, 32>>>(lengths, out);
}

// round 11
// speedup vs baseline: 5.3290x; 1.3821x over previous
#include <cuda_runtime.h>
#include <cuda_fp16.h>
#include <math.h>
#include <stdint.h>

#define VV 32000
#define DD 256
#define HH 256
#define LLEN 4
#define TT 128
#define BB 8
#define G4 1024
#define NROWS 5040      // 5 steps * 126 starts * 8 batch
#define RPAD 5120       // 40 * 128
#define NCHV 125        // 32000/256 vocab chunks
#define LOGINF 1000000.0f
#define EOS_TOK 1
#define KSPLIT 256      // single-term fp16 K
#define CHUNKS 4        // 256/64

// ------------------------- device scratch (globals) -------------------------
__device__ float g_emb[TT*BB*DD];
__device__ float g_preE[TT*BB*G4];
__device__ float g_enc[TT*BB*HH];
__device__ float g_seg[TT*BB*HH];
__device__ float g_startIh[TT*BB*G4];
__device__ float g_winIh[TT*BB*G4];
__device__ float g_decIh[5*1024*G4];
__device__ float g_hD[1024*HH];
__device__ float g_cD[1024*HH];
__device__ float g_gates[1024*G4];
__device__ float g_hdec[RPAD*HH];
__device__ float g_u[RPAD*HH];
__device__ __align__(16) __half g_uH[(size_t)RPAD*KSPLIT];
__device__ __align__(16) __half g_eH[(size_t)VV*KSPLIT];
__device__ float g_pM[(size_t)NCHV*RPAD];
__device__ float g_pS[(size_t)NCHV*RPAD];
__device__ float g_lse[RPAD];
__device__ float g_tlp[RPAD];
__device__ float g_elp[RPAD];
__device__ float g_logpy[(TT-1)*LLEN*BB];

__device__ __forceinline__ float sigf(float x) { return 1.0f / (1.0f + expf(-x)); }

// FMA-pipe exp (no MUFU): magic-number rint + 2^f poly + exponent splice.
__device__ __forceinline__ float fexp(float x) {
    float t = fmaf(x, 1.442695041f, 12582912.0f);
    int   k = __float_as_int(t) - 0x4B400000;
    float kf = t - 12582912.0f;
    float f = fmaf(x, 1.442695041f, -kf);
    float p = 1.54035304e-4f;
    p = fmaf(p, f, 1.33335581e-3f);
    p = fmaf(p, f, 9.61812911e-3f);
    p = fmaf(p, f, 5.55041087e-2f);
    p = fmaf(p, f, 2.40226507e-1f);
    p = fmaf(p, f, 6.93147180e-1f);
    p = fmaf(p, f, 1.0f);
    float r = __int_as_float(__float_as_int(p) + (k << 23));
    return (x < -87.0f) ? 0.0f : r;
}

__device__ __forceinline__ uint32_t smem_u32(const void* p) {
    uint32_t a;
    asm("{ .reg .u64 t; cvta.to.shared.u64 t, %1; cvt.u32.u64 %0, t; }" : "=r"(a) : "l"(p));
    return a;
}

#define LDMX4(r0,r1,r2,r3,addr)                                               \
    asm volatile("ldmatrix.sync.aligned.m8n8.x4.shared.b16 {%0,%1,%2,%3}, [%4];" \
        : "=r"(r0), "=r"(r1), "=r"(r2), "=r"(r3) : "r"(addr))

#define MMA16816(c, a, b)                                                     \
    asm volatile("mma.sync.aligned.m16n8k16.row.col.f32.f16.f16.f32 "         \
        "{%0,%1,%2,%3}, {%4,%5,%6,%7}, {%8,%9}, {%0,%1,%2,%3};"               \
        : "+f"((c)[0]), "+f"((c)[1]), "+f"((c)[2]), "+f"((c)[3])              \
        : "r"((a)[0]), "r"((a)[1]), "r"((a)[2]), "r"((a)[3]),                 \
          "r"((b)[0]), "r"((b)[1]))

#define CPA16(dst, src)  asm volatile("cp.async.cg.shared.global [%0], [%1], 16;" :: "r"(dst), "l"(src))
#define CPA_COMMIT()     asm volatile("cp.async.commit_group;")
#define CPA_WAIT1()      asm volatile("cp.async.wait_group 1;")
#define CPA_WAIT0()      asm volatile("cp.async.wait_group 0;")

// swizzled offset within a K64 tile: row r (128B rows), 16B-chunk c
__device__ __forceinline__ uint32_t sw_off(int r, int c) {
    uint32_t off = (uint32_t)(r >> 3)*1024u + (uint32_t)(r & 7)*128u;
    return off + (((uint32_t)c*16u) ^ ((uint32_t)(r & 7)*16u));
}

// ------------------------- init: zero decoder state --------------------------
__global__ void init_kernel() {
    int i = blockIdx.x * 256 + threadIdx.x;   // grid 1024 -> 262144 = 1024*HH
    g_hD[i] = 0.f;
    g_cD[i] = 0.f;
}

// ------------------------- embedding gather ---------------------------------
__global__ void embed_kernel(const int* __restrict__ x, const float* __restrict__ E) {
    int tb = blockIdx.x;
    int t = tb >> 3, b = tb & 7;
    int tok = x[b*TT + t];
    int d = threadIdx.x * 4;
    *(float4*)&g_emb[(size_t)tb*DD + d] = *(const float4*)&E[(size_t)tok*DD + d];
}

// ------------------------- generic fp32 GEMM 64x64 tile ----------------------
// act: 0 none, 1 tanh, 2 = also write fp16 u (N==256)
__global__ __launch_bounds__(256) void gemm_kernel(
    const float* __restrict__ A, const float* __restrict__ Bm,
    const float* __restrict__ bias, const float* __restrict__ addM,
    float* __restrict__ C, int M, int N, int K, int act)
{
    __shared__ float As[16][68];
    __shared__ float Bs[16][68];
    int n0 = blockIdx.x * 64, m0 = blockIdx.y * 64;
    int tid = threadIdx.x;
    int tx = tid & 15, ty = tid >> 4;
    float acc[4][4];
    #pragma unroll
    for (int i = 0; i < 4; i++)
        #pragma unroll
        for (int j = 0; j < 4; j++) acc[i][j] = 0.f;

    int arow = tid >> 2, akk = (tid & 3) << 2;
    int bkk  = tid >> 4, bnc = (tid & 15) << 2;

    for (int k0 = 0; k0 < K; k0 += 16) {
        float4 av = *(const float4*)&A[(size_t)(m0 + arow)*K + k0 + akk];
        As[akk+0][arow] = av.x; As[akk+1][arow] = av.y;
        As[akk+2][arow] = av.z; As[akk+3][arow] = av.w;
        *(float4*)&Bs[bkk][bnc] = *(const float4*)&Bm[(size_t)(k0 + bkk)*N + n0 + bnc];
        __syncthreads();
        #pragma unroll
        for (int kk = 0; kk < 16; kk++) {
            float a0 = As[kk][ty*4+0], a1 = As[kk][ty*4+1];
            float a2 = As[kk][ty*4+2], a3 = As[kk][ty*4+3];
            float4 bq = *(float4*)&Bs[kk][tx*4];
            acc[0][0] += a0*bq.x; acc[0][1] += a0*bq.y; acc[0][2] += a0*bq.z; acc[0][3] += a0*bq.w;
            acc[1][0] += a1*bq.x; acc[1][1] += a1*bq.y; acc[1][2] += a1*bq.z; acc[1][3] += a1*bq.w;
            acc[2][0] += a2*bq.x; acc[2][1] += a2*bq.y; acc[2][2] += a2*bq.z; acc[2][3] += a2*bq.w;
            acc[3][0] += a3*bq.x; acc[3][1] += a3*bq.y; acc[3][2] += a3*bq.z; acc[3][3] += a3*bq.w;
        }
        __syncthreads();
    }
    #pragma unroll
    for (int i = 0; i < 4; i++) {
        int m = m0 + ty*4 + i;
        #pragma unroll
        for (int j = 0; j < 4; j++) {
            int n = n0 + tx*4 + j;
            float v = acc[i][j];
            if (bias) v += bias[n];
            if (addM) v += addM[(size_t)m*N + n];
            if (act == 1) v = tanhf(v);
            C[(size_t)m*N + n] = v;
            if (act == 2) g_uH[(size_t)m*KSPLIT + n] = __float2half_rn(v);
        }
    }
}

// ------------------------- batch-parallel encoder LSTM -----------------------
// 8 blocks (one per batch) x 1024 threads. Zero inter-block communication:
// h (256) and c (256) live in this block's smem. Thread tid owns gate-column
// tid; computes full 256-dot against W_hh in ORIGINAL k-major layout
// (lane-consecutive coalesced loads). Two __syncthreads per step.
__global__ __launch_bounds__(1024) void enc_all_kernel(const float* __restrict__ Whh) {
    __shared__ float hsm[HH];
    __shared__ float csm[HH];
    __shared__ float garr[G4];
    int tid = threadIdx.x;
    int b = blockIdx.x;
    if (tid < HH) { hsm[tid] = 0.f; csm[tid] = 0.f; }
    __syncthreads();

    for (int t = 0; t < TT; t++) {
        float acc = 0.f;
        #pragma unroll 4
        for (int k = 0; k < HH; k += 4) {
            float4 hv = *(float4*)&hsm[k];
            acc += Whh[(size_t)(k+0)*G4 + tid] * hv.x;
            acc += Whh[(size_t)(k+1)*G4 + tid] * hv.y;
            acc += Whh[(size_t)(k+2)*G4 + tid] * hv.z;
            acc += Whh[(size_t)(k+3)*G4 + tid] * hv.w;
        }
        garr[tid] = acc;
        __syncthreads();               // garr complete; all h reads done

        if (tid < HH) {
            const float* pr = &g_preE[((size_t)t*BB + b)*G4];
            float gi = garr[tid]        + pr[tid];
            float gf = garr[256 + tid]  + pr[256 + tid];
            float gg = garr[512 + tid]  + pr[512 + tid];
            float go = garr[768 + tid]  + pr[768 + tid];
            float c = sigf(gf)*csm[tid] + sigf(gi)*tanhf(gg);
            float h = sigf(go)*tanhf(c);
            csm[tid] = c;
            hsm[tid] = h;
            g_enc[((size_t)t*BB + b)*HH + tid] = 0.5f*h;
        }
        __syncthreads();               // h updated before next dot
    }
}

// ------------------------- decoder input staging -----------------------------
__global__ void decih_kernel(const float* __restrict__ b_d) {
    int blk = blockIdx.x;
    int s = blk >> 10, rr = blk & 1023;
    float* dst = &g_decIh[((size_t)s*1024 + rr)*G4];
    int tid = threadIdx.x;
    if (rr >= 1008) {
        for (int i = 0; i < 4; i++) dst[tid*4 + i] = 0.f;
        return;
    }
    int j = (rr >> 3) + 1, b = rr & 7;
    const float* src;
    if (s == 0) src = &g_startIh[(size_t)rr*G4];
    else {
        int t = j + s - 1;
        if (t < TT) src = &g_winIh[(size_t)(t*BB + b)*G4];
        else        src = 0;
    }
    if (src) *(float4*)&dst[tid*4] = *(const float4*)&src[tid*4];
    else     *(float4*)&dst[tid*4] = *(const float4*)&b_d[tid*4];
}

// ------------------------- decoder LSTM cell ---------------------------------
__global__ void dec_cell_kernel(int s) {
    int rr = blockIdx.x;
    int n = threadIdx.x;
    const float* g = &g_gates[(size_t)rr*G4];
    float gi = g[n], gf = g[256+n], gg = g[512+n], go = g[768+n];
    float c = sigf(gf) * g_cD[rr*HH + n] + sigf(gi) * tanhf(gg);
    float h = sigf(go) * tanhf(c);
    g_cD[rr*HH + n] = c;
    g_hD[rr*HH + n] = h;
    g_hdec[((size_t)s*1008 + rr)*HH + n] = h;
}

// ------------------------- fp16 cast of E (vectorized) -----------------------
__global__ void cast_e_kernel(const float* __restrict__ E) {
    int i = blockIdx.x * 256 + threadIdx.x;       // grid 8000
    float2 e2 = *(const float2*)&E[(size_t)i*4];
    float2 e2b = *(const float2*)&E[(size_t)i*4 + 2];
    __half2 h0 = __floats2half2_rn(e2.x, e2.y);
    __half2 h1 = __floats2half2_rn(e2b.x, e2b.y);
    *(__half2*)&g_eH[(size_t)i*4]     = h0;
    *(__half2*)&g_eH[(size_t)i*4 + 2] = h1;
}

// ------------------------- fp16 HMMA vocab GEMM + online LSE -----------------
// grid (125, 40) x 256 thr. CTA tile: 128 u-rows x 256 vocab, K=256.
// 8 warps = 2(m) x 4(n); warp tile 64x64 via m16n8k16 mma.
// Dyn smem 96KB: buf0 [A 16K | B 32K] @0, buf1 @48K. SW128-style swizzle.
__global__ __launch_bounds__(256) void lse_mma_kernel() {
    extern __shared__ char dsm[];
    __shared__ float partM[4][128];
    __shared__ float partS[4][128];
    uint32_t sbase = smem_u32(dsm);
    int tid = threadIdx.x, lane = tid & 31, wid = tid >> 5;
    int wm = wid >> 2, wn = wid & 3;          // 2 x 4 warp grid
    int v0 = blockIdx.x * 256, m0 = blockIdx.y * 128;

    const __half* Abase = g_uH + (size_t)m0 * KSPLIT;
    const __half* Bbase = g_eH + (size_t)v0 * KSPLIT;

    int rowA = wm*64 + (lane & 15);
    uint32_t aBase = ((uint32_t)(rowA >> 3) << 10) + ((uint32_t)(rowA & 7) << 7);
    uint32_t aH = ((uint32_t)(lane >> 4)) << 4;
    uint32_t aM = ((uint32_t)(rowA & 7)) << 4;
    int rowB = wn*64 + (lane & 7) + ((lane & 16) >> 1);
    uint32_t bBase = ((uint32_t)(rowB >> 3) << 10) + ((uint32_t)(rowB & 7) << 7);
    uint32_t bH = ((uint32_t)((lane >> 3) & 1)) << 4;
    uint32_t bM = ((uint32_t)(lane & 7)) << 4;

    float acc[4][8][4];
    #pragma unroll
    for (int i = 0; i < 4; i++)
        #pragma unroll
        for (int j = 0; j < 8; j++)
            #pragma unroll
            for (int q = 0; q < 4; q++) acc[i][j][q] = 0.f;

    {
        #pragma unroll
        for (int it = 0; it < 4; it++) {
            int idx = tid + it*256;
            int r = idx >> 3, c = idx & 7;
            CPA16(sbase + sw_off(r, c), (const char*)(Abase + (size_t)r*KSPLIT + c*8));
        }
        #pragma unroll
        for (int it = 0; it < 8; it++) {
            int idx = tid + it*256;
            int r = idx >> 3, c = idx & 7;
            CPA16(sbase + 16384u + sw_off(r, c), (const char*)(Bbase + (size_t)r*KSPLIT + c*8));
        }
        CPA_COMMIT();
    }

    for (int s = 0; s < CHUNKS; s++) {
        int buf = s & 1;
        if (s + 1 < CHUNKS) {
            int k0 = (s + 1) * 64;
            uint32_t dst = sbase + (uint32_t)((s+1)&1)*49152u;
            #pragma unroll
            for (int it = 0; it < 4; it++) {
                int idx = tid + it*256;
                int r = idx >> 3, c = idx & 7;
                CPA16(dst + sw_off(r, c), (const char*)(Abase + (size_t)r*KSPLIT + k0 + c*8));
            }
            #pragma unroll
            for (int it = 0; it < 8; it++) {
                int idx = tid + it*256;
                int r = idx >> 3, c = idx & 7;
                CPA16(dst + 16384u + sw_off(r, c), (const char*)(Bbase + (size_t)r*KSPLIT + k0 + c*8));
            }
            CPA_COMMIT();
            CPA_WAIT1();
        } else {
            CPA_WAIT0();
        }
        __syncthreads();

        uint32_t sA = sbase + (uint32_t)buf*49152u;
        uint32_t sB = sA + 16384u;
        #pragma unroll
        for (int ks = 0; ks < 4; ks++) {
            uint32_t a[4][4];
            #pragma unroll
            for (int mi = 0; mi < 4; mi++) {
                uint32_t addr = sA + aBase + (uint32_t)mi*2048u + (((uint32_t)ks*32u + aH) ^ aM);
                LDMX4(a[mi][0], a[mi][1], a[mi][2], a[mi][3], addr);
            }
            uint32_t b[8][2];
            #pragma unroll
            for (int p = 0; p < 4; p++) {
                uint32_t addr = sB + bBase + (uint32_t)p*2048u + (((uint32_t)ks*32u + bH) ^ bM);
                LDMX4(b[2*p][0], b[2*p][1], b[2*p+1][0], b[2*p+1][1], addr);
            }
            #pragma unroll
            for (int mi = 0; mi < 4; mi++)
                #pragma unroll
                for (int nt = 0; nt < 8; nt++)
                    MMA16816(acc[mi][nt], a[mi], b[nt]);
        }
        __syncthreads();
    }

    // epilogue: per-row (max, sumexp) over this CTA's 256 vocab cols
    int r4 = lane >> 2;
    #pragma unroll
    for (int mi = 0; mi < 4; mi++) {
        #pragma unroll
        for (int h = 0; h < 2; h++) {
            float mx = -LOGINF;
            #pragma unroll
            for (int nt = 0; nt < 8; nt++) {
                mx = fmaxf(mx, acc[mi][nt][h*2]);
                mx = fmaxf(mx, acc[mi][nt][h*2+1]);
            }
            float sum = 0.f;
            #pragma unroll
            for (int nt = 0; nt < 8; nt++) {
                sum += fexp(acc[mi][nt][h*2]   - mx);
                sum += fexp(acc[mi][nt][h*2+1] - mx);
            }
            #pragma unroll
            for (int off = 1; off <= 2; off <<= 1) {
                float om = __shfl_xor_sync(0xffffffff, mx, off);
                float os = __shfl_xor_sync(0xffffffff, sum, off);
                float M = fmaxf(mx, om);
                sum = sum * fexp(mx - M) + os * fexp(om - M);
                mx = M;
            }
            if ((lane & 3) == 0) {
                int mloc = wm*64 + mi*16 + h*8 + r4;
                partM[wn][mloc] = mx;
                partS[wn][mloc] = sum;
            }
        }
    }
    __syncthreads();
    if (tid < 128) {
        float M = partM[0][tid], S = partS[0][tid];
        #pragma unroll
        for (int p = 1; p < 4; p++) {
            float m2 = partM[p][tid], s2 = partS[p][tid];
            float Mn = fmaxf(M, m2);
            S = S * fexp(M - Mn) + s2 * fexp(m2 - Mn);
            M = Mn;
        }
        g_pM[(size_t)blockIdx.x*RPAD + m0 + tid] = M;
        g_pS[(size_t)blockIdx.x*RPAD + m0 + tid] = S;
    }
}

// ------------------------- merge chunk partials -> LSE -----------------------
__global__ void lse_merge_kernel() {
    int r = blockIdx.x * 4 + (threadIdx.x >> 5);
    int lane = threadIdx.x & 31;
    if (r >= NROWS) return;
    float lm[4], ls[4];
    float mx = -LOGINF;
    #pragma unroll
    for (int i = 0; i < 4; i++) {
        int c = lane + i*32;
        if (c < NCHV) { lm[i] = g_pM[(size_t)c*RPAD + r]; ls[i] = g_pS[(size_t)c*RPAD + r]; }
        else          { lm[i] = -LOGINF; ls[i] = 0.f; }
        mx = fmaxf(mx, lm[i]);
    }
    #pragma unroll
    for (int off = 16; off > 0; off >>= 1)
        mx = fmaxf(mx, __shfl_xor_sync(0xffffffff, mx, off));
    float s = 0.f;
    #pragma unroll
    for (int i = 0; i < 4; i++) s += ls[i] * expf(lm[i] - mx);
    #pragma unroll
    for (int off = 16; off > 0; off >>= 1)
        s += __shfl_xor_sync(0xffffffff, s, off);
    if (lane == 0) g_lse[r] = mx + logf(s);
}

// ------------------------- per-row tgt + EOS log-probs -----------------------
__global__ void tgt_eos_kernel(const int* __restrict__ x, const float* __restrict__ E) {
    __shared__ float red[4];
    int r = blockIdx.x;
    int s = r / 1008, rem = r % 1008;
    int j = (rem >> 3) + 1, b = rem & 7;
    int tt = j + s;
    int tok = (tt < TT) ? x[b*TT + tt] : 0;
    int tid = threadIdx.x;
    float4 uv = *(const float4*)&g_u[(size_t)r*HH + tid*4];
    float4 et = *(const float4*)&E[(size_t)tok*DD + tid*4];
    float4 ee = *(const float4*)&E[(size_t)EOS_TOK*DD + tid*4];
    float dt = uv.x*et.x + uv.y*et.y + uv.z*et.z + uv.w*et.w;
    float de = uv.x*ee.x + uv.y*ee.y + uv.z*ee.z + uv.w*ee.w;
    #pragma unroll
    for (int off = 16; off > 0; off >>= 1) {
        dt += __shfl_xor_sync(0xffffffff, dt, off);
        de += __shfl_xor_sync(0xffffffff, de, off);
    }
    if ((tid & 31) == 0) { red[(tid >> 5)*2] = dt; red[(tid >> 5)*2 + 1] = de; }
    __syncthreads();
    if (tid == 0) {
        float lse = g_lse[r];
        g_tlp[r] = red[0] + red[2] - lse;
        g_elp[r] = red[1] + red[3] - lse;
    }
}

// ------------------------- assemble logpy ------------------------------------
__device__ __forceinline__ float is_single_tok(const int* x, int t, int b) {
    if (t >= TT) return 0.f;
    int tok = x[b*TT + t];
    return (tok == 2 || tok == 3 || tok == 4) ? -LOGINF : 0.f;
}

__global__ void logpy_kernel(const int* __restrict__ x) {
    int tid = blockIdx.x * 256 + threadIdx.x;
    if (tid >= 1008) return;
    int j = (tid >> 3) + 1, b = tid & 7;
    float iss0 = is_single_tok(x, j, b);
    float csum = 0.f;
    #pragma unroll
    for (int k = 0; k < LLEN; k++) {
        int rbase = (j-1)*8 + b;
        float tl = g_tlp[k*1008 + rbase];
        float el = g_elp[(k+1)*1008 + rbase];
        float addk = (k == 0) ? 0.f : is_single_tok(x, j + k, b);
        csum += tl + addk;
        float v = csum + ((k >= 1) ? iss0 : 0.f) + el + 1.0f;
        if (k > TT - 2 - j) v = -LOGINF;
        g_logpy[((size_t)j*LLEN + k)*BB + b] = v;
    }
}

// ------------------------- segmental DP + final reduction --------------------
__global__ void dp_kernel(const int* __restrict__ lengths, float* __restrict__ out) {
    __shared__ float alpha[TT-1][BB];
    __shared__ float nll_s[BB];
    int b = threadIdx.x;
    if (b < BB) {
        float buf[LLEN];
        buf[0] = -LOGINF; buf[1] = -LOGINF; buf[2] = -LOGINF; buf[3] = 0.f;
        alpha[0][b] = 0.f;
        for (int m = 1; m <= TT-2; m++) {
            float c[LLEN];
            #pragma unroll
            for (int k = 0; k < LLEN; k++) {
                int idx = m - k;
                float d = (idx >= 1) ? g_logpy[((size_t)idx*LLEN + k)*BB + b] : -LOGINF;
                c[k] = buf[LLEN-1-k] + d;
            }
            float mx = fmaxf(fmaxf(c[0], c[1]), fmaxf(c[2], c[3]));
            float a = mx + logf(expf(c[0]-mx) + expf(c[1]-mx) + expf(c[2]-mx) + expf(c[3]-mx));
            buf[0] = buf[1]; buf[1] = buf[2]; buf[2] = buf[3]; buf[3] = a;
            alpha[m][b] = a;
        }
        nll_s[b] = -alpha[lengths[b] - 2][b];
    }
    __syncthreads();
    if (b == 0) {
        float tot = 0.f; int tl = 0;
        for (int i = 0; i < BB; i++) { tot += nll_s[i]; tl += lengths[i]; }
        out[0] = tot / (float)(tl - 2*BB);
    }
}

// ------------------------- host launch ---------------------------------------
extern "C" void kernel_launch(void* const* d_in, const int* in_sizes, int n_in,
                              void* d_out, int out_size) {
    const int*   x        = (const int*)  d_in[0];
    const int*   lengths  = (const int*)  d_in[1];
    const float* E        = (const float*)d_in[2];
    const float* W_ih_e   = (const float*)d_in[3];
    const float* W_hh_e   = (const float*)d_in[4];
    const float* b_e      = (const float*)d_in[5];
    const float* W_start  = (const float*)d_in[6];
    const float* W_ih_d   = (const float*)d_in[7];
    const float* W_hh_d   = (const float*)d_in[8];
    const float* b_d      = (const float*)d_in[9];
    const float* W_proj   = (const float*)d_in[10];
    float* out = (float*)d_out;

    float *p_emb, *p_preE, *p_enc, *p_seg, *p_startIh, *p_winIh, *p_decIh;
    float *p_hD, *p_gates, *p_hdec, *p_u;
    cudaGetSymbolAddress((void**)&p_emb, g_emb);
    cudaGetSymbolAddress((void**)&p_preE, g_preE);
    cudaGetSymbolAddress((void**)&p_enc, g_enc);
    cudaGetSymbolAddress((void**)&p_seg, g_seg);
    cudaGetSymbolAddress((void**)&p_startIh, g_startIh);
    cudaGetSymbolAddress((void**)&p_winIh, g_winIh);
    cudaGetSymbolAddress((void**)&p_decIh, g_decIh);
    cudaGetSymbolAddress((void**)&p_hD, g_hD);
    cudaGetSymbolAddress((void**)&p_gates, g_gates);
    cudaGetSymbolAddress((void**)&p_hdec, g_hdec);
    cudaGetSymbolAddress((void**)&p_u, g_u);

    cudaFuncSetAttribute(lse_mma_kernel, cudaFuncAttributeMaxDynamicSharedMemorySize, 98304);

    // launch order chosen so the 4th launch (ncu sample slot) is enc_all
    init_kernel<<<1024, 256>>>();                                         // 1
    embed_kernel<<<TT*BB, 64>>>(x, E);                                    // 2
    gemm_kernel<<<dim3(16, 16), 256>>>(p_emb, W_ih_e, b_e, 0, p_preE,
                                       1024, 1024, 256, 0);               // 3
    enc_all_kernel<<<BB, 1024>>>(W_hh_e);                                 // 4  <- ncu

    cast_e_kernel<<<8000, 256>>>(E);
    gemm_kernel<<<dim3(4, 16), 256>>>(p_enc, W_start, 0, 0, p_seg, 1024, 256, 256, 1);
    gemm_kernel<<<dim3(16, 16), 256>>>(p_seg, W_ih_d, b_d, 0, p_startIh, 1024, 1024, 256, 0);
    gemm_kernel<<<dim3(16, 16), 256>>>(p_emb, W_ih_d, b_d, 0, p_winIh, 1024, 1024, 256, 0);

    decih_kernel<<<5*1024, 256>>>(b_d);

    for (int s = 0; s < 5; s++) {
        gemm_kernel<<<dim3(16, 16), 256>>>(p_hD, W_hh_d, 0, p_decIh + (size_t)s*1024*G4,
                                           p_gates, 1024, 1024, 256, 0);
        dec_cell_kernel<<<1008, 256>>>(s);
    }

    // u = hdec @ W_proj, fused fp16 u cast (act=2, N=256)
    gemm_kernel<<<dim3(4, 80), 256>>>(p_hdec, W_proj, 0, 0, p_u, RPAD, 256, 256, 2);

    lse_mma_kernel<<<dim3(NCHV, RPAD/128), 256, 98304>>>();
    lse_merge_kernel<<<(NROWS + 3)/4, 128>>>();
    tgt_eos_kernel<<<NROWS, 64>>>(x, E);
    logpy_kernel<<<4, 256>>>(x);
    dp_kernel<<<1, 32>>>(lengths, out);
}

// round 12
// speedup vs baseline: 5.8429x; 1.0964x over previous
#include <cuda_runtime.h>
#include <cuda_fp16.h>
#include <math.h>
#include <stdint.h>

#define VV 32000
#define DD 256
#define HH 256
#define LLEN 4
#define TT 128
#define BB 8
#define G4 1024
#define NROWS 5040      // 5 steps * 126 starts * 8 batch
#define RPAD 5120       // 40 * 128
#define NCHV 125        // 32000/256 vocab chunks
#define LOGINF 1000000.0f
#define EOS_TOK 1
#define KSPLIT 256      // single-term fp16 K
#define CHUNKS 4        // 256/64

// ------------------------- device scratch (globals) -------------------------
__device__ float g_emb[TT*BB*DD];
__device__ float g_preE[TT*BB*G4];          // gate-interleaved
__device__ float g_enc[TT*BB*HH];
__device__ float g_seg[TT*BB*HH];
__device__ float g_startIh[TT*BB*G4];       // gate-interleaved
__device__ float g_winIh[TT*BB*G4];         // gate-interleaved
__device__ float g_decIh[5*1024*G4];        // gate-interleaved
__device__ float g_hD[1024*HH];
__device__ float g_cD[1024*HH];
__device__ float g_gates[4];                // dummy C target for act=3
__device__ float g_hdec[RPAD*HH];
__device__ float g_u[RPAD*HH];
__device__ __align__(16) __half g_uH[(size_t)RPAD*KSPLIT];
__device__ __align__(16) __half g_eH[(size_t)VV*KSPLIT];
__device__ float g_pM[(size_t)NCHV*RPAD];
__device__ float g_pS[(size_t)NCHV*RPAD];
__device__ float g_lse[RPAD];
__device__ float g_tlp[RPAD];
__device__ float g_elp[RPAD];
__device__ float g_logpy[(TT-1)*LLEN*BB];
// gate-interleaved weight copies
__device__ __align__(16) float g_WihEP[256*G4];
__device__ __align__(16) float g_WhhEP[256*G4];
__device__ __align__(16) float g_WihDP[256*G4];
__device__ __align__(16) float g_WhhDP[256*G4];
__device__ float g_bEP[G4];
__device__ float g_bDP[G4];

__device__ __forceinline__ float sigf(float x) { return 1.0f / (1.0f + expf(-x)); }

// FMA-pipe exp (no MUFU): magic-number rint + 2^f poly + exponent splice.
__device__ __forceinline__ float fexp(float x) {
    float t = fmaf(x, 1.442695041f, 12582912.0f);
    int   k = __float_as_int(t) - 0x4B400000;
    float kf = t - 12582912.0f;
    float f = fmaf(x, 1.442695041f, -kf);
    float p = 1.54035304e-4f;
    p = fmaf(p, f, 1.33335581e-3f);
    p = fmaf(p, f, 9.61812911e-3f);
    p = fmaf(p, f, 5.55041087e-2f);
    p = fmaf(p, f, 2.40226507e-1f);
    p = fmaf(p, f, 6.93147180e-1f);
    p = fmaf(p, f, 1.0f);
    float r = __int_as_float(__float_as_int(p) + (k << 23));
    return (x < -87.0f) ? 0.0f : r;
}

__device__ __forceinline__ uint32_t smem_u32(const void* p) {
    uint32_t a;
    asm("{ .reg .u64 t; cvta.to.shared.u64 t, %1; cvt.u32.u64 %0, t; }" : "=r"(a) : "l"(p));
    return a;
}

#define LDMX4(r0,r1,r2,r3,addr)                                               \
    asm volatile("ldmatrix.sync.aligned.m8n8.x4.shared.b16 {%0,%1,%2,%3}, [%4];" \
        : "=r"(r0), "=r"(r1), "=r"(r2), "=r"(r3) : "r"(addr))

#define MMA16816(c, a, b)                                                     \
    asm volatile("mma.sync.aligned.m16n8k16.row.col.f32.f16.f16.f32 "         \
        "{%0,%1,%2,%3}, {%4,%5,%6,%7}, {%8,%9}, {%0,%1,%2,%3};"               \
        : "+f"((c)[0]), "+f"((c)[1]), "+f"((c)[2]), "+f"((c)[3])              \
        : "r"((a)[0]), "r"((a)[1]), "r"((a)[2]), "r"((a)[3]),                 \
          "r"((b)[0]), "r"((b)[1]))

#define CPA16(dst, src)  asm volatile("cp.async.cg.shared.global [%0], [%1], 16;" :: "r"(dst), "l"(src))
#define CPA_COMMIT()     asm volatile("cp.async.commit_group;")
#define CPA_WAIT1()      asm volatile("cp.async.wait_group 1;")
#define CPA_WAIT0()      asm volatile("cp.async.wait_group 0;")

// swizzled offset within a K64 tile: row r (128B rows), 16B-chunk c
__device__ __forceinline__ uint32_t sw_off(int r, int c) {
    uint32_t off = (uint32_t)(r >> 3)*1024u + (uint32_t)(r & 7)*128u;
    return off + (((uint32_t)c*16u) ^ ((uint32_t)(r & 7)*16u));
}

// ------------------------- permute weights + init state ----------------------
// new col 4n+j = old col j*256+n (j = gate index i/f/g/o)
__global__ void perm_kernel(const float* __restrict__ Wihe, const float* __restrict__ Whhe,
                            const float* __restrict__ Wihd, const float* __restrict__ Whhd,
                            const float* __restrict__ be,   const float* __restrict__ bd) {
    int blk = blockIdx.x, tid = threadIdx.x;
    if (blk < 4096) {
        int mat = blk >> 10;
        int w = (blk & 1023) * 256 + tid;      // 0..262143
        int k = w >> 10, cn = w & 1023;
        int n = cn >> 2, j = cn & 3;
        const float* src = (mat == 0) ? Wihe : (mat == 1) ? Whhe : (mat == 2) ? Wihd : Whhd;
        float* dst = (mat == 0) ? g_WihEP : (mat == 1) ? g_WhhEP : (mat == 2) ? g_WihDP : g_WhhDP;
        dst[(size_t)k*G4 + cn] = src[(size_t)k*G4 + j*256 + n];
    } else if (blk < 4104) {
        int w = (blk - 4096) * 256 + tid;      // 0..2047
        int cn = w & 1023;
        int n = cn >> 2, j = cn & 3;
        if (w < 1024) g_bEP[cn] = be[j*256 + n];
        else          g_bDP[cn] = bd[j*256 + n];
    } else {
        int w = (blk - 4104) * 256 + tid;      // 0..524287
        if (w < 262144) g_hD[w] = 0.f;
        else            g_cD[w - 262144] = 0.f;
    }
}

// ------------------------- embedding gather ---------------------------------
__global__ void embed_kernel(const int* __restrict__ x, const float* __restrict__ E) {
    int tb = blockIdx.x;
    int t = tb >> 3, b = tb & 7;
    int tok = x[b*TT + t];
    int d = threadIdx.x * 4;
    *(float4*)&g_emb[(size_t)tb*DD + d] = *(const float4*)&E[(size_t)tok*DD + d];
}

// ------------------------- generic fp32 GEMM 64x64 tile ----------------------
// act: 0 none, 1 tanh, 2 = also write fp16 u (N==256),
//      3 = fused decoder LSTM cell (gate-interleaved, N==1024; skips C store)
__global__ __launch_bounds__(256) void gemm_kernel(
    const float* __restrict__ A, const float* __restrict__ Bm,
    const float* __restrict__ bias, const float* __restrict__ addM,
    float* __restrict__ C, int M, int N, int K, int act, int s)
{
    __shared__ float As[16][68];
    __shared__ float Bs[16][68];
    int n0 = blockIdx.x * 64, m0 = blockIdx.y * 64;
    int tid = threadIdx.x;
    int tx = tid & 15, ty = tid >> 4;
    float acc[4][4];
    #pragma unroll
    for (int i = 0; i < 4; i++)
        #pragma unroll
        for (int j = 0; j < 4; j++) acc[i][j] = 0.f;

    int arow = tid >> 2, akk = (tid & 3) << 2;
    int bkk  = tid >> 4, bnc = (tid & 15) << 2;

    for (int k0 = 0; k0 < K; k0 += 16) {
        float4 av = *(const float4*)&A[(size_t)(m0 + arow)*K + k0 + akk];
        As[akk+0][arow] = av.x; As[akk+1][arow] = av.y;
        As[akk+2][arow] = av.z; As[akk+3][arow] = av.w;
        *(float4*)&Bs[bkk][bnc] = *(const float4*)&Bm[(size_t)(k0 + bkk)*N + n0 + bnc];
        __syncthreads();
        #pragma unroll
        for (int kk = 0; kk < 16; kk++) {
            float a0 = As[kk][ty*4+0], a1 = As[kk][ty*4+1];
            float a2 = As[kk][ty*4+2], a3 = As[kk][ty*4+3];
            float4 bq = *(float4*)&Bs[kk][tx*4];
            acc[0][0] += a0*bq.x; acc[0][1] += a0*bq.y; acc[0][2] += a0*bq.z; acc[0][3] += a0*bq.w;
            acc[1][0] += a1*bq.x; acc[1][1] += a1*bq.y; acc[1][2] += a1*bq.z; acc[1][3] += a1*bq.w;
            acc[2][0] += a2*bq.x; acc[2][1] += a2*bq.y; acc[2][2] += a2*bq.z; acc[2][3] += a2*bq.w;
            acc[3][0] += a3*bq.x; acc[3][1] += a3*bq.y; acc[3][2] += a3*bq.z; acc[3][3] += a3*bq.w;
        }
        __syncthreads();
    }
    #pragma unroll
    for (int i = 0; i < 4; i++) {
        int m = m0 + ty*4 + i;
        float v[4];
        #pragma unroll
        for (int j = 0; j < 4; j++) {
            int n = n0 + tx*4 + j;
            float vv = acc[i][j];
            if (bias) vv += bias[n];
            if (addM) vv += addM[(size_t)m*N + n];
            if (act == 1) vv = tanhf(vv);
            v[j] = vv;
        }
        if (act == 3) {
            int un = (n0 >> 2) + tx;     // h-unit index (0..255)
            float c = sigf(v[1]) * g_cD[(size_t)m*HH + un] + sigf(v[0]) * tanhf(v[2]);
            float h = sigf(v[3]) * tanhf(c);
            g_cD[(size_t)m*HH + un] = c;
            g_hD[(size_t)m*HH + un] = h;
            if (m < 1008) g_hdec[((size_t)s*1008 + m)*HH + un] = h;
        } else {
            #pragma unroll
            for (int j = 0; j < 4; j++) {
                int n = n0 + tx*4 + j;
                C[(size_t)m*N + n] = v[j];
                if (act == 2) g_uH[(size_t)m*KSPLIT + n] = __float2half_rn(v[j]);
            }
        }
    }
}

// ------------------------- batch-parallel vectorized encoder -----------------
// 8 blocks (one per batch) x 1024 threads. thread (u = tid&255, kq = tid>>8):
// owns the 4 interleaved gates of unit u over k-quarter kq. 64 LDG.128/thread
// per step; float4 h broadcasts; STS.128 partial; 4-way smem reduction + cell.
__global__ __launch_bounds__(1024) void enc_all_kernel() {
    __shared__ float hsm[HH];
    __shared__ float csm[HH];
    __shared__ float4 part[4][256];     // 16KB
    int tid = threadIdx.x;
    int u = tid & 255;
    int kq = tid >> 8;
    int b = blockIdx.x;
    if (tid < HH) { hsm[tid] = 0.f; csm[tid] = 0.f; }
    __syncthreads();

    const float* Wbase = g_WhhEP + (size_t)(kq * 64) * G4 + 4 * u;
    for (int t = 0; t < TT; t++) {
        float4 acc = make_float4(0.f, 0.f, 0.f, 0.f);
        const float* W = Wbase;
        #pragma unroll 2
        for (int i4 = 0; i4 < 16; i4++) {
            float4 hk = *(const float4*)&hsm[kq*64 + i4*4];
            float4 w0 = *(const float4*)(W);
            float4 w1 = *(const float4*)(W + G4);
            float4 w2 = *(const float4*)(W + 2*G4);
            float4 w3 = *(const float4*)(W + 3*G4);
            acc.x += w0.x*hk.x + w1.x*hk.y + w2.x*hk.z + w3.x*hk.w;
            acc.y += w0.y*hk.x + w1.y*hk.y + w2.y*hk.z + w3.y*hk.w;
            acc.z += w0.z*hk.x + w1.z*hk.y + w2.z*hk.z + w3.z*hk.w;
            acc.w += w0.w*hk.x + w1.w*hk.y + w2.w*hk.z + w3.w*hk.w;
            W += 4*G4;
        }
        part[kq][u] = acc;
        __syncthreads();

        if (tid < HH) {
            float4 s0 = part[0][tid], s1 = part[1][tid];
            float4 s2 = part[2][tid], s3 = part[3][tid];
            float4 pv = *(const float4*)&g_preE[((size_t)t*BB + b)*G4 + 4*tid];
            float gi = s0.x + s1.x + s2.x + s3.x + pv.x;
            float gf = s0.y + s1.y + s2.y + s3.y + pv.y;
            float gg = s0.z + s1.z + s2.z + s3.z + pv.z;
            float go = s0.w + s1.w + s2.w + s3.w + pv.w;
            float c = sigf(gf)*csm[tid] + sigf(gi)*tanhf(gg);
            float h = sigf(go)*tanhf(c);
            csm[tid] = c;
            hsm[tid] = h;
            g_enc[((size_t)t*BB + b)*HH + tid] = 0.5f*h;
        }
        __syncthreads();
    }
}

// ------------------------- decoder input staging -----------------------------
__global__ void decih_kernel(const float* __restrict__ b_dP) {
    int blk = blockIdx.x;
    int s = blk >> 10, rr = blk & 1023;
    float* dst = &g_decIh[((size_t)s*1024 + rr)*G4];
    int tid = threadIdx.x;
    if (rr >= 1008) {
        for (int i = 0; i < 4; i++) dst[tid*4 + i] = 0.f;
        return;
    }
    int j = (rr >> 3) + 1, b = rr & 7;
    const float* src;
    if (s == 0) src = &g_startIh[(size_t)rr*G4];
    else {
        int t = j + s - 1;
        if (t < TT) src = &g_winIh[(size_t)(t*BB + b)*G4];
        else        src = 0;
    }
    if (src) *(float4*)&dst[tid*4] = *(const float4*)&src[tid*4];
    else     *(float4*)&dst[tid*4] = *(const float4*)&b_dP[tid*4];
}

// ------------------------- fp16 cast of E (vectorized) -----------------------
__global__ void cast_e_kernel(const float* __restrict__ E) {
    int i = blockIdx.x * 256 + threadIdx.x;       // grid 8000
    float2 e2 = *(const float2*)&E[(size_t)i*4];
    float2 e2b = *(const float2*)&E[(size_t)i*4 + 2];
    __half2 h0 = __floats2half2_rn(e2.x, e2.y);
    __half2 h1 = __floats2half2_rn(e2b.x, e2b.y);
    *(__half2*)&g_eH[(size_t)i*4]     = h0;
    *(__half2*)&g_eH[(size_t)i*4 + 2] = h1;
}

// ------------------------- fp16 HMMA vocab GEMM + online LSE -----------------
__global__ __launch_bounds__(256) void lse_mma_kernel() {
    extern __shared__ char dsm[];
    __shared__ float partM[4][128];
    __shared__ float partS[4][128];
    uint32_t sbase = smem_u32(dsm);
    int tid = threadIdx.x, lane = tid & 31, wid = tid >> 5;
    int wm = wid >> 2, wn = wid & 3;          // 2 x 4 warp grid
    int v0 = blockIdx.x * 256, m0 = blockIdx.y * 128;

    const __half* Abase = g_uH + (size_t)m0 * KSPLIT;
    const __half* Bbase = g_eH + (size_t)v0 * KSPLIT;

    int rowA = wm*64 + (lane & 15);
    uint32_t aBase = ((uint32_t)(rowA >> 3) << 10) + ((uint32_t)(rowA & 7) << 7);
    uint32_t aH = ((uint32_t)(lane >> 4)) << 4;
    uint32_t aM = ((uint32_t)(rowA & 7)) << 4;
    int rowB = wn*64 + (lane & 7) + ((lane & 16) >> 1);
    uint32_t bBase = ((uint32_t)(rowB >> 3) << 10) + ((uint32_t)(rowB & 7) << 7);
    uint32_t bH = ((uint32_t)((lane >> 3) & 1)) << 4;
    uint32_t bM = ((uint32_t)(lane & 7)) << 4;

    float acc[4][8][4];
    #pragma unroll
    for (int i = 0; i < 4; i++)
        #pragma unroll
        for (int j = 0; j < 8; j++)
            #pragma unroll
            for (int q = 0; q < 4; q++) acc[i][j][q] = 0.f;

    {
        #pragma unroll
        for (int it = 0; it < 4; it++) {
            int idx = tid + it*256;
            int r = idx >> 3, c = idx & 7;
            CPA16(sbase + sw_off(r, c), (const char*)(Abase + (size_t)r*KSPLIT + c*8));
        }
        #pragma unroll
        for (int it = 0; it < 8; it++) {
            int idx = tid + it*256;
            int r = idx >> 3, c = idx & 7;
            CPA16(sbase + 16384u + sw_off(r, c), (const char*)(Bbase + (size_t)r*KSPLIT + c*8));
        }
        CPA_COMMIT();
    }

    for (int s = 0; s < CHUNKS; s++) {
        int buf = s & 1;
        if (s + 1 < CHUNKS) {
            int k0 = (s + 1) * 64;
            uint32_t dst = sbase + (uint32_t)((s+1)&1)*49152u;
            #pragma unroll
            for (int it = 0; it < 4; it++) {
                int idx = tid + it*256;
                int r = idx >> 3, c = idx & 7;
                CPA16(dst + sw_off(r, c), (const char*)(Abase + (size_t)r*KSPLIT + k0 + c*8));
            }
            #pragma unroll
            for (int it = 0; it < 8; it++) {
                int idx = tid + it*256;
                int r = idx >> 3, c = idx & 7;
                CPA16(dst + 16384u + sw_off(r, c), (const char*)(Bbase + (size_t)r*KSPLIT + k0 + c*8));
            }
            CPA_COMMIT();
            CPA_WAIT1();
        } else {
            CPA_WAIT0();
        }
        __syncthreads();

        uint32_t sA = sbase + (uint32_t)buf*49152u;
        uint32_t sB = sA + 16384u;
        #pragma unroll
        for (int ks = 0; ks < 4; ks++) {
            uint32_t a[4][4];
            #pragma unroll
            for (int mi = 0; mi < 4; mi++) {
                uint32_t addr = sA + aBase + (uint32_t)mi*2048u + (((uint32_t)ks*32u + aH) ^ aM);
                LDMX4(a[mi][0], a[mi][1], a[mi][2], a[mi][3], addr);
            }
            uint32_t b[8][2];
            #pragma unroll
            for (int p = 0; p < 4; p++) {
                uint32_t addr = sB + bBase + (uint32_t)p*2048u + (((uint32_t)ks*32u + bH) ^ bM);
                LDMX4(b[2*p][0], b[2*p][1], b[2*p+1][0], b[2*p+1][1], addr);
            }
            #pragma unroll
            for (int mi = 0; mi < 4; mi++)
                #pragma unroll
                for (int nt = 0; nt < 8; nt++)
                    MMA16816(acc[mi][nt], a[mi], b[nt]);
        }
        __syncthreads();
    }

    int r4 = lane >> 2;
    #pragma unroll
    for (int mi = 0; mi < 4; mi++) {
        #pragma unroll
        for (int h = 0; h < 2; h++) {
            float mx = -LOGINF;
            #pragma unroll
            for (int nt = 0; nt < 8; nt++) {
                mx = fmaxf(mx, acc[mi][nt][h*2]);
                mx = fmaxf(mx, acc[mi][nt][h*2+1]);
            }
            float sum = 0.f;
            #pragma unroll
            for (int nt = 0; nt < 8; nt++) {
                sum += fexp(acc[mi][nt][h*2]   - mx);
                sum += fexp(acc[mi][nt][h*2+1] - mx);
            }
            #pragma unroll
            for (int off = 1; off <= 2; off <<= 1) {
                float om = __shfl_xor_sync(0xffffffff, mx, off);
                float os = __shfl_xor_sync(0xffffffff, sum, off);
                float M = fmaxf(mx, om);
                sum = sum * fexp(mx - M) + os * fexp(om - M);
                mx = M;
            }
            if ((lane & 3) == 0) {
                int mloc = wm*64 + mi*16 + h*8 + r4;
                partM[wn][mloc] = mx;
                partS[wn][mloc] = sum;
            }
        }
    }
    __syncthreads();
    if (tid < 128) {
        float M = partM[0][tid], S = partS[0][tid];
        #pragma unroll
        for (int p = 1; p < 4; p++) {
            float m2 = partM[p][tid], s2 = partS[p][tid];
            float Mn = fmaxf(M, m2);
            S = S * fexp(M - Mn) + s2 * fexp(m2 - Mn);
            M = Mn;
        }
        g_pM[(size_t)blockIdx.x*RPAD + m0 + tid] = M;
        g_pS[(size_t)blockIdx.x*RPAD + m0 + tid] = S;
    }
}

// ------------------------- merge chunk partials -> LSE -----------------------
__global__ void lse_merge_kernel() {
    int r = blockIdx.x * 4 + (threadIdx.x >> 5);
    int lane = threadIdx.x & 31;
    if (r >= NROWS) return;
    float lm[4], ls[4];
    float mx = -LOGINF;
    #pragma unroll
    for (int i = 0; i < 4; i++) {
        int c = lane + i*32;
        if (c < NCHV) { lm[i] = g_pM[(size_t)c*RPAD + r]; ls[i] = g_pS[(size_t)c*RPAD + r]; }
        else          { lm[i] = -LOGINF; ls[i] = 0.f; }
        mx = fmaxf(mx, lm[i]);
    }
    #pragma unroll
    for (int off = 16; off > 0; off >>= 1)
        mx = fmaxf(mx, __shfl_xor_sync(0xffffffff, mx, off));
    float s = 0.f;
    #pragma unroll
    for (int i = 0; i < 4; i++) s += ls[i] * expf(lm[i] - mx);
    #pragma unroll
    for (int off = 16; off > 0; off >>= 1)
        s += __shfl_xor_sync(0xffffffff, s, off);
    if (lane == 0) g_lse[r] = mx + logf(s);
}

// ------------------------- per-row tgt + EOS log-probs -----------------------
__global__ void tgt_eos_kernel(const int* __restrict__ x, const float* __restrict__ E) {
    __shared__ float red[4];
    int r = blockIdx.x;
    int s = r / 1008, rem = r % 1008;
    int j = (rem >> 3) + 1, b = rem & 7;
    int tt = j + s;
    int tok = (tt < TT) ? x[b*TT + tt] : 0;
    int tid = threadIdx.x;
    float4 uv = *(const float4*)&g_u[(size_t)r*HH + tid*4];
    float4 et = *(const float4*)&E[(size_t)tok*DD + tid*4];
    float4 ee = *(const float4*)&E[(size_t)EOS_TOK*DD + tid*4];
    float dt = uv.x*et.x + uv.y*et.y + uv.z*et.z + uv.w*et.w;
    float de = uv.x*ee.x + uv.y*ee.y + uv.z*ee.z + uv.w*ee.w;
    #pragma unroll
    for (int off = 16; off > 0; off >>= 1) {
        dt += __shfl_xor_sync(0xffffffff, dt, off);
        de += __shfl_xor_sync(0xffffffff, de, off);
    }
    if ((tid & 31) == 0) { red[(tid >> 5)*2] = dt; red[(tid >> 5)*2 + 1] = de; }
    __syncthreads();
    if (tid == 0) {
        float lse = g_lse[r];
        g_tlp[r] = red[0] + red[2] - lse;
        g_elp[r] = red[1] + red[3] - lse;
    }
}

// ------------------------- assemble logpy ------------------------------------
__device__ __forceinline__ float is_single_tok(const int* x, int t, int b) {
    if (t >= TT) return 0.f;
    int tok = x[b*TT + t];
    return (tok == 2 || tok == 3 || tok == 4) ? -LOGINF : 0.f;
}

__global__ void logpy_kernel(const int* __restrict__ x) {
    int tid = blockIdx.x * 256 + threadIdx.x;
    if (tid >= 1008) return;
    int j = (tid >> 3) + 1, b = tid & 7;
    float iss0 = is_single_tok(x, j, b);
    float csum = 0.f;
    #pragma unroll
    for (int k = 0; k < LLEN; k++) {
        int rbase = (j-1)*8 + b;
        float tl = g_tlp[k*1008 + rbase];
        float el = g_elp[(k+1)*1008 + rbase];
        float addk = (k == 0) ? 0.f : is_single_tok(x, j + k, b);
        csum += tl + addk;
        float v = csum + ((k >= 1) ? iss0 : 0.f) + el + 1.0f;
        if (k > TT - 2 - j) v = -LOGINF;
        g_logpy[((size_t)j*LLEN + k)*BB + b] = v;
    }
}

// ------------------------- segmental DP + final reduction --------------------
__global__ void dp_kernel(const int* __restrict__ lengths, float* __restrict__ out) {
    __shared__ float alpha[TT-1][BB];
    __shared__ float nll_s[BB];
    int b = threadIdx.x;
    if (b < BB) {
        float buf[LLEN];
        buf[0] = -LOGINF; buf[1] = -LOGINF; buf[2] = -LOGINF; buf[3] = 0.f;
        alpha[0][b] = 0.f;
        for (int m = 1; m <= TT-2; m++) {
            float c[LLEN];
            #pragma unroll
            for (int k = 0; k < LLEN; k++) {
                int idx = m - k;
                float d = (idx >= 1) ? g_logpy[((size_t)idx*LLEN + k)*BB + b] : -LOGINF;
                c[k] = buf[LLEN-1-k] + d;
            }
            float mx = fmaxf(fmaxf(c[0], c[1]), fmaxf(c[2], c[3]));
            float a = mx + logf(expf(c[0]-mx) + expf(c[1]-mx) + expf(c[2]-mx) + expf(c[3]-mx));
            buf[0] = buf[1]; buf[1] = buf[2]; buf[2] = buf[3]; buf[3] = a;
            alpha[m][b] = a;
        }
        nll_s[b] = -alpha[lengths[b] - 2][b];
    }
    __syncthreads();
    if (b == 0) {
        float tot = 0.f; int tl = 0;
        for (int i = 0; i < BB; i++) { tot += nll_s[i]; tl += lengths[i]; }
        out[0] = tot / (float)(tl - 2*BB);
    }
}

// ------------------------- host launch ---------------------------------------
extern "C" void kernel_launch(void* const* d_in, const int* in_sizes, int n_in,
                              void* d_out, int out_size) {
    const int*   x        = (const int*)  d_in[0];
    const int*   lengths  = (const int*)  d_in[1];
    const float* E        = (const float*)d_in[2];
    const float* W_ih_e   = (const float*)d_in[3];
    const float* W_hh_e   = (const float*)d_in[4];
    const float* b_e      = (const float*)d_in[5];
    const float* W_start  = (const float*)d_in[6];
    const float* W_ih_d   = (const float*)d_in[7];
    const float* W_hh_d   = (const float*)d_in[8];
    const float* b_d      = (const float*)d_in[9];
    const float* W_proj   = (const float*)d_in[10];
    float* out = (float*)d_out;

    float *p_emb, *p_preE, *p_enc, *p_seg, *p_startIh, *p_winIh, *p_decIh;
    float *p_hD, *p_gates, *p_hdec, *p_u;
    float *p_WihEP, *p_WihDP, *p_WhhDP, *p_bEP, *p_bDP;
    cudaGetSymbolAddress((void**)&p_emb, g_emb);
    cudaGetSymbolAddress((void**)&p_preE, g_preE);
    cudaGetSymbolAddress((void**)&p_enc, g_enc);
    cudaGetSymbolAddress((void**)&p_seg, g_seg);
    cudaGetSymbolAddress((void**)&p_startIh, g_startIh);
    cudaGetSymbolAddress((void**)&p_winIh, g_winIh);
    cudaGetSymbolAddress((void**)&p_decIh, g_decIh);
    cudaGetSymbolAddress((void**)&p_hD, g_hD);
    cudaGetSymbolAddress((void**)&p_gates, g_gates);
    cudaGetSymbolAddress((void**)&p_hdec, g_hdec);
    cudaGetSymbolAddress((void**)&p_u, g_u);
    cudaGetSymbolAddress((void**)&p_WihEP, g_WihEP);
    cudaGetSymbolAddress((void**)&p_WihDP, g_WihDP);
    cudaGetSymbolAddress((void**)&p_WhhDP, g_WhhDP);
    cudaGetSymbolAddress((void**)&p_bEP, g_bEP);
    cudaGetSymbolAddress((void**)&p_bDP, g_bDP);

    cudaFuncSetAttribute(lse_mma_kernel, cudaFuncAttributeMaxDynamicSharedMemorySize, 98304);

    // slot-4 ncu sampling target = enc_all
    perm_kernel<<<6152, 256>>>(W_ih_e, W_hh_e, W_ih_d, W_hh_d, b_e, b_d);  // 1
    embed_kernel<<<TT*BB, 64>>>(x, E);                                     // 2
    gemm_kernel<<<dim3(16, 16), 256>>>(p_emb, p_WihEP, p_bEP, 0, p_preE,
                                       1024, 1024, 256, 0, 0);             // 3
    enc_all_kernel<<<BB, 1024>>>();                                        // 4  <- ncu

    cast_e_kernel<<<8000, 256>>>(E);
    gemm_kernel<<<dim3(4, 16), 256>>>(p_enc, W_start, 0, 0, p_seg, 1024, 256, 256, 1, 0);
    gemm_kernel<<<dim3(16, 16), 256>>>(p_seg, p_WihDP, p_bDP, 0, p_startIh, 1024, 1024, 256, 0, 0);
    gemm_kernel<<<dim3(16, 16), 256>>>(p_emb, p_WihDP, p_bDP, 0, p_winIh, 1024, 1024, 256, 0, 0);

    decih_kernel<<<5*1024, 256>>>(p_bDP);

    for (int s = 0; s < 5; s++) {
        gemm_kernel<<<dim3(16, 16), 256>>>(p_hD, p_WhhDP, 0, p_decIh + (size_t)s*1024*G4,
                                           p_gates, 1024, 1024, 256, 3, s);
    }

    // u = hdec @ W_proj, fused fp16 u cast (act=2, N=256)
    gemm_kernel<<<dim3(4, 80), 256>>>(p_hdec, W_proj, 0, 0, p_u, RPAD, 256, 256, 2, 0);

    lse_mma_kernel<<<dim3(NCHV, RPAD/128), 256, 98304>>>();
    lse_merge_kernel<<<(NROWS + 3)/4, 128>>>();
    tgt_eos_kernel<<<NROWS, 64>>>(x, E);
    logpy_kernel<<<4, 256>>>(x);
    dp_kernel<<<1, 32>>>(lengths, out);
}

// round 13
// speedup vs baseline: 6.2650x; 1.0722x over previous
#include <cuda_runtime.h>
#include <cuda_fp16.h>
#include <math.h>
#include <stdint.h>

#define VV 32000
#define DD 256
#define HH 256
#define LLEN 4
#define TT 128
#define BB 8
#define G4 1024
#define NROWS 5040      // 5 steps * 126 starts * 8 batch
#define RPAD 5120       // 40 * 128
#define NCHV 125        // 32000/256 vocab chunks
#define LOGINF 1000000.0f
#define EOS_TOK 1
#define KSPLIT 256      // single-term fp16 K
#define CHUNKS 4        // 256/64

// ------------------------- device scratch (globals) -------------------------
__device__ float g_emb[TT*BB*DD];
__device__ float g_preE[TT*BB*G4];          // gate-interleaved
__device__ float g_enc[TT*BB*HH];
__device__ float g_seg[TT*BB*HH];
__device__ float g_startIh[TT*BB*G4];       // gate-interleaved
__device__ float g_winIh[TT*BB*G4];         // gate-interleaved
__device__ float g_decIh[5*1024*G4];        // gate-interleaved
__device__ float g_hD[1024*HH];
__device__ float g_cD[1024*HH];
__device__ float g_gates[4];                // dummy C target for act=3
__device__ float g_hdec[RPAD*HH];
__device__ float g_u[RPAD*HH];
__device__ __align__(16) __half g_uH[(size_t)RPAD*KSPLIT];
__device__ __align__(16) __half g_eH[(size_t)VV*KSPLIT];
__device__ float g_pM[(size_t)NCHV*RPAD];
__device__ float g_pS[(size_t)NCHV*RPAD];
__device__ float g_lse[RPAD];
__device__ float g_tlp[RPAD];
__device__ float g_elp[RPAD];
__device__ float g_logpy[(TT-1)*LLEN*BB];
// gate-interleaved weight copies
__device__ __align__(16) float g_WihEP[256*G4];
__device__ __align__(16) float g_WhhEP[256*G4];
__device__ __align__(16) float g_WihDP[256*G4];
__device__ __align__(16) float g_WhhDP[256*G4];
__device__ float g_bEP[G4];
__device__ float g_bDP[G4];

__device__ __forceinline__ float sigf(float x) { return 1.0f / (1.0f + expf(-x)); }

// FMA-pipe exp (no MUFU): magic-number rint + 2^f poly + exponent splice.
__device__ __forceinline__ float fexp(float x) {
    float t = fmaf(x, 1.442695041f, 12582912.0f);
    int   k = __float_as_int(t) - 0x4B400000;
    float kf = t - 12582912.0f;
    float f = fmaf(x, 1.442695041f, -kf);
    float p = 1.54035304e-4f;
    p = fmaf(p, f, 1.33335581e-3f);
    p = fmaf(p, f, 9.61812911e-3f);
    p = fmaf(p, f, 5.55041087e-2f);
    p = fmaf(p, f, 2.40226507e-1f);
    p = fmaf(p, f, 6.93147180e-1f);
    p = fmaf(p, f, 1.0f);
    float r = __int_as_float(__float_as_int(p) + (k << 23));
    return (x < -87.0f) ? 0.0f : r;
}

__device__ __forceinline__ uint32_t smem_u32(const void* p) {
    uint32_t a;
    asm("{ .reg .u64 t; cvta.to.shared.u64 t, %1; cvt.u32.u64 %0, t; }" : "=r"(a) : "l"(p));
    return a;
}

#define LDMX4(r0,r1,r2,r3,addr)                                               \
    asm volatile("ldmatrix.sync.aligned.m8n8.x4.shared.b16 {%0,%1,%2,%3}, [%4];" \
        : "=r"(r0), "=r"(r1), "=r"(r2), "=r"(r3) : "r"(addr))

#define MMA16816(c, a, b)                                                     \
    asm volatile("mma.sync.aligned.m16n8k16.row.col.f32.f16.f16.f32 "         \
        "{%0,%1,%2,%3}, {%4,%5,%6,%7}, {%8,%9}, {%0,%1,%2,%3};"               \
        : "+f"((c)[0]), "+f"((c)[1]), "+f"((c)[2]), "+f"((c)[3])              \
        : "r"((a)[0]), "r"((a)[1]), "r"((a)[2]), "r"((a)[3]),                 \
          "r"((b)[0]), "r"((b)[1]))

#define CPA16(dst, src)  asm volatile("cp.async.cg.shared.global [%0], [%1], 16;" :: "r"(dst), "l"(src))
#define CPA_COMMIT()     asm volatile("cp.async.commit_group;")
#define CPA_WAIT1()      asm volatile("cp.async.wait_group 1;")
#define CPA_WAIT0()      asm volatile("cp.async.wait_group 0;")

// swizzled offset within a K64 tile: row r (128B rows), 16B-chunk c
__device__ __forceinline__ uint32_t sw_off(int r, int c) {
    uint32_t off = (uint32_t)(r >> 3)*1024u + (uint32_t)(r & 7)*128u;
    return off + (((uint32_t)c*16u) ^ ((uint32_t)(r & 7)*16u));
}

// ------------------------- permute weights + init state ----------------------
// new col 4n+j = old col j*256+n (j = gate index i/f/g/o)
__global__ void perm_kernel(const float* __restrict__ Wihe, const float* __restrict__ Whhe,
                            const float* __restrict__ Wihd, const float* __restrict__ Whhd,
                            const float* __restrict__ be,   const float* __restrict__ bd) {
    int blk = blockIdx.x, tid = threadIdx.x;
    if (blk < 4096) {
        int mat = blk >> 10;
        int w = (blk & 1023) * 256 + tid;      // 0..262143
        int k = w >> 10, cn = w & 1023;
        int n = cn >> 2, j = cn & 3;
        const float* src = (mat == 0) ? Wihe : (mat == 1) ? Whhe : (mat == 2) ? Wihd : Whhd;
        float* dst = (mat == 0) ? g_WihEP : (mat == 1) ? g_WhhEP : (mat == 2) ? g_WihDP : g_WhhDP;
        dst[(size_t)k*G4 + cn] = src[(size_t)k*G4 + j*256 + n];
    } else if (blk < 4104) {
        int w = (blk - 4096) * 256 + tid;      // 0..2047
        int cn = w & 1023;
        int n = cn >> 2, j = cn & 3;
        if (w < 1024) g_bEP[cn] = be[j*256 + n];
        else          g_bDP[cn] = bd[j*256 + n];
    } else {
        int w = (blk - 4104) * 256 + tid;      // 0..524287
        if (w < 262144) g_hD[w] = 0.f;
        else            g_cD[w - 262144] = 0.f;
    }
}

// ------------------------- embedding gather ---------------------------------
__global__ void embed_kernel(const int* __restrict__ x, const float* __restrict__ E) {
    int tb = blockIdx.x;
    int t = tb >> 3, b = tb & 7;
    int tok = x[b*TT + t];
    int d = threadIdx.x * 4;
    *(float4*)&g_emb[(size_t)tb*DD + d] = *(const float4*)&E[(size_t)tok*DD + d];
}

// ------------------------- generic fp32 GEMM 64x64 tile ----------------------
// act: 0 none, 1 tanh, 2 = also write fp16 u (N==256),
//      3 = fused decoder LSTM cell (gate-interleaved, N==1024; skips C store)
__global__ __launch_bounds__(256) void gemm_kernel(
    const float* __restrict__ A, const float* __restrict__ Bm,
    const float* __restrict__ bias, const float* __restrict__ addM,
    float* __restrict__ C, int M, int N, int K, int act, int s)
{
    __shared__ float As[16][68];
    __shared__ float Bs[16][68];
    int n0 = blockIdx.x * 64, m0 = blockIdx.y * 64;
    int tid = threadIdx.x;
    int tx = tid & 15, ty = tid >> 4;
    float acc[4][4];
    #pragma unroll
    for (int i = 0; i < 4; i++)
        #pragma unroll
        for (int j = 0; j < 4; j++) acc[i][j] = 0.f;

    int arow = tid >> 2, akk = (tid & 3) << 2;
    int bkk  = tid >> 4, bnc = (tid & 15) << 2;

    for (int k0 = 0; k0 < K; k0 += 16) {
        float4 av = *(const float4*)&A[(size_t)(m0 + arow)*K + k0 + akk];
        As[akk+0][arow] = av.x; As[akk+1][arow] = av.y;
        As[akk+2][arow] = av.z; As[akk+3][arow] = av.w;
        *(float4*)&Bs[bkk][bnc] = *(const float4*)&Bm[(size_t)(k0 + bkk)*N + n0 + bnc];
        __syncthreads();
        #pragma unroll
        for (int kk = 0; kk < 16; kk++) {
            float a0 = As[kk][ty*4+0], a1 = As[kk][ty*4+1];
            float a2 = As[kk][ty*4+2], a3 = As[kk][ty*4+3];
            float4 bq = *(float4*)&Bs[kk][tx*4];
            acc[0][0] += a0*bq.x; acc[0][1] += a0*bq.y; acc[0][2] += a0*bq.z; acc[0][3] += a0*bq.w;
            acc[1][0] += a1*bq.x; acc[1][1] += a1*bq.y; acc[1][2] += a1*bq.z; acc[1][3] += a1*bq.w;
            acc[2][0] += a2*bq.x; acc[2][1] += a2*bq.y; acc[2][2] += a2*bq.z; acc[2][3] += a2*bq.w;
            acc[3][0] += a3*bq.x; acc[3][1] += a3*bq.y; acc[3][2] += a3*bq.z; acc[3][3] += a3*bq.w;
        }
        __syncthreads();
    }
    #pragma unroll
    for (int i = 0; i < 4; i++) {
        int m = m0 + ty*4 + i;
        float v[4];
        #pragma unroll
        for (int j = 0; j < 4; j++) {
            int n = n0 + tx*4 + j;
            float vv = acc[i][j];
            if (bias) vv += bias[n];
            if (addM) vv += addM[(size_t)m*N + n];
            if (act == 1) vv = tanhf(vv);
            v[j] = vv;
        }
        if (act == 3) {
            int un = (n0 >> 2) + tx;     // h-unit index (0..255)
            float c = sigf(v[1]) * g_cD[(size_t)m*HH + un] + sigf(v[0]) * tanhf(v[2]);
            float h = sigf(v[3]) * tanhf(c);
            g_cD[(size_t)m*HH + un] = c;
            g_hD[(size_t)m*HH + un] = h;
            if (m < 1008) g_hdec[((size_t)s*1008 + m)*HH + un] = h;
        } else {
            #pragma unroll
            for (int j = 0; j < 4; j++) {
                int n = n0 + tx*4 + j;
                C[(size_t)m*N + n] = v[j];
                if (act == 2) g_uH[(size_t)m*KSPLIT + n] = __float2half_rn(v[j]);
            }
        }
    }
}

// ------------------------- batch-parallel encoder, 8-deep load batching ------
// 8 blocks (one per batch) x 1024 threads. thread (u = tid&255, kq = tid>>8)
// owns the 4 interleaved gates of unit u over k-quarter kq. Inner loop: 8
// groups; each group front-issues 8 independent LDG.128 (imm offsets off one
// base pointer) before its 32 FMAs -> MLP >= 8 hides L2 latency.
__global__ __launch_bounds__(1024) void enc_all_kernel() {
    __shared__ float hsm[HH];
    __shared__ float csm[HH];
    __shared__ float4 part[4][256];     // 16KB
    int tid = threadIdx.x;
    int u = tid & 255;
    int kq = tid >> 8;
    int b = blockIdx.x;
    if (tid < HH) { hsm[tid] = 0.f; csm[tid] = 0.f; }
    __syncthreads();

    const float* Wbase = g_WhhEP + (size_t)(kq * 64) * G4 + 4 * u;
    for (int t = 0; t < TT; t++) {
        float4 acc = make_float4(0.f, 0.f, 0.f, 0.f);
        #pragma unroll
        for (int grp = 0; grp < 8; grp++) {
            float4 w[8];
            #pragma unroll
            for (int i = 0; i < 8; i++)
                w[i] = *(const float4*)(Wbase + (size_t)(grp*8 + i)*G4);
            float4 h0 = *(const float4*)&hsm[kq*64 + grp*8];
            float4 h1 = *(const float4*)&hsm[kq*64 + grp*8 + 4];
            acc.x += w[0].x*h0.x + w[1].x*h0.y + w[2].x*h0.z + w[3].x*h0.w
                   + w[4].x*h1.x + w[5].x*h1.y + w[6].x*h1.z + w[7].x*h1.w;
            acc.y += w[0].y*h0.x + w[1].y*h0.y + w[2].y*h0.z + w[3].y*h0.w
                   + w[4].y*h1.x + w[5].y*h1.y + w[6].y*h1.z + w[7].y*h1.w;
            acc.z += w[0].z*h0.x + w[1].z*h0.y + w[2].z*h0.z + w[3].z*h0.w
                   + w[4].z*h1.x + w[5].z*h1.y + w[6].z*h1.z + w[7].z*h1.w;
            acc.w += w[0].w*h0.x + w[1].w*h0.y + w[2].w*h0.z + w[3].w*h0.w
                   + w[4].w*h1.x + w[5].w*h1.y + w[6].w*h1.z + w[7].w*h1.w;
        }
        part[kq][u] = acc;
        __syncthreads();

        if (tid < HH) {
            float4 s0 = part[0][tid], s1 = part[1][tid];
            float4 s2 = part[2][tid], s3 = part[3][tid];
            float4 pv = *(const float4*)&g_preE[((size_t)t*BB + b)*G4 + 4*tid];
            float gi = s0.x + s1.x + s2.x + s3.x + pv.x;
            float gf = s0.y + s1.y + s2.y + s3.y + pv.y;
            float gg = s0.z + s1.z + s2.z + s3.z + pv.z;
            float go = s0.w + s1.w + s2.w + s3.w + pv.w;
            float c = sigf(gf)*csm[tid] + sigf(gi)*tanhf(gg);
            float h = sigf(go)*tanhf(c);
            csm[tid] = c;
            hsm[tid] = h;
            g_enc[((size_t)t*BB + b)*HH + tid] = 0.5f*h;
        }
        __syncthreads();
    }
}

// ------------------------- decoder input staging -----------------------------
__global__ void decih_kernel(const float* __restrict__ b_dP) {
    int blk = blockIdx.x;
    int s = blk >> 10, rr = blk & 1023;
    float* dst = &g_decIh[((size_t)s*1024 + rr)*G4];
    int tid = threadIdx.x;
    if (rr >= 1008) {
        for (int i = 0; i < 4; i++) dst[tid*4 + i] = 0.f;
        return;
    }
    int j = (rr >> 3) + 1, b = rr & 7;
    const float* src;
    if (s == 0) src = &g_startIh[(size_t)rr*G4];
    else {
        int t = j + s - 1;
        if (t < TT) src = &g_winIh[(size_t)(t*BB + b)*G4];
        else        src = 0;
    }
    if (src) *(float4*)&dst[tid*4] = *(const float4*)&src[tid*4];
    else     *(float4*)&dst[tid*4] = *(const float4*)&b_dP[tid*4];
}

// ------------------------- fp16 cast of E (vectorized) -----------------------
__global__ void cast_e_kernel(const float* __restrict__ E) {
    int i = blockIdx.x * 256 + threadIdx.x;       // grid 8000
    float2 e2 = *(const float2*)&E[(size_t)i*4];
    float2 e2b = *(const float2*)&E[(size_t)i*4 + 2];
    __half2 h0 = __floats2half2_rn(e2.x, e2.y);
    __half2 h1 = __floats2half2_rn(e2b.x, e2b.y);
    *(__half2*)&g_eH[(size_t)i*4]     = h0;
    *(__half2*)&g_eH[(size_t)i*4 + 2] = h1;
}

// ------------------------- fp16 HMMA vocab GEMM + online LSE -----------------
__global__ __launch_bounds__(256) void lse_mma_kernel() {
    extern __shared__ char dsm[];
    __shared__ float partM[4][128];
    __shared__ float partS[4][128];
    uint32_t sbase = smem_u32(dsm);
    int tid = threadIdx.x, lane = tid & 31, wid = tid >> 5;
    int wm = wid >> 2, wn = wid & 3;          // 2 x 4 warp grid
    int v0 = blockIdx.x * 256, m0 = blockIdx.y * 128;

    const __half* Abase = g_uH + (size_t)m0 * KSPLIT;
    const __half* Bbase = g_eH + (size_t)v0 * KSPLIT;

    int rowA = wm*64 + (lane & 15);
    uint32_t aBase = ((uint32_t)(rowA >> 3) << 10) + ((uint32_t)(rowA & 7) << 7);
    uint32_t aH = ((uint32_t)(lane >> 4)) << 4;
    uint32_t aM = ((uint32_t)(rowA & 7)) << 4;
    int rowB = wn*64 + (lane & 7) + ((lane & 16) >> 1);
    uint32_t bBase = ((uint32_t)(rowB >> 3) << 10) + ((uint32_t)(rowB & 7) << 7);
    uint32_t bH = ((uint32_t)((lane >> 3) & 1)) << 4;
    uint32_t bM = ((uint32_t)(lane & 7)) << 4;

    float acc[4][8][4];
    #pragma unroll
    for (int i = 0; i < 4; i++)
        #pragma unroll
        for (int j = 0; j < 8; j++)
            #pragma unroll
            for (int q = 0; q < 4; q++) acc[i][j][q] = 0.f;

    {
        #pragma unroll
        for (int it = 0; it < 4; it++) {
            int idx = tid + it*256;
            int r = idx >> 3, c = idx & 7;
            CPA16(sbase + sw_off(r, c), (const char*)(Abase + (size_t)r*KSPLIT + c*8));
        }
        #pragma unroll
        for (int it = 0; it < 8; it++) {
            int idx = tid + it*256;
            int r = idx >> 3, c = idx & 7;
            CPA16(sbase + 16384u + sw_off(r, c), (const char*)(Bbase + (size_t)r*KSPLIT + c*8));
        }
        CPA_COMMIT();
    }

    for (int s = 0; s < CHUNKS; s++) {
        int buf = s & 1;
        if (s + 1 < CHUNKS) {
            int k0 = (s + 1) * 64;
            uint32_t dst = sbase + (uint32_t)((s+1)&1)*49152u;
            #pragma unroll
            for (int it = 0; it < 4; it++) {
                int idx = tid + it*256;
                int r = idx >> 3, c = idx & 7;
                CPA16(dst + sw_off(r, c), (const char*)(Abase + (size_t)r*KSPLIT + k0 + c*8));
            }
            #pragma unroll
            for (int it = 0; it < 8; it++) {
                int idx = tid + it*256;
                int r = idx >> 3, c = idx & 7;
                CPA16(dst + 16384u + sw_off(r, c), (const char*)(Bbase + (size_t)r*KSPLIT + k0 + c*8));
            }
            CPA_COMMIT();
            CPA_WAIT1();
        } else {
            CPA_WAIT0();
        }
        __syncthreads();

        uint32_t sA = sbase + (uint32_t)buf*49152u;
        uint32_t sB = sA + 16384u;
        #pragma unroll
        for (int ks = 0; ks < 4; ks++) {
            uint32_t a[4][4];
            #pragma unroll
            for (int mi = 0; mi < 4; mi++) {
                uint32_t addr = sA + aBase + (uint32_t)mi*2048u + (((uint32_t)ks*32u + aH) ^ aM);
                LDMX4(a[mi][0], a[mi][1], a[mi][2], a[mi][3], addr);
            }
            uint32_t b[8][2];
            #pragma unroll
            for (int p = 0; p < 4; p++) {
                uint32_t addr = sB + bBase + (uint32_t)p*2048u + (((uint32_t)ks*32u + bH) ^ bM);
                LDMX4(b[2*p][0], b[2*p][1], b[2*p+1][0], b[2*p+1][1], addr);
            }
            #pragma unroll
            for (int mi = 0; mi < 4; mi++)
                #pragma unroll
                for (int nt = 0; nt < 8; nt++)
                    MMA16816(acc[mi][nt], a[mi], b[nt]);
        }
        __syncthreads();
    }

    int r4 = lane >> 2;
    #pragma unroll
    for (int mi = 0; mi < 4; mi++) {
        #pragma unroll
        for (int h = 0; h < 2; h++) {
            float mx = -LOGINF;
            #pragma unroll
            for (int nt = 0; nt < 8; nt++) {
                mx = fmaxf(mx, acc[mi][nt][h*2]);
                mx = fmaxf(mx, acc[mi][nt][h*2+1]);
            }
            float sum = 0.f;
            #pragma unroll
            for (int nt = 0; nt < 8; nt++) {
                sum += fexp(acc[mi][nt][h*2]   - mx);
                sum += fexp(acc[mi][nt][h*2+1] - mx);
            }
            #pragma unroll
            for (int off = 1; off <= 2; off <<= 1) {
                float om = __shfl_xor_sync(0xffffffff, mx, off);
                float os = __shfl_xor_sync(0xffffffff, sum, off);
                float M = fmaxf(mx, om);
                sum = sum * fexp(mx - M) + os * fexp(om - M);
                mx = M;
            }
            if ((lane & 3) == 0) {
                int mloc = wm*64 + mi*16 + h*8 + r4;
                partM[wn][mloc] = mx;
                partS[wn][mloc] = sum;
            }
        }
    }
    __syncthreads();
    if (tid < 128) {
        float M = partM[0][tid], S = partS[0][tid];
        #pragma unroll
        for (int p = 1; p < 4; p++) {
            float m2 = partM[p][tid], s2 = partS[p][tid];
            float Mn = fmaxf(M, m2);
            S = S * fexp(M - Mn) + s2 * fexp(m2 - Mn);
            M = Mn;
        }
        g_pM[(size_t)blockIdx.x*RPAD + m0 + tid] = M;
        g_pS[(size_t)blockIdx.x*RPAD + m0 + tid] = S;
    }
}

// ------------------------- merge chunk partials -> LSE -----------------------
__global__ void lse_merge_kernel() {
    int r = blockIdx.x * 4 + (threadIdx.x >> 5);
    int lane = threadIdx.x & 31;
    if (r >= NROWS) return;
    float lm[4], ls[4];
    float mx = -LOGINF;
    #pragma unroll
    for (int i = 0; i < 4; i++) {
        int c = lane + i*32;
        if (c < NCHV) { lm[i] = g_pM[(size_t)c*RPAD + r]; ls[i] = g_pS[(size_t)c*RPAD + r]; }
        else          { lm[i] = -LOGINF; ls[i] = 0.f; }
        mx = fmaxf(mx, lm[i]);
    }
    #pragma unroll
    for (int off = 16; off > 0; off >>= 1)
        mx = fmaxf(mx, __shfl_xor_sync(0xffffffff, mx, off));
    float s = 0.f;
    #pragma unroll
    for (int i = 0; i < 4; i++) s += ls[i] * expf(lm[i] - mx);
    #pragma unroll
    for (int off = 16; off > 0; off >>= 1)
        s += __shfl_xor_sync(0xffffffff, s, off);
    if (lane == 0) g_lse[r] = mx + logf(s);
}

// ------------------------- per-row tgt + EOS log-probs -----------------------
__global__ void tgt_eos_kernel(const int* __restrict__ x, const float* __restrict__ E) {
    __shared__ float red[4];
    int r = blockIdx.x;
    int s = r / 1008, rem = r % 1008;
    int j = (rem >> 3) + 1, b = rem & 7;
    int tt = j + s;
    int tok = (tt < TT) ? x[b*TT + tt] : 0;
    int tid = threadIdx.x;
    float4 uv = *(const float4*)&g_u[(size_t)r*HH + tid*4];
    float4 et = *(const float4*)&E[(size_t)tok*DD + tid*4];
    float4 ee = *(const float4*)&E[(size_t)EOS_TOK*DD + tid*4];
    float dt = uv.x*et.x + uv.y*et.y + uv.z*et.z + uv.w*et.w;
    float de = uv.x*ee.x + uv.y*ee.y + uv.z*ee.z + uv.w*ee.w;
    #pragma unroll
    for (int off = 16; off > 0; off >>= 1) {
        dt += __shfl_xor_sync(0xffffffff, dt, off);
        de += __shfl_xor_sync(0xffffffff, de, off);
    }
    if ((tid & 31) == 0) { red[(tid >> 5)*2] = dt; red[(tid >> 5)*2 + 1] = de; }
    __syncthreads();
    if (tid == 0) {
        float lse = g_lse[r];
        g_tlp[r] = red[0] + red[2] - lse;
        g_elp[r] = red[1] + red[3] - lse;
    }
}

// ------------------------- assemble logpy ------------------------------------
__device__ __forceinline__ float is_single_tok(const int* x, int t, int b) {
    if (t >= TT) return 0.f;
    int tok = x[b*TT + t];
    return (tok == 2 || tok == 3 || tok == 4) ? -LOGINF : 0.f;
}

__global__ void logpy_kernel(const int* __restrict__ x) {
    int tid = blockIdx.x * 256 + threadIdx.x;
    if (tid >= 1008) return;
    int j = (tid >> 3) + 1, b = tid & 7;
    float iss0 = is_single_tok(x, j, b);
    float csum = 0.f;
    #pragma unroll
    for (int k = 0; k < LLEN; k++) {
        int rbase = (j-1)*8 + b;
        float tl = g_tlp[k*1008 + rbase];
        float el = g_elp[(k+1)*1008 + rbase];
        float addk = (k == 0) ? 0.f : is_single_tok(x, j + k, b);
        csum += tl + addk;
        float v = csum + ((k >= 1) ? iss0 : 0.f) + el + 1.0f;
        if (k > TT - 2 - j) v = -LOGINF;
        g_logpy[((size_t)j*LLEN + k)*BB + b] = v;
    }
}

// ------------------------- segmental DP + final reduction --------------------
__global__ void dp_kernel(const int* __restrict__ lengths, float* __restrict__ out) {
    __shared__ float alpha[TT-1][BB];
    __shared__ float nll_s[BB];
    int b = threadIdx.x;
    if (b < BB) {
        float buf[LLEN];
        buf[0] = -LOGINF; buf[1] = -LOGINF; buf[2] = -LOGINF; buf[3] = 0.f;
        alpha[0][b] = 0.f;
        for (int m = 1; m <= TT-2; m++) {
            float c[LLEN];
            #pragma unroll
            for (int k = 0; k < LLEN; k++) {
                int idx = m - k;
                float d = (idx >= 1) ? g_logpy[((size_t)idx*LLEN + k)*BB + b] : -LOGINF;
                c[k] = buf[LLEN-1-k] + d;
            }
            float mx = fmaxf(fmaxf(c[0], c[1]), fmaxf(c[2], c[3]));
            float a = mx + logf(expf(c[0]-mx) + expf(c[1]-mx) + expf(c[2]-mx) + expf(c[3]-mx));
            buf[0] = buf[1]; buf[1] = buf[2]; buf[2] = buf[3]; buf[3] = a;
            alpha[m][b] = a;
        }
        nll_s[b] = -alpha[lengths[b] - 2][b];
    }
    __syncthreads();
    if (b == 0) {
        float tot = 0.f; int tl = 0;
        for (int i = 0; i < BB; i++) { tot += nll_s[i]; tl += lengths[i]; }
        out[0] = tot / (float)(tl - 2*BB);
    }
}

// ------------------------- host launch ---------------------------------------
extern "C" void kernel_launch(void* const* d_in, const int* in_sizes, int n_in,
                              void* d_out, int out_size) {
    const int*   x        = (const int*)  d_in[0];
    const int*   lengths  = (const int*)  d_in[1];
    const float* E        = (const float*)d_in[2];
    const float* W_ih_e   = (const float*)d_in[3];
    const float* W_hh_e   = (const float*)d_in[4];
    const float* b_e      = (const float*)d_in[5];
    const float* W_start  = (const float*)d_in[6];
    const float* W_ih_d   = (const float*)d_in[7];
    const float* W_hh_d   = (const float*)d_in[8];
    const float* b_d      = (const float*)d_in[9];
    const float* W_proj   = (const float*)d_in[10];
    float* out = (float*)d_out;

    float *p_emb, *p_preE, *p_enc, *p_seg, *p_startIh, *p_winIh, *p_decIh;
    float *p_hD, *p_gates, *p_hdec, *p_u;
    float *p_WihEP, *p_WihDP, *p_WhhDP, *p_bEP, *p_bDP;
    cudaGetSymbolAddress((void**)&p_emb, g_emb);
    cudaGetSymbolAddress((void**)&p_preE, g_preE);
    cudaGetSymbolAddress((void**)&p_enc, g_enc);
    cudaGetSymbolAddress((void**)&p_seg, g_seg);
    cudaGetSymbolAddress((void**)&p_startIh, g_startIh);
    cudaGetSymbolAddress((void**)&p_winIh, g_winIh);
    cudaGetSymbolAddress((void**)&p_decIh, g_decIh);
    cudaGetSymbolAddress((void**)&p_hD, g_hD);
    cudaGetSymbolAddress((void**)&p_gates, g_gates);
    cudaGetSymbolAddress((void**)&p_hdec, g_hdec);
    cudaGetSymbolAddress((void**)&p_u, g_u);
    cudaGetSymbolAddress((void**)&p_WihEP, g_WihEP);
    cudaGetSymbolAddress((void**)&p_WihDP, g_WihDP);
    cudaGetSymbolAddress((void**)&p_WhhDP, g_WhhDP);
    cudaGetSymbolAddress((void**)&p_bEP, g_bEP);
    cudaGetSymbolAddress((void**)&p_bDP, g_bDP);

    cudaFuncSetAttribute(lse_mma_kernel, cudaFuncAttributeMaxDynamicSharedMemorySize, 98304);

    // slot-4 ncu sampling target = enc_all
    perm_kernel<<<6152, 256>>>(W_ih_e, W_hh_e, W_ih_d, W_hh_d, b_e, b_d);  // 1
    embed_kernel<<<TT*BB, 64>>>(x, E);                                     // 2
    gemm_kernel<<<dim3(16, 16), 256>>>(p_emb, p_WihEP, p_bEP, 0, p_preE,
                                       1024, 1024, 256, 0, 0);             // 3
    enc_all_kernel<<<BB, 1024>>>();                                        // 4  <- ncu

    cast_e_kernel<<<8000, 256>>>(E);
    gemm_kernel<<<dim3(4, 16), 256>>>(p_enc, W_start, 0, 0, p_seg, 1024, 256, 256, 1, 0);
    gemm_kernel<<<dim3(16, 16), 256>>>(p_seg, p_WihDP, p_bDP, 0, p_startIh, 1024, 1024, 256, 0, 0);
    gemm_kernel<<<dim3(16, 16), 256>>>(p_emb, p_WihDP, p_bDP, 0, p_winIh, 1024, 1024, 256, 0, 0);

    decih_kernel<<<5*1024, 256>>>(p_bDP);

    for (int s = 0; s < 5; s++) {
        gemm_kernel<<<dim3(16, 16), 256>>>(p_hD, p_WhhDP, 0, p_decIh + (size_t)s*1024*G4,
                                           p_gates, 1024, 1024, 256, 3, s);
    }

    // u = hdec @ W_proj, fused fp16 u cast (act=2, N=256)
    gemm_kernel<<<dim3(4, 80), 256>>>(p_hdec, W_proj, 0, 0, p_u, RPAD, 256, 256, 2, 0);

    lse_mma_kernel<<<dim3(NCHV, RPAD/128), 256, 98304>>>();
    lse_merge_kernel<<<(NROWS + 3)/4, 128>>>();
    tgt_eos_kernel<<<NROWS, 64>>>(x, E);
    logpy_kernel<<<4, 256>>>(x);
    dp_kernel<<<1, 32>>>(lengths, out);
}

// round 14
// speedup vs baseline: 7.0087x; 1.1187x over previous
#include <cuda_runtime.h>
#include <cuda_fp16.h>
#include <math.h>
#include <stdint.h>

#define VV 32000
#define DD 256
#define HH 256
#define LLEN 4
#define TT 128
#define BB 8
#define G4 1024
#define NROWS 5040      // 5 steps * 126 starts * 8 batch
#define RPAD 5120       // 40 * 128
#define NCHV 125        // 32000/256 vocab chunks
#define LOGINF 1000000.0f
#define EOS_TOK 1
#define KSPLIT 256      // single-term fp16 K
#define CHUNKS 4        // 256/64

// ------------------------- device scratch (globals) -------------------------
__device__ float g_emb[TT*BB*DD];
__device__ float g_preE[TT*BB*G4];          // gate-interleaved
__device__ float g_enc[TT*BB*HH];
__device__ float g_seg[TT*BB*HH];
__device__ float g_startIh[TT*BB*G4];       // gate-interleaved
__device__ float g_winIh[TT*BB*G4];         // gate-interleaved
__device__ float g_decIh[5*1024*G4];        // gate-interleaved
__device__ float g_hD[1024*HH];
__device__ float g_cD[1024*HH];
__device__ float g_gates[4];                // dummy C target for act=3
__device__ float g_hdec[RPAD*HH];
__device__ float g_u[RPAD*HH];
__device__ __align__(16) __half g_uH[(size_t)RPAD*KSPLIT];
__device__ __align__(16) __half g_eH[(size_t)VV*KSPLIT];
__device__ float g_pM[(size_t)NCHV*RPAD];
__device__ float g_pS[(size_t)NCHV*RPAD];
__device__ float g_lse[RPAD];
__device__ float g_tlp[RPAD];
__device__ float g_elp[RPAD];
__device__ float g_logpy[(TT-1)*LLEN*BB];
// encoder pairwise exchange
__device__ __align__(16) float g_partX[2][BB][G4];
__device__ int g_barX[TT*BB];
// gate-interleaved weight copies
__device__ __align__(16) float g_WihEP[256*G4];
__device__ __align__(16) float g_WhhEP[256*G4];
__device__ __align__(16) float g_WihDP[256*G4];
__device__ __align__(16) float g_WhhDP[256*G4];
__device__ float g_bEP[G4];
__device__ float g_bDP[G4];

__device__ __forceinline__ float sigf(float x) { return 1.0f / (1.0f + expf(-x)); }

// FMA-pipe exp (no MUFU): magic-number rint + 2^f poly + exponent splice.
__device__ __forceinline__ float fexp(float x) {
    float t = fmaf(x, 1.442695041f, 12582912.0f);
    int   k = __float_as_int(t) - 0x4B400000;
    float kf = t - 12582912.0f;
    float f = fmaf(x, 1.442695041f, -kf);
    float p = 1.54035304e-4f;
    p = fmaf(p, f, 1.33335581e-3f);
    p = fmaf(p, f, 9.61812911e-3f);
    p = fmaf(p, f, 5.55041087e-2f);
    p = fmaf(p, f, 2.40226507e-1f);
    p = fmaf(p, f, 6.93147180e-1f);
    p = fmaf(p, f, 1.0f);
    float r = __int_as_float(__float_as_int(p) + (k << 23));
    return (x < -87.0f) ? 0.0f : r;
}

__device__ __forceinline__ uint32_t smem_u32(const void* p) {
    uint32_t a;
    asm("{ .reg .u64 t; cvta.to.shared.u64 t, %1; cvt.u32.u64 %0, t; }" : "=r"(a) : "l"(p));
    return a;
}

__device__ __forceinline__ void stcg_v4(float* p, float4 v) {
    asm volatile("st.global.cg.v4.f32 [%0], {%1,%2,%3,%4};"
        :: "l"(p), "f"(v.x), "f"(v.y), "f"(v.z), "f"(v.w) : "memory");
}
__device__ __forceinline__ float4 ldcg_v4f(const float* p) {
    float4 v;
    asm volatile("ld.global.cg.v4.f32 {%0,%1,%2,%3}, [%4];"
        : "=f"(v.x), "=f"(v.y), "=f"(v.z), "=f"(v.w) : "l"(p) : "memory");
    return v;
}

#define LDMX4(r0,r1,r2,r3,addr)                                               \
    asm volatile("ldmatrix.sync.aligned.m8n8.x4.shared.b16 {%0,%1,%2,%3}, [%4];" \
        : "=r"(r0), "=r"(r1), "=r"(r2), "=r"(r3) : "r"(addr))

#define MMA16816(c, a, b)                                                     \
    asm volatile("mma.sync.aligned.m16n8k16.row.col.f32.f16.f16.f32 "         \
        "{%0,%1,%2,%3}, {%4,%5,%6,%7}, {%8,%9}, {%0,%1,%2,%3};"               \
        : "+f"((c)[0]), "+f"((c)[1]), "+f"((c)[2]), "+f"((c)[3])              \
        : "r"((a)[0]), "r"((a)[1]), "r"((a)[2]), "r"((a)[3]),                 \
          "r"((b)[0]), "r"((b)[1]))

#define CPA16(dst, src)  asm volatile("cp.async.cg.shared.global [%0], [%1], 16;" :: "r"(dst), "l"(src))
#define CPA_COMMIT()     asm volatile("cp.async.commit_group;")
#define CPA_WAIT1()      asm volatile("cp.async.wait_group 1;")
#define CPA_WAIT0()      asm volatile("cp.async.wait_group 0;")

// swizzled offset within a K64 tile: row r (128B rows), 16B-chunk c
__device__ __forceinline__ uint32_t sw_off(int r, int c) {
    uint32_t off = (uint32_t)(r >> 3)*1024u + (uint32_t)(r & 7)*128u;
    return off + (((uint32_t)c*16u) ^ ((uint32_t)(r & 7)*16u));
}

// ------------------------- permute weights + init state ----------------------
// new col 4n+j = old col j*256+n (j = gate index i/f/g/o)
__global__ void perm_kernel(const float* __restrict__ Wihe, const float* __restrict__ Whhe,
                            const float* __restrict__ Wihd, const float* __restrict__ Whhd,
                            const float* __restrict__ be,   const float* __restrict__ bd) {
    int blk = blockIdx.x, tid = threadIdx.x;
    if (blk < 4096) {
        int mat = blk >> 10;
        int w = (blk & 1023) * 256 + tid;      // 0..262143
        int k = w >> 10, cn = w & 1023;
        int n = cn >> 2, j = cn & 3;
        const float* src = (mat == 0) ? Wihe : (mat == 1) ? Whhe : (mat == 2) ? Wihd : Whhd;
        float* dst = (mat == 0) ? g_WihEP : (mat == 1) ? g_WhhEP : (mat == 2) ? g_WihDP : g_WhhDP;
        dst[(size_t)k*G4 + cn] = src[(size_t)k*G4 + j*256 + n];
    } else if (blk < 4104) {
        int w = (blk - 4096) * 256 + tid;      // 0..2047
        int cn = w & 1023;
        int n = cn >> 2, j = cn & 3;
        if (w < 1024) g_bEP[cn] = be[j*256 + n];
        else          g_bDP[cn] = bd[j*256 + n];
    } else if (blk < 6152) {
        int w = (blk - 4104) * 256 + tid;      // 0..524287
        if (w < 262144) g_hD[w] = 0.f;
        else            g_cD[w - 262144] = 0.f;
    } else {
        int w = (blk - 6152) * 256 + tid;      // 0..1023
        if (w < TT*BB) g_barX[w] = 0;
    }
}

// ------------------------- embedding gather ---------------------------------
__global__ void embed_kernel(const int* __restrict__ x, const float* __restrict__ E) {
    int tb = blockIdx.x;
    int t = tb >> 3, b = tb & 7;
    int tok = x[b*TT + t];
    int d = threadIdx.x * 4;
    *(float4*)&g_emb[(size_t)tb*DD + d] = *(const float4*)&E[(size_t)tok*DD + d];
}

// ------------------------- generic fp32 GEMM 64x64 tile ----------------------
// act: 0 none, 1 tanh, 2 = also write fp16 u (N==256),
//      3 = fused decoder LSTM cell (gate-interleaved, N==1024; skips C store)
__global__ __launch_bounds__(256) void gemm_kernel(
    const float* __restrict__ A, const float* __restrict__ Bm,
    const float* __restrict__ bias, const float* __restrict__ addM,
    float* __restrict__ C, int M, int N, int K, int act, int s)
{
    __shared__ float As[16][68];
    __shared__ float Bs[16][68];
    int n0 = blockIdx.x * 64, m0 = blockIdx.y * 64;
    int tid = threadIdx.x;
    int tx = tid & 15, ty = tid >> 4;
    float acc[4][4];
    #pragma unroll
    for (int i = 0; i < 4; i++)
        #pragma unroll
        for (int j = 0; j < 4; j++) acc[i][j] = 0.f;

    int arow = tid >> 2, akk = (tid & 3) << 2;
    int bkk  = tid >> 4, bnc = (tid & 15) << 2;

    for (int k0 = 0; k0 < K; k0 += 16) {
        float4 av = *(const float4*)&A[(size_t)(m0 + arow)*K + k0 + akk];
        As[akk+0][arow] = av.x; As[akk+1][arow] = av.y;
        As[akk+2][arow] = av.z; As[akk+3][arow] = av.w;
        *(float4*)&Bs[bkk][bnc] = *(const float4*)&Bm[(size_t)(k0 + bkk)*N + n0 + bnc];
        __syncthreads();
        #pragma unroll
        for (int kk = 0; kk < 16; kk++) {
            float a0 = As[kk][ty*4+0], a1 = As[kk][ty*4+1];
            float a2 = As[kk][ty*4+2], a3 = As[kk][ty*4+3];
            float4 bq = *(float4*)&Bs[kk][tx*4];
            acc[0][0] += a0*bq.x; acc[0][1] += a0*bq.y; acc[0][2] += a0*bq.z; acc[0][3] += a0*bq.w;
            acc[1][0] += a1*bq.x; acc[1][1] += a1*bq.y; acc[1][2] += a1*bq.z; acc[1][3] += a1*bq.w;
            acc[2][0] += a2*bq.x; acc[2][1] += a2*bq.y; acc[2][2] += a2*bq.z; acc[2][3] += a2*bq.w;
            acc[3][0] += a3*bq.x; acc[3][1] += a3*bq.y; acc[3][2] += a3*bq.z; acc[3][3] += a3*bq.w;
        }
        __syncthreads();
    }
    #pragma unroll
    for (int i = 0; i < 4; i++) {
        int m = m0 + ty*4 + i;
        float v[4];
        #pragma unroll
        for (int j = 0; j < 4; j++) {
            int n = n0 + tx*4 + j;
            float vv = acc[i][j];
            if (bias) vv += bias[n];
            if (addM) vv += addM[(size_t)m*N + n];
            if (act == 1) vv = tanhf(vv);
            v[j] = vv;
        }
        if (act == 3) {
            int un = (n0 >> 2) + tx;     // h-unit index (0..255)
            float c = sigf(v[1]) * g_cD[(size_t)m*HH + un] + sigf(v[0]) * tanhf(v[2]);
            float h = sigf(v[3]) * tanhf(c);
            g_cD[(size_t)m*HH + un] = c;
            g_hD[(size_t)m*HH + un] = h;
            if (m < 1008) g_hdec[((size_t)s*1008 + m)*HH + un] = h;
        } else {
            #pragma unroll
            for (int j = 0; j < 4; j++) {
                int n = n0 + tx*4 + j;
                C[(size_t)m*N + n] = v[j];
                if (act == 2) g_uH[(size_t)m*KSPLIT + n] = __float2half_rn(v[j]);
            }
        }
    }
}

// ------------------------- pairwise k-split encoder (16 SMs) -----------------
// 16 blocks = (batch b, half) x 1024 threads. Block computes gate partials for
// k in [half*128, half*128+128); pair exchanges 4KB partials via L2 with the
// proven release/acquire counter handshake (2 arrivals per (step,batch)).
// Both blocks then compute the identical cell update (commutative fp32 add ->
// bit-identical h), so no h exchange is needed.
__global__ __launch_bounds__(1024) void enc_all_kernel() {
    __shared__ float hsm[HH];
    __shared__ float csm[HH];
    __shared__ float4 part[4][256];     // 16KB
    int tid = threadIdx.x;
    int u = tid & 255;                  // h-unit (gate-column group)
    int kq = tid >> 8;                  // 0..3 sub-quarter within our half
    int b = blockIdx.x & 7;
    int half = blockIdx.x >> 3;
    if (tid < HH) { hsm[tid] = 0.f; csm[tid] = 0.f; }
    __syncthreads();

    const float* Wbase = g_WhhEP + (size_t)(half*128 + kq*32) * G4 + 4 * u;
    int hbase = half*128 + kq*32;
    float* myPart = &g_partX[half][b][0];
    const float* otherPart = &g_partX[1 - half][b][0];

    for (int t = 0; t < TT; t++) {
        float4 acc = make_float4(0.f, 0.f, 0.f, 0.f);
        #pragma unroll
        for (int grp = 0; grp < 4; grp++) {
            float4 w[8];
            #pragma unroll
            for (int i = 0; i < 8; i++)
                w[i] = *(const float4*)(Wbase + (size_t)(grp*8 + i)*G4);
            float4 h0 = *(const float4*)&hsm[hbase + grp*8];
            float4 h1 = *(const float4*)&hsm[hbase + grp*8 + 4];
            acc.x += w[0].x*h0.x + w[1].x*h0.y + w[2].x*h0.z + w[3].x*h0.w
                   + w[4].x*h1.x + w[5].x*h1.y + w[6].x*h1.z + w[7].x*h1.w;
            acc.y += w[0].y*h0.x + w[1].y*h0.y + w[2].y*h0.z + w[3].y*h0.w
                   + w[4].y*h1.x + w[5].y*h1.y + w[6].y*h1.z + w[7].y*h1.w;
            acc.z += w[0].z*h0.x + w[1].z*h0.y + w[2].z*h0.z + w[3].z*h0.w
                   + w[4].z*h1.x + w[5].z*h1.y + w[6].z*h1.z + w[7].z*h1.w;
            acc.w += w[0].w*h0.x + w[1].w*h0.y + w[2].w*h0.z + w[3].w*h0.w
                   + w[4].w*h1.x + w[5].w*h1.y + w[6].w*h1.z + w[7].w*h1.w;
        }
        part[kq][u] = acc;
        __syncthreads();

        float4 mine;
        if (tid < 256) {
            float4 s0 = part[0][tid], s1 = part[1][tid];
            float4 s2 = part[2][tid], s3 = part[3][tid];
            mine.x = s0.x + s1.x + s2.x + s3.x;
            mine.y = s0.y + s1.y + s2.y + s3.y;
            mine.z = s0.z + s1.z + s2.z + s3.z;
            mine.w = s0.w + s1.w + s2.w + s3.w;
            stcg_v4(myPart + 4*tid, mine);
        }
        __syncthreads();                 // all partial STGs program-ordered before release
        if (tid == 0) {
            int* bar = &g_barX[t*BB + b];
            asm volatile("red.release.gpu.global.add.s32 [%0], 1;" :: "l"(bar) : "memory");
            int v;
            do {
                asm volatile("ld.acquire.gpu.global.s32 %0, [%1];" : "=r"(v) : "l"(bar) : "memory");
            } while (v < 2);
        }
        __syncthreads();

        if (tid < 256) {
            float4 o = ldcg_v4f(otherPart + 4*tid);
            float4 pv = *(const float4*)&g_preE[((size_t)t*BB + b)*G4 + 4*tid];
            float gi = mine.x + o.x + pv.x;
            float gf = mine.y + o.y + pv.y;
            float gg = mine.z + o.z + pv.z;
            float go = mine.w + o.w + pv.w;
            float c = sigf(gf)*csm[tid] + sigf(gi)*tanhf(gg);
            float h = sigf(go)*tanhf(c);
            csm[tid] = c;
            hsm[tid] = h;
            g_enc[((size_t)t*BB + b)*HH + tid] = 0.5f*h;   // both halves write same value
        }
        __syncthreads();
    }
}

// ------------------------- decoder input staging -----------------------------
__global__ void decih_kernel(const float* __restrict__ b_dP) {
    int blk = blockIdx.x;
    int s = blk >> 10, rr = blk & 1023;
    float* dst = &g_decIh[((size_t)s*1024 + rr)*G4];
    int tid = threadIdx.x;
    if (rr >= 1008) {
        for (int i = 0; i < 4; i++) dst[tid*4 + i] = 0.f;
        return;
    }
    int j = (rr >> 3) + 1, b = rr & 7;
    const float* src;
    if (s == 0) src = &g_startIh[(size_t)rr*G4];
    else {
        int t = j + s - 1;
        if (t < TT) src = &g_winIh[(size_t)(t*BB + b)*G4];
        else        src = 0;
    }
    if (src) *(float4*)&dst[tid*4] = *(const float4*)&src[tid*4];
    else     *(float4*)&dst[tid*4] = *(const float4*)&b_dP[tid*4];
}

// ------------------------- fp16 cast of E (vectorized) -----------------------
__global__ void cast_e_kernel(const float* __restrict__ E) {
    int i = blockIdx.x * 256 + threadIdx.x;       // grid 8000
    float2 e2 = *(const float2*)&E[(size_t)i*4];
    float2 e2b = *(const float2*)&E[(size_t)i*4 + 2];
    __half2 h0 = __floats2half2_rn(e2.x, e2.y);
    __half2 h1 = __floats2half2_rn(e2b.x, e2b.y);
    *(__half2*)&g_eH[(size_t)i*4]     = h0;
    *(__half2*)&g_eH[(size_t)i*4 + 2] = h1;
}

// ------------------------- fp16 HMMA vocab GEMM + online LSE -----------------
__global__ __launch_bounds__(256) void lse_mma_kernel() {
    extern __shared__ char dsm[];
    __shared__ float partM[4][128];
    __shared__ float partS[4][128];
    uint32_t sbase = smem_u32(dsm);
    int tid = threadIdx.x, lane = tid & 31, wid = tid >> 5;
    int wm = wid >> 2, wn = wid & 3;          // 2 x 4 warp grid
    int v0 = blockIdx.x * 256, m0 = blockIdx.y * 128;

    const __half* Abase = g_uH + (size_t)m0 * KSPLIT;
    const __half* Bbase = g_eH + (size_t)v0 * KSPLIT;

    int rowA = wm*64 + (lane & 15);
    uint32_t aBase = ((uint32_t)(rowA >> 3) << 10) + ((uint32_t)(rowA & 7) << 7);
    uint32_t aH = ((uint32_t)(lane >> 4)) << 4;
    uint32_t aM = ((uint32_t)(rowA & 7)) << 4;
    int rowB = wn*64 + (lane & 7) + ((lane & 16) >> 1);
    uint32_t bBase = ((uint32_t)(rowB >> 3) << 10) + ((uint32_t)(rowB & 7) << 7);
    uint32_t bH = ((uint32_t)((lane >> 3) & 1)) << 4;
    uint32_t bM = ((uint32_t)(lane & 7)) << 4;

    float acc[4][8][4];
    #pragma unroll
    for (int i = 0; i < 4; i++)
        #pragma unroll
        for (int j = 0; j < 8; j++)
            #pragma unroll
            for (int q = 0; q < 4; q++) acc[i][j][q] = 0.f;

    {
        #pragma unroll
        for (int it = 0; it < 4; it++) {
            int idx = tid + it*256;
            int r = idx >> 3, c = idx & 7;
            CPA16(sbase + sw_off(r, c), (const char*)(Abase + (size_t)r*KSPLIT + c*8));
        }
        #pragma unroll
        for (int it = 0; it < 8; it++) {
            int idx = tid + it*256;
            int r = idx >> 3, c = idx & 7;
            CPA16(sbase + 16384u + sw_off(r, c), (const char*)(Bbase + (size_t)r*KSPLIT + c*8));
        }
        CPA_COMMIT();
    }

    for (int s = 0; s < CHUNKS; s++) {
        int buf = s & 1;
        if (s + 1 < CHUNKS) {
            int k0 = (s + 1) * 64;
            uint32_t dst = sbase + (uint32_t)((s+1)&1)*49152u;
            #pragma unroll
            for (int it = 0; it < 4; it++) {
                int idx = tid + it*256;
                int r = idx >> 3, c = idx & 7;
                CPA16(dst + sw_off(r, c), (const char*)(Abase + (size_t)r*KSPLIT + k0 + c*8));
            }
            #pragma unroll
            for (int it = 0; it < 8; it++) {
                int idx = tid + it*256;
                int r = idx >> 3, c = idx & 7;
                CPA16(dst + 16384u + sw_off(r, c), (const char*)(Bbase + (size_t)r*KSPLIT + k0 + c*8));
            }
            CPA_COMMIT();
            CPA_WAIT1();
        } else {
            CPA_WAIT0();
        }
        __syncthreads();

        uint32_t sA = sbase + (uint32_t)buf*49152u;
        uint32_t sB = sA + 16384u;
        #pragma unroll
        for (int ks = 0; ks < 4; ks++) {
            uint32_t a[4][4];
            #pragma unroll
            for (int mi = 0; mi < 4; mi++) {
                uint32_t addr = sA + aBase + (uint32_t)mi*2048u + (((uint32_t)ks*32u + aH) ^ aM);
                LDMX4(a[mi][0], a[mi][1], a[mi][2], a[mi][3], addr);
            }
            uint32_t b[8][2];
            #pragma unroll
            for (int p = 0; p < 4; p++) {
                uint32_t addr = sB + bBase + (uint32_t)p*2048u + (((uint32_t)ks*32u + bH) ^ bM);
                LDMX4(b[2*p][0], b[2*p][1], b[2*p+1][0], b[2*p+1][1], addr);
            }
            #pragma unroll
            for (int mi = 0; mi < 4; mi++)
                #pragma unroll
                for (int nt = 0; nt < 8; nt++)
                    MMA16816(acc[mi][nt], a[mi], b[nt]);
        }
        __syncthreads();
    }

    int r4 = lane >> 2;
    #pragma unroll
    for (int mi = 0; mi < 4; mi++) {
        #pragma unroll
        for (int h = 0; h < 2; h++) {
            float mx = -LOGINF;
            #pragma unroll
            for (int nt = 0; nt < 8; nt++) {
                mx = fmaxf(mx, acc[mi][nt][h*2]);
                mx = fmaxf(mx, acc[mi][nt][h*2+1]);
            }
            float sum = 0.f;
            #pragma unroll
            for (int nt = 0; nt < 8; nt++) {
                sum += fexp(acc[mi][nt][h*2]   - mx);
                sum += fexp(acc[mi][nt][h*2+1] - mx);
            }
            #pragma unroll
            for (int off = 1; off <= 2; off <<= 1) {
                float om = __shfl_xor_sync(0xffffffff, mx, off);
                float os = __shfl_xor_sync(0xffffffff, sum, off);
                float M = fmaxf(mx, om);
                sum = sum * fexp(mx - M) + os * fexp(om - M);
                mx = M;
            }
            if ((lane & 3) == 0) {
                int mloc = wm*64 + mi*16 + h*8 + r4;
                partM[wn][mloc] = mx;
                partS[wn][mloc] = sum;
            }
        }
    }
    __syncthreads();
    if (tid < 128) {
        float M = partM[0][tid], S = partS[0][tid];
        #pragma unroll
        for (int p = 1; p < 4; p++) {
            float m2 = partM[p][tid], s2 = partS[p][tid];
            float Mn = fmaxf(M, m2);
            S = S * fexp(M - Mn) + s2 * fexp(m2 - Mn);
            M = Mn;
        }
        g_pM[(size_t)blockIdx.x*RPAD + m0 + tid] = M;
        g_pS[(size_t)blockIdx.x*RPAD + m0 + tid] = S;
    }
}

// ------------------------- merge chunk partials -> LSE -----------------------
__global__ void lse_merge_kernel() {
    int r = blockIdx.x * 4 + (threadIdx.x >> 5);
    int lane = threadIdx.x & 31;
    if (r >= NROWS) return;
    float lm[4], ls[4];
    float mx = -LOGINF;
    #pragma unroll
    for (int i = 0; i < 4; i++) {
        int c = lane + i*32;
        if (c < NCHV) { lm[i] = g_pM[(size_t)c*RPAD + r]; ls[i] = g_pS[(size_t)c*RPAD + r]; }
        else          { lm[i] = -LOGINF; ls[i] = 0.f; }
        mx = fmaxf(mx, lm[i]);
    }
    #pragma unroll
    for (int off = 16; off > 0; off >>= 1)
        mx = fmaxf(mx, __shfl_xor_sync(0xffffffff, mx, off));
    float s = 0.f;
    #pragma unroll
    for (int i = 0; i < 4; i++) s += ls[i] * expf(lm[i] - mx);
    #pragma unroll
    for (int off = 16; off > 0; off >>= 1)
        s += __shfl_xor_sync(0xffffffff, s, off);
    if (lane == 0) g_lse[r] = mx + logf(s);
}

// ------------------------- per-row tgt + EOS log-probs -----------------------
__global__ void tgt_eos_kernel(const int* __restrict__ x, const float* __restrict__ E) {
    __shared__ float red[4];
    int r = blockIdx.x;
    int s = r / 1008, rem = r % 1008;
    int j = (rem >> 3) + 1, b = rem & 7;
    int tt = j + s;
    int tok = (tt < TT) ? x[b*TT + tt] : 0;
    int tid = threadIdx.x;
    float4 uv = *(const float4*)&g_u[(size_t)r*HH + tid*4];
    float4 et = *(const float4*)&E[(size_t)tok*DD + tid*4];
    float4 ee = *(const float4*)&E[(size_t)EOS_TOK*DD + tid*4];
    float dt = uv.x*et.x + uv.y*et.y + uv.z*et.z + uv.w*et.w;
    float de = uv.x*ee.x + uv.y*ee.y + uv.z*ee.z + uv.w*ee.w;
    #pragma unroll
    for (int off = 16; off > 0; off >>= 1) {
        dt += __shfl_xor_sync(0xffffffff, dt, off);
        de += __shfl_xor_sync(0xffffffff, de, off);
    }
    if ((tid & 31) == 0) { red[(tid >> 5)*2] = dt; red[(tid >> 5)*2 + 1] = de; }
    __syncthreads();
    if (tid == 0) {
        float lse = g_lse[r];
        g_tlp[r] = red[0] + red[2] - lse;
        g_elp[r] = red[1] + red[3] - lse;
    }
}

// ------------------------- assemble logpy ------------------------------------
__device__ __forceinline__ float is_single_tok(const int* x, int t, int b) {
    if (t >= TT) return 0.f;
    int tok = x[b*TT + t];
    return (tok == 2 || tok == 3 || tok == 4) ? -LOGINF : 0.f;
}

__global__ void logpy_kernel(const int* __restrict__ x) {
    int tid = blockIdx.x * 256 + threadIdx.x;
    if (tid >= 1008) return;
    int j = (tid >> 3) + 1, b = tid & 7;
    float iss0 = is_single_tok(x, j, b);
    float csum = 0.f;
    #pragma unroll
    for (int k = 0; k < LLEN; k++) {
        int rbase = (j-1)*8 + b;
        float tl = g_tlp[k*1008 + rbase];
        float el = g_elp[(k+1)*1008 + rbase];
        float addk = (k == 0) ? 0.f : is_single_tok(x, j + k, b);
        csum += tl + addk;
        float v = csum + ((k >= 1) ? iss0 : 0.f) + el + 1.0f;
        if (k > TT - 2 - j) v = -LOGINF;
        g_logpy[((size_t)j*LLEN + k)*BB + b] = v;
    }
}

// ------------------------- segmental DP + final reduction --------------------
__global__ void dp_kernel(const int* __restrict__ lengths, float* __restrict__ out) {
    __shared__ float alpha[TT-1][BB];
    __shared__ float nll_s[BB];
    int b = threadIdx.x;
    if (b < BB) {
        float buf[LLEN];
        buf[0] = -LOGINF; buf[1] = -LOGINF; buf[2] = -LOGINF; buf[3] = 0.f;
        alpha[0][b] = 0.f;
        for (int m = 1; m <= TT-2; m++) {
            float c[LLEN];
            #pragma unroll
            for (int k = 0; k < LLEN; k++) {
                int idx = m - k;
                float d = (idx >= 1) ? g_logpy[((size_t)idx*LLEN + k)*BB + b] : -LOGINF;
                c[k] = buf[LLEN-1-k] + d;
            }
            float mx = fmaxf(fmaxf(c[0], c[1]), fmaxf(c[2], c[3]));
            float a = mx + logf(expf(c[0]-mx) + expf(c[1]-mx) + expf(c[2]-mx) + expf(c[3]-mx));
            buf[0] = buf[1]; buf[1] = buf[2]; buf[2] = buf[3]; buf[3] = a;
            alpha[m][b] = a;
        }
        nll_s[b] = -alpha[lengths[b] - 2][b];
    }
    __syncthreads();
    if (b == 0) {
        float tot = 0.f; int tl = 0;
        for (int i = 0; i < BB; i++) { tot += nll_s[i]; tl += lengths[i]; }
        out[0] = tot / (float)(tl - 2*BB);
    }
}

// ------------------------- host launch ---------------------------------------
extern "C" void kernel_launch(void* const* d_in, const int* in_sizes, int n_in,
                              void* d_out, int out_size) {
    const int*   x        = (const int*)  d_in[0];
    const int*   lengths  = (const int*)  d_in[1];
    const float* E        = (const float*)d_in[2];
    const float* W_ih_e   = (const float*)d_in[3];
    const float* W_hh_e   = (const float*)d_in[4];
    const float* b_e      = (const float*)d_in[5];
    const float* W_start  = (const float*)d_in[6];
    const float* W_ih_d   = (const float*)d_in[7];
    const float* W_hh_d   = (const float*)d_in[8];
    const float* b_d      = (const float*)d_in[9];
    const float* W_proj   = (const float*)d_in[10];
    float* out = (float*)d_out;

    float *p_emb, *p_preE, *p_enc, *p_seg, *p_startIh, *p_winIh, *p_decIh;
    float *p_hD, *p_gates, *p_hdec, *p_u;
    float *p_WihEP, *p_WihDP, *p_WhhDP, *p_bEP, *p_bDP;
    cudaGetSymbolAddress((void**)&p_emb, g_emb);
    cudaGetSymbolAddress((void**)&p_preE, g_preE);
    cudaGetSymbolAddress((void**)&p_enc, g_enc);
    cudaGetSymbolAddress((void**)&p_seg, g_seg);
    cudaGetSymbolAddress((void**)&p_startIh, g_startIh);
    cudaGetSymbolAddress((void**)&p_winIh, g_winIh);
    cudaGetSymbolAddress((void**)&p_decIh, g_decIh);
    cudaGetSymbolAddress((void**)&p_hD, g_hD);
    cudaGetSymbolAddress((void**)&p_gates, g_gates);
    cudaGetSymbolAddress((void**)&p_hdec, g_hdec);
    cudaGetSymbolAddress((void**)&p_u, g_u);
    cudaGetSymbolAddress((void**)&p_WihEP, g_WihEP);
    cudaGetSymbolAddress((void**)&p_WihDP, g_WihDP);
    cudaGetSymbolAddress((void**)&p_WhhDP, g_WhhDP);
    cudaGetSymbolAddress((void**)&p_bEP, g_bEP);
    cudaGetSymbolAddress((void**)&p_bDP, g_bDP);

    cudaFuncSetAttribute(lse_mma_kernel, cudaFuncAttributeMaxDynamicSharedMemorySize, 98304);

    // slot-4 ncu sampling target = enc_all
    perm_kernel<<<6156, 256>>>(W_ih_e, W_hh_e, W_ih_d, W_hh_d, b_e, b_d);  // 1
    embed_kernel<<<TT*BB, 64>>>(x, E);                                     // 2
    gemm_kernel<<<dim3(16, 16), 256>>>(p_emb, p_WihEP, p_bEP, 0, p_preE,
                                       1024, 1024, 256, 0, 0);             // 3
    enc_all_kernel<<<2*BB, 1024>>>();                                      // 4  <- ncu

    cast_e_kernel<<<8000, 256>>>(E);
    gemm_kernel<<<dim3(4, 16), 256>>>(p_enc, W_start, 0, 0, p_seg, 1024, 256, 256, 1, 0);
    gemm_kernel<<<dim3(16, 16), 256>>>(p_seg, p_WihDP, p_bDP, 0, p_startIh, 1024, 1024, 256, 0, 0);
    gemm_kernel<<<dim3(16, 16), 256>>>(p_emb, p_WihDP, p_bDP, 0, p_winIh, 1024, 1024, 256, 0, 0);

    decih_kernel<<<5*1024, 256>>>(p_bDP);

    for (int s = 0; s < 5; s++) {
        gemm_kernel<<<dim3(16, 16), 256>>>(p_hD, p_WhhDP, 0, p_decIh + (size_t)s*1024*G4,
                                           p_gates, 1024, 1024, 256, 3, s);
    }

    // u = hdec @ W_proj, fused fp16 u cast (act=2, N=256)
    gemm_kernel<<<dim3(4, 80), 256>>>(p_hdec, W_proj, 0, 0, p_u, RPAD, 256, 256, 2, 0);

    lse_mma_kernel<<<dim3(NCHV, RPAD/128), 256, 98304>>>();
    lse_merge_kernel<<<(NROWS + 3)/4, 128>>>();
    tgt_eos_kernel<<<NROWS, 64>>>(x, E);
    logpy_kernel<<<4, 256>>>(x);
    dp_kernel<<<1, 32>>>(lengths, out);
}

// round 17
// speedup vs baseline: 7.9690x; 1.1370x over previous
#include <cuda_runtime.h>
#include <cuda_fp16.h>
#include <math.h>
#include <stdint.h>

#define VV 32000
#define DD 256
#define HH 256
#define LLEN 4
#define TT 128
#define BB 8
#define G4 1024
#define NROWS 5040      // 5 steps * 126 starts * 8 batch
#define RPAD 5120       // 40 * 128
#define NCHV 125        // 32000/256 vocab chunks
#define LOGINF 1000000.0f
#define EOS_TOK 1
#define KSPLIT 256      // single-term fp16 K
#define CHUNKS 4        // 256/64

// ------------------------- device scratch (globals) -------------------------
__device__ float g_emb[TT*BB*DD];
__device__ float g_preE[TT*BB*G4];          // gate-interleaved
__device__ float g_enc[TT*BB*HH];
__device__ float g_seg[TT*BB*HH];
__device__ float g_startIh[TT*BB*G4];       // gate-interleaved
__device__ float g_winIh[TT*BB*G4];         // gate-interleaved
__device__ float g_decIh[5*1024*G4];        // gate-interleaved
__device__ float g_hD[1024*HH];
__device__ float g_cD[1024*HH];
__device__ float g_gates[4];                // dummy C target for act=3
__device__ float g_hdec[RPAD*HH];
__device__ float g_u[RPAD*HH];
__device__ __align__(16) __half g_uH[(size_t)RPAD*KSPLIT];
__device__ __align__(16) __half g_eH[(size_t)VV*KSPLIT];
__device__ float g_pM[(size_t)NCHV*RPAD];
__device__ float g_pS[(size_t)NCHV*RPAD];
__device__ float g_lse[RPAD];
__device__ float g_tlp[RPAD];
__device__ float g_elp[RPAD];
__device__ float g_logpy[(TT-1)*LLEN*BB];
// encoder 4-way exchange
__device__ __align__(16) float g_partX[4][BB][G4];
__device__ int g_barX[TT*BB];
// gate-interleaved weight copies
__device__ __align__(16) float g_WihEP[256*G4];
__device__ __align__(16) float g_WhhEP[256*G4];
__device__ __align__(16) float g_WihDP[256*G4];
__device__ __align__(16) float g_WhhDP[256*G4];
__device__ float g_bEP[G4];
__device__ float g_bDP[G4];

__device__ __forceinline__ float sigf(float x) { return 1.0f / (1.0f + expf(-x)); }

// FMA-pipe exp (no MUFU): magic-number rint + 2^f poly + exponent splice.
__device__ __forceinline__ float fexp(float x) {
    float t = fmaf(x, 1.442695041f, 12582912.0f);
    int   k = __float_as_int(t) - 0x4B400000;
    float kf = t - 12582912.0f;
    float f = fmaf(x, 1.442695041f, -kf);
    float p = 1.54035304e-4f;
    p = fmaf(p, f, 1.33335581e-3f);
    p = fmaf(p, f, 9.61812911e-3f);
    p = fmaf(p, f, 5.55041087e-2f);
    p = fmaf(p, f, 2.40226507e-1f);
    p = fmaf(p, f, 6.93147180e-1f);
    p = fmaf(p, f, 1.0f);
    float r = __int_as_float(__float_as_int(p) + (k << 23));
    return (x < -87.0f) ? 0.0f : r;
}

__device__ __forceinline__ uint32_t smem_u32(const void* p) {
    uint32_t a;
    asm("{ .reg .u64 t; cvta.to.shared.u64 t, %1; cvt.u32.u64 %0, t; }" : "=r"(a) : "l"(p));
    return a;
}

__device__ __forceinline__ void stcg_v4(float* p, float4 v) {
    asm volatile("st.global.cg.v4.f32 [%0], {%1,%2,%3,%4};"
        :: "l"(p), "f"(v.x), "f"(v.y), "f"(v.z), "f"(v.w) : "memory");
}
__device__ __forceinline__ float4 ldcg_v4f(const float* p) {
    float4 v;
    asm volatile("ld.global.cg.v4.f32 {%0,%1,%2,%3}, [%4];"
        : "=f"(v.x), "=f"(v.y), "=f"(v.z), "=f"(v.w) : "l"(p) : "memory");
    return v;
}

#define LDMX4(r0,r1,r2,r3,addr)                                               \
    asm volatile("ldmatrix.sync.aligned.m8n8.x4.shared.b16 {%0,%1,%2,%3}, [%4];" \
        : "=r"(r0), "=r"(r1), "=r"(r2), "=r"(r3) : "r"(addr))

#define MMA16816(c, a, b)                                                     \
    asm volatile("mma.sync.aligned.m16n8k16.row.col.f32.f16.f16.f32 "         \
        "{%0,%1,%2,%3}, {%4,%5,%6,%7}, {%8,%9}, {%0,%1,%2,%3};"               \
        : "+f"((c)[0]), "+f"((c)[1]), "+f"((c)[2]), "+f"((c)[3])              \
        : "r"((a)[0]), "r"((a)[1]), "r"((a)[2]), "r"((a)[3]),                 \
          "r"((b)[0]), "r"((b)[1]))

#define CPA16(dst, src)  asm volatile("cp.async.cg.shared.global [%0], [%1], 16;" :: "r"(dst), "l"(src))
#define CPA_COMMIT()     asm volatile("cp.async.commit_group;")
#define CPA_WAIT1()      asm volatile("cp.async.wait_group 1;")
#define CPA_WAIT0()      asm volatile("cp.async.wait_group 0;")

// swizzled offset within a K64 tile: row r (128B rows), 16B-chunk c
__device__ __forceinline__ uint32_t sw_off(int r, int c) {
    uint32_t off = (uint32_t)(r >> 3)*1024u + (uint32_t)(r & 7)*128u;
    return off + (((uint32_t)c*16u) ^ ((uint32_t)(r & 7)*16u));
}

// ------------------------- permute weights + init + E cast -------------------
// new col 4n+j = old col j*256+n (j = gate index i/f/g/o); also casts E->fp16.
__global__ void perm_kernel(const float* __restrict__ Wihe, const float* __restrict__ Whhe,
                            const float* __restrict__ Wihd, const float* __restrict__ Whhd,
                            const float* __restrict__ be,   const float* __restrict__ bd,
                            const float* __restrict__ E) {
    int blk = blockIdx.x, tid = threadIdx.x;
    if (blk < 4096) {
        int mat = blk >> 10;
        int w = (blk & 1023) * 256 + tid;      // 0..262143
        int k = w >> 10, cn = w & 1023;
        int n = cn >> 2, j = cn & 3;
        const float* src = (mat == 0) ? Wihe : (mat == 1) ? Whhe : (mat == 2) ? Wihd : Whhd;
        float* dst = (mat == 0) ? g_WihEP : (mat == 1) ? g_WhhEP : (mat == 2) ? g_WihDP : g_WhhDP;
        dst[(size_t)k*G4 + cn] = src[(size_t)k*G4 + j*256 + n];
    } else if (blk < 4104) {
        int w = (blk - 4096) * 256 + tid;      // 0..2047
        int cn = w & 1023;
        int n = cn >> 2, j = cn & 3;
        if (w < 1024) g_bEP[cn] = be[j*256 + n];
        else          g_bDP[cn] = bd[j*256 + n];
    } else if (blk < 6152) {
        int w = (blk - 4104) * 256 + tid;      // 0..524287
        if (w < 262144) g_hD[w] = 0.f;
        else            g_cD[w - 262144] = 0.f;
    } else if (blk < 6156) {
        int w = (blk - 6152) * 256 + tid;      // 0..1023
        if (w < TT*BB) g_barX[w] = 0;
    } else {
        int i = (blk - 6156) * 256 + tid;      // VV*DD/4 groups
        float2 e2 = *(const float2*)&E[(size_t)i*4];
        float2 e2b = *(const float2*)&E[(size_t)i*4 + 2];
        __half2 h0 = __floats2half2_rn(e2.x, e2.y);
        __half2 h1 = __floats2half2_rn(e2b.x, e2b.y);
        *(__half2*)&g_eH[(size_t)i*4]     = h0;
        *(__half2*)&g_eH[(size_t)i*4 + 2] = h1;
    }
}

// ------------------------- embedding gather ---------------------------------
__global__ void embed_kernel(const int* __restrict__ x, const float* __restrict__ E) {
    int tb = blockIdx.x;
    int t = tb >> 3, b = tb & 7;
    int tok = x[b*TT + t];
    int d = threadIdx.x * 4;
    *(float4*)&g_emb[(size_t)tb*DD + d] = *(const float4*)&E[(size_t)tok*DD + d];
}

// ------------------------- generic fp32 GEMM 64x64 tile ----------------------
// act: 0 none, 1 tanh, 2 = also write fp16 u (N==256),
//      3 = fused decoder LSTM cell (gate-interleaved, N==1024; skips C store)
__global__ __launch_bounds__(256) void gemm_kernel(
    const float* __restrict__ A, const float* __restrict__ Bm,
    const float* __restrict__ bias, const float* __restrict__ addM,
    float* __restrict__ C, int M, int N, int K, int act, int s)
{
    __shared__ float As[16][68];
    __shared__ float Bs[16][68];
    int n0 = blockIdx.x * 64, m0 = blockIdx.y * 64;
    int tid = threadIdx.x;
    int tx = tid & 15, ty = tid >> 4;
    float acc[4][4];
    #pragma unroll
    for (int i = 0; i < 4; i++)
        #pragma unroll
        for (int j = 0; j < 4; j++) acc[i][j] = 0.f;

    int arow = tid >> 2, akk = (tid & 3) << 2;
    int bkk  = tid >> 4, bnc = (tid & 15) << 2;

    for (int k0 = 0; k0 < K; k0 += 16) {
        float4 av = *(const float4*)&A[(size_t)(m0 + arow)*K + k0 + akk];
        As[akk+0][arow] = av.x; As[akk+1][arow] = av.y;
        As[akk+2][arow] = av.z; As[akk+3][arow] = av.w;
        *(float4*)&Bs[bkk][bnc] = *(const float4*)&Bm[(size_t)(k0 + bkk)*N + n0 + bnc];
        __syncthreads();
        #pragma unroll
        for (int kk = 0; kk < 16; kk++) {
            float a0 = As[kk][ty*4+0], a1 = As[kk][ty*4+1];
            float a2 = As[kk][ty*4+2], a3 = As[kk][ty*4+3];
            float4 bq = *(float4*)&Bs[kk][tx*4];
            acc[0][0] += a0*bq.x; acc[0][1] += a0*bq.y; acc[0][2] += a0*bq.z; acc[0][3] += a0*bq.w;
            acc[1][0] += a1*bq.x; acc[1][1] += a1*bq.y; acc[1][2] += a1*bq.z; acc[1][3] += a1*bq.w;
            acc[2][0] += a2*bq.x; acc[2][1] += a2*bq.y; acc[2][2] += a2*bq.z; acc[2][3] += a2*bq.w;
            acc[3][0] += a3*bq.x; acc[3][1] += a3*bq.y; acc[3][2] += a3*bq.z; acc[3][3] += a3*bq.w;
        }
        __syncthreads();
    }
    #pragma unroll
    for (int i = 0; i < 4; i++) {
        int m = m0 + ty*4 + i;
        float v[4];
        #pragma unroll
        for (int j = 0; j < 4; j++) {
            int n = n0 + tx*4 + j;
            float vv = acc[i][j];
            if (bias) vv += bias[n];
            if (addM) vv += addM[(size_t)m*N + n];
            if (act == 1) vv = tanhf(vv);
            v[j] = vv;
        }
        if (act == 3) {
            int un = (n0 >> 2) + tx;     // h-unit index (0..255)
            float c = sigf(v[1]) * g_cD[(size_t)m*HH + un] + sigf(v[0]) * tanhf(v[2]);
            float h = sigf(v[3]) * tanhf(c);
            g_cD[(size_t)m*HH + un] = c;
            g_hD[(size_t)m*HH + un] = h;
            if (m < 1008) g_hdec[((size_t)s*1008 + m)*HH + un] = h;
        } else {
            #pragma unroll
            for (int j = 0; j < 4; j++) {
                int n = n0 + tx*4 + j;
                C[(size_t)m*N + n] = v[j];
                if (act == 2) g_uH[(size_t)m*KSPLIT + n] = __float2half_rn(v[j]);
            }
        }
    }
}

// ------------------------- 4-way k-split encoder (32 SMs) --------------------
// 32 blocks = (quarter q, batch b) x 1024 threads. Block computes gate partials
// for k in [q*64, q*64+64). Exchange via L2 with the PROVEN R13 handshake:
// tid0-only release+poll (32 pollers total), then __syncthreads broadcast.
// Each block redundantly computes the identical cell update (commutative fp32
// adds -> bit-identical h), so h never crosses blocks.
__global__ __launch_bounds__(1024) void enc_all_kernel() {
    __shared__ float hsm[HH];
    __shared__ float csm[HH];
    __shared__ float4 part[4][256];     // 16KB
    int tid = threadIdx.x;
    int u = tid & 255;                  // h-unit
    int sub = tid >> 8;                 // 0..3: 16-k slice within our quarter
    int b = blockIdx.x & 7;
    int q = blockIdx.x >> 3;            // 0..3
    if (tid < HH) { hsm[tid] = 0.f; csm[tid] = 0.f; }
    __syncthreads();

    int k0 = q*64 + sub*16;
    const float* Wbase = g_WhhEP + (size_t)k0 * G4 + 4 * u;
    float* myPart = &g_partX[q][b][0];

    for (int t = 0; t < TT; t++) {
        float4 acc = make_float4(0.f, 0.f, 0.f, 0.f);
        #pragma unroll
        for (int grp = 0; grp < 2; grp++) {
            float4 w[8];
            #pragma unroll
            for (int i = 0; i < 8; i++)
                w[i] = *(const float4*)(Wbase + (size_t)(grp*8 + i)*G4);
            float4 h0 = *(const float4*)&hsm[k0 + grp*8];
            float4 h1 = *(const float4*)&hsm[k0 + grp*8 + 4];
            acc.x += w[0].x*h0.x + w[1].x*h0.y + w[2].x*h0.z + w[3].x*h0.w
                   + w[4].x*h1.x + w[5].x*h1.y + w[6].x*h1.z + w[7].x*h1.w;
            acc.y += w[0].y*h0.x + w[1].y*h0.y + w[2].y*h0.z + w[3].y*h0.w
                   + w[4].y*h1.x + w[5].y*h1.y + w[6].y*h1.z + w[7].y*h1.w;
            acc.z += w[0].z*h0.x + w[1].z*h0.y + w[2].z*h0.z + w[3].z*h0.w
                   + w[4].z*h1.x + w[5].z*h1.y + w[6].z*h1.z + w[7].z*h1.w;
            acc.w += w[0].w*h0.x + w[1].w*h0.y + w[2].w*h0.z + w[3].w*h0.w
                   + w[4].w*h1.x + w[5].w*h1.y + w[6].w*h1.z + w[7].w*h1.w;
        }
        part[sub][u] = acc;
        __syncthreads();

        float4 mine;
        if (tid < 256) {
            float4 s0 = part[0][tid], s1 = part[1][tid];
            float4 s2 = part[2][tid], s3 = part[3][tid];
            mine.x = s0.x + s1.x + s2.x + s3.x;
            mine.y = s0.y + s1.y + s2.y + s3.y;
            mine.z = s0.z + s1.z + s2.z + s3.z;
            mine.w = s0.w + s1.w + s2.w + s3.w;
            stcg_v4(myPart + 4*tid, mine);
        }
        __syncthreads();                 // all partial STGs ordered before release
        if (tid == 0) {
            int* bar = &g_barX[t*BB + b];
            asm volatile("red.release.gpu.global.add.s32 [%0], 1;" :: "l"(bar) : "memory");
            int v;
            do {
                asm volatile("ld.acquire.gpu.global.s32 %0, [%1];" : "=r"(v) : "l"(bar) : "memory");
            } while (v < 4);
        }
        __syncthreads();                 // broadcast readiness (proven R13 shape)

        if (tid < 256) {
            float4 pv = *(const float4*)&g_preE[((size_t)t*BB + b)*G4 + 4*tid];
            float gi = pv.x, gf = pv.y, gg = pv.z, go = pv.w;
            #pragma unroll
            for (int p = 0; p < 4; p++) {
                float4 o = (p == q) ? mine : ldcg_v4f(&g_partX[p][b][4*tid]);
                gi += o.x; gf += o.y; gg += o.z; go += o.w;
            }
            float c = sigf(gf)*csm[tid] + sigf(gi)*tanhf(gg);
            float h = sigf(go)*tanhf(c);
            csm[tid] = c;
            hsm[tid] = h;
            g_enc[((size_t)t*BB + b)*HH + tid] = 0.5f*h;   // all quarters write same value
        }
        __syncthreads();
    }
}

// ------------------------- decoder input staging -----------------------------
__global__ void decih_kernel(const float* __restrict__ b_dP) {
    int blk = blockIdx.x;
    int s = blk >> 10, rr = blk & 1023;
    float* dst = &g_decIh[((size_t)s*1024 + rr)*G4];
    int tid = threadIdx.x;
    if (rr >= 1008) {
        for (int i = 0; i < 4; i++) dst[tid*4 + i] = 0.f;
        return;
    }
    int j = (rr >> 3) + 1, b = rr & 7;
    const float* src;
    if (s == 0) src = &g_startIh[(size_t)rr*G4];
    else {
        int t = j + s - 1;
        if (t < TT) src = &g_winIh[(size_t)(t*BB + b)*G4];
        else        src = 0;
    }
    if (src) *(float4*)&dst[tid*4] = *(const float4*)&src[tid*4];
    else     *(float4*)&dst[tid*4] = *(const float4*)&b_dP[tid*4];
}

// ------------------------- fp16 HMMA vocab GEMM + online LSE -----------------
__global__ __launch_bounds__(256) void lse_mma_kernel() {
    extern __shared__ char dsm[];
    __shared__ float partM[4][128];
    __shared__ float partS[4][128];
    uint32_t sbase = smem_u32(dsm);
    int tid = threadIdx.x, lane = tid & 31, wid = tid >> 5;
    int wm = wid >> 2, wn = wid & 3;          // 2 x 4 warp grid
    int v0 = blockIdx.x * 256, m0 = blockIdx.y * 128;

    const __half* Abase = g_uH + (size_t)m0 * KSPLIT;
    const __half* Bbase = g_eH + (size_t)v0 * KSPLIT;

    int rowA = wm*64 + (lane & 15);
    uint32_t aBase = ((uint32_t)(rowA >> 3) << 10) + ((uint32_t)(rowA & 7) << 7);
    uint32_t aH = ((uint32_t)(lane >> 4)) << 4;
    uint32_t aM = ((uint32_t)(rowA & 7)) << 4;
    int rowB = wn*64 + (lane & 7) + ((lane & 16) >> 1);
    uint32_t bBase = ((uint32_t)(rowB >> 3) << 10) + ((uint32_t)(rowB & 7) << 7);
    uint32_t bH = ((uint32_t)((lane >> 3) & 1)) << 4;
    uint32_t bM = ((uint32_t)(lane & 7)) << 4;

    float acc[4][8][4];
    #pragma unroll
    for (int i = 0; i < 4; i++)
        #pragma unroll
        for (int j = 0; j < 8; j++)
            #pragma unroll
            for (int q = 0; q < 4; q++) acc[i][j][q] = 0.f;

    {
        #pragma unroll
        for (int it = 0; it < 4; it++) {
            int idx = tid + it*256;
            int r = idx >> 3, c = idx & 7;
            CPA16(sbase + sw_off(r, c), (const char*)(Abase + (size_t)r*KSPLIT + c*8));
        }
        #pragma unroll
        for (int it = 0; it < 8; it++) {
            int idx = tid + it*256;
            int r = idx >> 3, c = idx & 7;
            CPA16(sbase + 16384u + sw_off(r, c), (const char*)(Bbase + (size_t)r*KSPLIT + c*8));
        }
        CPA_COMMIT();
    }

    for (int s = 0; s < CHUNKS; s++) {
        int buf = s & 1;
        if (s + 1 < CHUNKS) {
            int k0 = (s + 1) * 64;
            uint32_t dst = sbase + (uint32_t)((s+1)&1)*49152u;
            #pragma unroll
            for (int it = 0; it < 4; it++) {
                int idx = tid + it*256;
                int r = idx >> 3, c = idx & 7;
                CPA16(dst + sw_off(r, c), (const char*)(Abase + (size_t)r*KSPLIT + k0 + c*8));
            }
            #pragma unroll
            for (int it = 0; it < 8; it++) {
                int idx = tid + it*256;
                int r = idx >> 3, c = idx & 7;
                CPA16(dst + 16384u + sw_off(r, c), (const char*)(Bbase + (size_t)r*KSPLIT + k0 + c*8));
            }
            CPA_COMMIT();
            CPA_WAIT1();
        } else {
            CPA_WAIT0();
        }
        __syncthreads();

        uint32_t sA = sbase + (uint32_t)buf*49152u;
        uint32_t sB = sA + 16384u;
        #pragma unroll
        for (int ks = 0; ks < 4; ks++) {
            uint32_t a[4][4];
            #pragma unroll
            for (int mi = 0; mi < 4; mi++) {
                uint32_t addr = sA + aBase + (uint32_t)mi*2048u + (((uint32_t)ks*32u + aH) ^ aM);
                LDMX4(a[mi][0], a[mi][1], a[mi][2], a[mi][3], addr);
            }
            uint32_t b[8][2];
            #pragma unroll
            for (int p = 0; p < 4; p++) {
                uint32_t addr = sB + bBase + (uint32_t)p*2048u + (((uint32_t)ks*32u + bH) ^ bM);
                LDMX4(b[2*p][0], b[2*p][1], b[2*p+1][0], b[2*p+1][1], addr);
            }
            #pragma unroll
            for (int mi = 0; mi < 4; mi++)
                #pragma unroll
                for (int nt = 0; nt < 8; nt++)
                    MMA16816(acc[mi][nt], a[mi], b[nt]);
        }
        __syncthreads();
    }

    int r4 = lane >> 2;
    #pragma unroll
    for (int mi = 0; mi < 4; mi++) {
        #pragma unroll
        for (int h = 0; h < 2; h++) {
            float mx = -LOGINF;
            #pragma unroll
            for (int nt = 0; nt < 8; nt++) {
                mx = fmaxf(mx, acc[mi][nt][h*2]);
                mx = fmaxf(mx, acc[mi][nt][h*2+1]);
            }
            float sum = 0.f;
            #pragma unroll
            for (int nt = 0; nt < 8; nt++) {
                sum += fexp(acc[mi][nt][h*2]   - mx);
                sum += fexp(acc[mi][nt][h*2+1] - mx);
            }
            #pragma unroll
            for (int off = 1; off <= 2; off <<= 1) {
                float om = __shfl_xor_sync(0xffffffff, mx, off);
                float os = __shfl_xor_sync(0xffffffff, sum, off);
                float M = fmaxf(mx, om);
                sum = sum * fexp(mx - M) + os * fexp(om - M);
                mx = M;
            }
            if ((lane & 3) == 0) {
                int mloc = wm*64 + mi*16 + h*8 + r4;
                partM[wn][mloc] = mx;
                partS[wn][mloc] = sum;
            }
        }
    }
    __syncthreads();
    if (tid < 128) {
        float M = partM[0][tid], S = partS[0][tid];
        #pragma unroll
        for (int p = 1; p < 4; p++) {
            float m2 = partM[p][tid], s2 = partS[p][tid];
            float Mn = fmaxf(M, m2);
            S = S * fexp(M - Mn) + s2 * fexp(m2 - Mn);
            M = Mn;
        }
        g_pM[(size_t)blockIdx.x*RPAD + m0 + tid] = M;
        g_pS[(size_t)blockIdx.x*RPAD + m0 + tid] = S;
    }
}

// ------------------------- merge chunk partials -> LSE -----------------------
__global__ void lse_merge_kernel() {
    int r = blockIdx.x * 4 + (threadIdx.x >> 5);
    int lane = threadIdx.x & 31;
    if (r >= NROWS) return;
    float lm[4], ls[4];
    float mx = -LOGINF;
    #pragma unroll
    for (int i = 0; i < 4; i++) {
        int c = lane + i*32;
        if (c < NCHV) { lm[i] = g_pM[(size_t)c*RPAD + r]; ls[i] = g_pS[(size_t)c*RPAD + r]; }
        else          { lm[i] = -LOGINF; ls[i] = 0.f; }
        mx = fmaxf(mx, lm[i]);
    }
    #pragma unroll
    for (int off = 16; off > 0; off >>= 1)
        mx = fmaxf(mx, __shfl_xor_sync(0xffffffff, mx, off));
    float s = 0.f;
    #pragma unroll
    for (int i = 0; i < 4; i++) s += ls[i] * expf(lm[i] - mx);
    #pragma unroll
    for (int off = 16; off > 0; off >>= 1)
        s += __shfl_xor_sync(0xffffffff, s, off);
    if (lane == 0) g_lse[r] = mx + logf(s);
}

// ------------------------- per-row tgt + EOS log-probs -----------------------
__global__ void tgt_eos_kernel(const int* __restrict__ x, const float* __restrict__ E) {
    __shared__ float red[4];
    int r = blockIdx.x;
    int s = r / 1008, rem = r % 1008;
    int j = (rem >> 3) + 1, b = rem & 7;
    int tt = j + s;
    int tok = (tt < TT) ? x[b*TT + tt] : 0;
    int tid = threadIdx.x;
    float4 uv = *(const float4*)&g_u[(size_t)r*HH + tid*4];
    float4 et = *(const float4*)&E[(size_t)tok*DD + tid*4];
    float4 ee = *(const float4*)&E[(size_t)EOS_TOK*DD + tid*4];
    float dt = uv.x*et.x + uv.y*et.y + uv.z*et.z + uv.w*et.w;
    float de = uv.x*ee.x + uv.y*ee.y + uv.z*ee.z + uv.w*ee.w;
    #pragma unroll
    for (int off = 16; off > 0; off >>= 1) {
        dt += __shfl_xor_sync(0xffffffff, dt, off);
        de += __shfl_xor_sync(0xffffffff, de, off);
    }
    if ((tid & 31) == 0) { red[(tid >> 5)*2] = dt; red[(tid >> 5)*2 + 1] = de; }
    __syncthreads();
    if (tid == 0) {
        float lse = g_lse[r];
        g_tlp[r] = red[0] + red[2] - lse;
        g_elp[r] = red[1] + red[3] - lse;
    }
}

// ------------------------- assemble logpy ------------------------------------
__device__ __forceinline__ float is_single_tok(const int* x, int t, int b) {
    if (t >= TT) return 0.f;
    int tok = x[b*TT + t];
    return (tok == 2 || tok == 3 || tok == 4) ? -LOGINF : 0.f;
}

__global__ void logpy_kernel(const int* __restrict__ x) {
    int tid = blockIdx.x * 256 + threadIdx.x;
    if (tid >= 1008) return;
    int j = (tid >> 3) + 1, b = tid & 7;
    float iss0 = is_single_tok(x, j, b);
    float csum = 0.f;
    #pragma unroll
    for (int k = 0; k < LLEN; k++) {
        int rbase = (j-1)*8 + b;
        float tl = g_tlp[k*1008 + rbase];
        float el = g_elp[(k+1)*1008 + rbase];
        float addk = (k == 0) ? 0.f : is_single_tok(x, j + k, b);
        csum += tl + addk;
        float v = csum + ((k >= 1) ? iss0 : 0.f) + el + 1.0f;
        if (k > TT - 2 - j) v = -LOGINF;
        g_logpy[((size_t)j*LLEN + k)*BB + b] = v;
    }
}

// ------------------------- segmental DP + final reduction --------------------
__global__ void dp_kernel(const int* __restrict__ lengths, float* __restrict__ out) {
    __shared__ float alpha[TT-1][BB];
    __shared__ float nll_s[BB];
    int b = threadIdx.x;
    if (b < BB) {
        float buf[LLEN];
        buf[0] = -LOGINF; buf[1] = -LOGINF; buf[2] = -LOGINF; buf[3] = 0.f;
        alpha[0][b] = 0.f;
        for (int m = 1; m <= TT-2; m++) {
            float c[LLEN];
            #pragma unroll
            for (int k = 0; k < LLEN; k++) {
                int idx = m - k;
                float d = (idx >= 1) ? g_logpy[((size_t)idx*LLEN + k)*BB + b] : -LOGINF;
                c[k] = buf[LLEN-1-k] + d;
            }
            float mx = fmaxf(fmaxf(c[0], c[1]), fmaxf(c[2], c[3]));
            float a = mx + logf(expf(c[0]-mx) + expf(c[1]-mx) + expf(c[2]-mx) + expf(c[3]-mx));
            buf[0] = buf[1]; buf[1] = buf[2]; buf[2] = buf[3]; buf[3] = a;
            alpha[m][b] = a;
        }
        nll_s[b] = -alpha[lengths[b] - 2][b];
    }
    __syncthreads();
    if (b == 0) {
        float tot = 0.f; int tl = 0;
        for (int i = 0; i < BB; i++) { tot += nll_s[i]; tl += lengths[i]; }
        out[0] = tot / (float)(tl - 2*BB);
    }
}

// ------------------------- host launch ---------------------------------------
extern "C" void kernel_launch(void* const* d_in, const int* in_sizes, int n_in,
                              void* d_out, int out_size) {
    const int*   x        = (const int*)  d_in[0];
    const int*   lengths  = (const int*)  d_in[1];
    const float* E        = (const float*)d_in[2];
    const float* W_ih_e   = (const float*)d_in[3];
    const float* W_hh_e   = (const float*)d_in[4];
    const float* b_e      = (const float*)d_in[5];
    const float* W_start  = (const float*)d_in[6];
    const float* W_ih_d   = (const float*)d_in[7];
    const float* W_hh_d   = (const float*)d_in[8];
    const float* b_d      = (const float*)d_in[9];
    const float* W_proj   = (const float*)d_in[10];
    float* out = (float*)d_out;

    float *p_emb, *p_preE, *p_enc, *p_seg, *p_startIh, *p_winIh, *p_decIh;
    float *p_hD, *p_gates, *p_hdec, *p_u;
    float *p_WihEP, *p_WihDP, *p_WhhDP, *p_bEP, *p_bDP;
    cudaGetSymbolAddress((void**)&p_emb, g_emb);
    cudaGetSymbolAddress((void**)&p_preE, g_preE);
    cudaGetSymbolAddress((void**)&p_enc, g_enc);
    cudaGetSymbolAddress((void**)&p_seg, g_seg);
    cudaGetSymbolAddress((void**)&p_startIh, g_startIh);
    cudaGetSymbolAddress((void**)&p_winIh, g_winIh);
    cudaGetSymbolAddress((void**)&p_decIh, g_decIh);
    cudaGetSymbolAddress((void**)&p_hD, g_hD);
    cudaGetSymbolAddress((void**)&p_gates, g_gates);
    cudaGetSymbolAddress((void**)&p_hdec, g_hdec);
    cudaGetSymbolAddress((void**)&p_u, g_u);
    cudaGetSymbolAddress((void**)&p_WihEP, g_WihEP);
    cudaGetSymbolAddress((void**)&p_WihDP, g_WihDP);
    cudaGetSymbolAddress((void**)&p_WhhDP, g_WhhDP);
    cudaGetSymbolAddress((void**)&p_bEP, g_bEP);
    cudaGetSymbolAddress((void**)&p_bDP, g_bDP);

    cudaFuncSetAttribute(lse_mma_kernel, cudaFuncAttributeMaxDynamicSharedMemorySize, 98304);

    // slot-4 ncu sampling target = enc_all
    perm_kernel<<<6156 + 8000, 256>>>(W_ih_e, W_hh_e, W_ih_d, W_hh_d,
                                      b_e, b_d, E);                        // 1
    embed_kernel<<<TT*BB, 64>>>(x, E);                                     // 2
    gemm_kernel<<<dim3(16, 16), 256>>>(p_emb, p_WihEP, p_bEP, 0, p_preE,
                                       1024, 1024, 256, 0, 0);             // 3
    enc_all_kernel<<<4*BB, 1024>>>();                                      // 4  <- ncu

    gemm_kernel<<<dim3(4, 16), 256>>>(p_enc, W_start, 0, 0, p_seg, 1024, 256, 256, 1, 0);
    gemm_kernel<<<dim3(16, 16), 256>>>(p_seg, p_WihDP, p_bDP, 0, p_startIh, 1024, 1024, 256, 0, 0);
    gemm_kernel<<<dim3(16, 16), 256>>>(p_emb, p_WihDP, p_bDP, 0, p_winIh, 1024, 1024, 256, 0, 0);

    decih_kernel<<<5*1024, 256>>>(p_bDP);

    for (int s = 0; s < 5; s++) {
        gemm_kernel<<<dim3(16, 16), 256>>>(p_hD, p_WhhDP, 0, p_decIh + (size_t)s*1024*G4,
                                           p_gates, 1024, 1024, 256, 3, s);
    }

    // u = hdec @ W_proj, fused fp16 u cast (act=2, N=256)
    gemm_kernel<<<dim3(4, 80), 256>>>(p_hdec, W_proj, 0, 0, p_u, RPAD, 256, 256, 2, 0);

    lse_mma_kernel<<<dim3(NCHV, RPAD/128), 256, 98304>>>();
    lse_merge_kernel<<<(NROWS + 3)/4, 128>>>();
    tgt_eos_kernel<<<NROWS, 64>>>(x, E);
    logpy_kernel<<<4, 256>>>(x);
    dp_kernel<<<1, 32>>>(lengths, out);
}